// round 8
// baseline (speedup 1.0000x reference)
#include <cuda_runtime.h>
#include <math.h>
#include <stdint.h>

// ---------------- problem constants ----------------
#define L_   12
#define B_   4
#define S_   512
#define D_   768
#define H_   12
#define DH_  64
#define FF_  3072
#define BH_  (B_*H_)        // 48
#define MR_  (B_*S_)        // 2048 rows of hidden
#define SS_  (S_*S_)        // 262144

// ---------------- scratch (device globals; allocation-free) ----------------
__device__ float g_bias  [BH_*SS_];
__device__ float g_scores[BH_*SS_];
__device__ float g_q  [BH_*S_*DH_];
__device__ float g_k  [BH_*S_*DH_];
__device__ float g_v  [BH_*S_*DH_];
__device__ float g_ctx [MR_*D_];
__device__ float g_h   [MR_*D_];
__device__ float g_tmp [MR_*D_];
__device__ float g_attn[MR_*D_];
__device__ float g_ff  [MR_*FF_];

// ---------------- helpers ----------------
__device__ __forceinline__ float to_tf32(float x)
{
    float r;
    asm("cvt.rna.tf32.f32 %0, %1;" : "=f"(r) : "f"(x));
    return r;
}

__device__ __forceinline__ void mma_tf32(float* c, const uint32_t* a, const uint32_t* b)
{
    asm("mma.sync.aligned.m16n8k8.row.col.f32.tf32.tf32.f32 "
        "{%0,%1,%2,%3}, {%4,%5,%6,%7}, {%8,%9}, {%0,%1,%2,%3};"
        : "+f"(c[0]), "+f"(c[1]), "+f"(c[2]), "+f"(c[3])
        : "r"(a[0]), "r"(a[1]), "r"(a[2]), "r"(a[3]),
          "r"(b[0]), "r"(b[1]));
}

// ---------------- small kernels ----------------
__global__ void bias_kernel(const float* __restrict__ rel,
                            const float* __restrict__ rel2,
                            const float* __restrict__ mask)
{
    long i = (long)blockIdx.x * 256 + threadIdx.x;
    if (i >= (long)BH_ * SS_) return;
    int b = (int)(i / ((long)H_ * SS_));
    int kcol = (int)(i & (S_ - 1));
    g_bias[i] = (rel[i] + rel2[i]) * 0.125f + mask[b * S_ + kcol];
}

__global__ void copy_kernel(const float* __restrict__ src, float* __restrict__ dst, long n)
{
    long i = (long)blockIdx.x * 256 + threadIdx.x;
    if (i < n) dst[i] = src[i];
}

// ---------------- tensor-core TF32 GEMM (double-buffered) ----------------
// C = A[M,K] @ B (NN: B[K,N]; NT: B[N,K]) with fused epilogue.
// BM=128, BK=16, 256 threads / 8 warps, __launch_bounds__(256,2).
// Smem row stride = +8 pad -> stride 136 == 8 (mod 32): conflict-free frags.
// EPI: 1 = fused QKV scatter to [B,H,S,DH]; block picks {Wq,Wk,Wv} by n-block
//      2 = acc + bias[n] + res[m*N+n]
//      3 = gelu(acc + bias[n])   (exact erf)
//      4 = ctx gather: C[(b*S+m)*D + h*DH + n], z=b*H+h
//      5 = scores: C[m*S+n] = acc + res[m*S+n]   (C,res z-strided)
template<int BN, int WARPS_M, int WARPS_N, int EPI, bool NT>
__global__ __launch_bounds__(256, 2)
void gemm_tc(const float* __restrict__ A, const float* __restrict__ Bg,
             float* __restrict__ C, const float* __restrict__ bias,
             const float* __restrict__ res,
             const float* __restrict__ Bg2, const float* __restrict__ bias2,
             float* __restrict__ C2,
             const float* __restrict__ Bg3, const float* __restrict__ bias3,
             float* __restrict__ C3,
             int M, int N, int K, long sA, long sB, long sC, long sR,
             float scaleval)
{
    constexpr int BM = 128, BK = 16;
    constexpr int WM = BM / WARPS_M, WN = BN / WARPS_N;
    constexpr int MT = WM / 16, NTL = WN / 8;
    constexpr int PAD = 8;

    const int z = blockIdx.z;
    A  += (long)z * sA;
    C  += (long)z * sC;
    if (res) res += (long)z * sR;

    int n0;
    if constexpr (EPI == 1) {
        // fused QKV: gridDim.x = 3*(N/BN); select weight/bias/output
        const int nb = N / BN;
        const int which = blockIdx.x / nb;
        n0 = (blockIdx.x % nb) * BN;
        if (which == 1) { Bg = Bg2; bias = bias2; C = C2; scaleval = 1.0f; }
        else if (which == 2) { Bg = Bg3; bias = bias3; C = C3; scaleval = 1.0f; }
    } else {
        Bg += (long)z * sB;
        n0 = blockIdx.x * BN;
    }
    const int m0 = blockIdx.y * BM;

    __shared__ float As[2][BK][BM + PAD];
    __shared__ float Bs[2][BK][BN + PAD];

    const int tid  = threadIdx.x;
    const int warp = tid >> 5, lane = tid & 31;
    const int g = lane >> 2, tig = lane & 3;
    const int wm = warp % WARPS_M, wn = warp / WARPS_M;
    const int m_base = wm * WM, n_base = wn * WN;

    float acc[MT][NTL][4] = {};
    float4 areg[2];
    float4 breg[2];

    auto loadA = [&](int k0) {
#pragma unroll
        for (int i = 0; i < 2; i++) {
            int id = tid * 2 + i;
            int row = id >> 2, c4 = (id & 3) * 4;
            areg[i] = *(const float4*)(A + (long)(m0 + row) * K + k0 + c4);
        }
    };
    auto storeA = [&](int buf) {
#pragma unroll
        for (int i = 0; i < 2; i++) {
            int id = tid * 2 + i;
            int row = id >> 2, c4 = (id & 3) * 4;
            As[buf][c4 + 0][row] = to_tf32(areg[i].x);
            As[buf][c4 + 1][row] = to_tf32(areg[i].y);
            As[buf][c4 + 2][row] = to_tf32(areg[i].z);
            As[buf][c4 + 3][row] = to_tf32(areg[i].w);
        }
    };
    auto loadB = [&](int k0) {
        if constexpr (!NT) {
            if constexpr (BN == 128) {
#pragma unroll
                for (int i = 0; i < 2; i++) {
                    int id = tid * 2 + i;
                    int k = id >> 5, n4 = (id & 31) * 4;
                    breg[i] = *(const float4*)(Bg + (long)(k0 + k) * N + n0 + n4);
                }
            } else {  // BN == 64
                int k = tid >> 4, n4 = (tid & 15) * 4;
                breg[0] = *(const float4*)(Bg + (long)(k0 + k) * N + n0 + n4);
            }
        } else {      // NT, BN == 128: Bg is [N,K] row-major
#pragma unroll
            for (int i = 0; i < 2; i++) {
                int id = tid * 2 + i;
                int n = id >> 2, c4 = (id & 3) * 4;
                breg[i] = *(const float4*)(Bg + (long)(n0 + n) * K + k0 + c4);
            }
        }
    };
    auto storeB = [&](int buf) {
        if constexpr (!NT) {
            if constexpr (BN == 128) {
#pragma unroll
                for (int i = 0; i < 2; i++) {
                    int id = tid * 2 + i;
                    int k = id >> 5, n4 = (id & 31) * 4;
                    float4 v = breg[i];
                    *(float4*)&Bs[buf][k][n4] = make_float4(to_tf32(v.x), to_tf32(v.y),
                                                            to_tf32(v.z), to_tf32(v.w));
                }
            } else {
                int k = tid >> 4, n4 = (tid & 15) * 4;
                float4 v = breg[0];
                *(float4*)&Bs[buf][k][n4] = make_float4(to_tf32(v.x), to_tf32(v.y),
                                                        to_tf32(v.z), to_tf32(v.w));
            }
        } else {
#pragma unroll
            for (int i = 0; i < 2; i++) {
                int id = tid * 2 + i;
                int n = id >> 2, c4 = (id & 3) * 4;
                float4 v = breg[i];
                Bs[buf][c4 + 0][n] = to_tf32(v.x);
                Bs[buf][c4 + 1][n] = to_tf32(v.y);
                Bs[buf][c4 + 2][n] = to_tf32(v.z);
                Bs[buf][c4 + 3][n] = to_tf32(v.w);
            }
        }
    };
    auto compute = [&](int buf) {
#pragma unroll
        for (int ks = 0; ks < 2; ks++) {
            const int kk = ks * 8;
            uint32_t af[MT][4], bf[NTL][2];
#pragma unroll
            for (int mt = 0; mt < MT; mt++) {
                int r = m_base + mt * 16 + g;
                af[mt][0] = __float_as_uint(As[buf][kk + tig][r]);
                af[mt][1] = __float_as_uint(As[buf][kk + tig][r + 8]);
                af[mt][2] = __float_as_uint(As[buf][kk + tig + 4][r]);
                af[mt][3] = __float_as_uint(As[buf][kk + tig + 4][r + 8]);
            }
#pragma unroll
            for (int nt = 0; nt < NTL; nt++) {
                int cc = n_base + nt * 8 + g;
                bf[nt][0] = __float_as_uint(Bs[buf][kk + tig][cc]);
                bf[nt][1] = __float_as_uint(Bs[buf][kk + tig + 4][cc]);
            }
#pragma unroll
            for (int mt = 0; mt < MT; mt++)
#pragma unroll
                for (int nt = 0; nt < NTL; nt++)
                    mma_tf32(acc[mt][nt], af[mt], bf[nt]);
        }
    };

    // prologue
    loadA(0); loadB(0);
    storeA(0); storeB(0);
    __syncthreads();
    int buf = 0;
    for (int k0 = BK; k0 < K; k0 += BK) {
        loadA(k0); loadB(k0);        // prefetch next tile into regs (LDG in flight)
        compute(buf);                // mma on current smem buffer
        storeA(buf ^ 1); storeB(buf ^ 1);
        __syncthreads();
        buf ^= 1;
    }
    compute(buf);

    // epilogue
    auto emit = [&](int m, int n, float v) {
        if constexpr (EPI == 1) {
            v = (v + bias[n]) * scaleval;
            int b = m >> 9, s = m & 511, hh = n >> 6, d = n & 63;
            C[((((long)b * H_ + hh) * S_ + s) * DH_) + d] = v;
        } else if constexpr (EPI == 2) {
            C[(long)m * N + n] = v + bias[n] + res[(long)m * N + n];
        } else if constexpr (EPI == 3) {
            float x = v + bias[n];
            C[(long)m * N + n] = 0.5f * x * (1.0f + erff(x * 0.70710678118654752f));
        } else if constexpr (EPI == 4) {
            int b = z / H_, hh = z % H_;
            C[((long)(b * S_ + m)) * D_ + hh * DH_ + n] = v;
        } else if constexpr (EPI == 5) {
            long idx = (long)m * S_ + n;
            C[idx] = v + res[idx];
        }
    };
#pragma unroll
    for (int mt = 0; mt < MT; mt++) {
        int r0 = m0 + m_base + mt * 16 + g;
#pragma unroll
        for (int nt = 0; nt < NTL; nt++) {
            int c0 = n0 + n_base + nt * 8 + 2 * tig;
            emit(r0,     c0,     acc[mt][nt][0]);
            emit(r0,     c0 + 1, acc[mt][nt][1]);
            emit(r0 + 8, c0,     acc[mt][nt][2]);
            emit(r0 + 8, c0 + 1, acc[mt][nt][3]);
        }
    }
}

// ---------------- softmax over rows of length 512 ----------------
__global__ __launch_bounds__(256)
void softmax512(float* __restrict__ sc)
{
    float* row = sc + (long)blockIdx.x * S_;
    int tid = threadIdx.x;
    float v0 = row[tid], v1 = row[tid + 256];
    __shared__ float red[8];

    float m = fmaxf(v0, v1);
#pragma unroll
    for (int o = 16; o; o >>= 1) m = fmaxf(m, __shfl_xor_sync(0xffffffffu, m, o));
    if ((tid & 31) == 0) red[tid >> 5] = m;
    __syncthreads();
    m = fmaxf(fmaxf(fmaxf(red[0], red[1]), fmaxf(red[2], red[3])),
              fmaxf(fmaxf(red[4], red[5]), fmaxf(red[6], red[7])));
    __syncthreads();

    float e0 = __expf(v0 - m), e1 = __expf(v1 - m);
    float s = e0 + e1;
#pragma unroll
    for (int o = 16; o; o >>= 1) s += __shfl_xor_sync(0xffffffffu, s, o);
    if ((tid & 31) == 0) red[tid >> 5] = s;
    __syncthreads();
    s = (red[0] + red[1]) + (red[2] + red[3]) + (red[4] + red[5]) + (red[6] + red[7]);
    float inv = 1.0f / s;
    row[tid]       = e0 * inv;
    row[tid + 256] = e1 * inv;
}

// ---------------- layernorm over rows of length 768 ----------------
__global__ __launch_bounds__(256)
void layernorm768(const float* __restrict__ x, const float* __restrict__ g,
                  const float* __restrict__ b, float* __restrict__ y)
{
    const float* row = x + (long)blockIdx.x * D_;
    float* orow = y + (long)blockIdx.x * D_;
    int tid = threadIdx.x;
    float a0 = row[tid], a1 = row[tid + 256], a2 = row[tid + 512];
    float s = a0 + a1 + a2;
    float q = a0 * a0 + a1 * a1 + a2 * a2;
    __shared__ float rs[8], rq[8];
#pragma unroll
    for (int o = 16; o; o >>= 1) {
        s += __shfl_xor_sync(0xffffffffu, s, o);
        q += __shfl_xor_sync(0xffffffffu, q, o);
    }
    if ((tid & 31) == 0) { rs[tid >> 5] = s; rq[tid >> 5] = q; }
    __syncthreads();
    s = (rs[0] + rs[1]) + (rs[2] + rs[3]) + (rs[4] + rs[5]) + (rs[6] + rs[7]);
    q = (rq[0] + rq[1]) + (rq[2] + rq[3]) + (rq[4] + rq[5]) + (rq[6] + rq[7]);
    float mean = s * (1.0f / D_);
    float var  = q * (1.0f / D_) - mean * mean;
    float r = rsqrtf(var + 1e-5f);
    orow[tid]       = (a0 - mean) * r * g[tid]       + b[tid];
    orow[tid + 256] = (a1 - mean) * r * g[tid + 256] + b[tid + 256];
    orow[tid + 512] = (a2 - mean) * r * g[tid + 512] + b[tid + 512];
}

// ---------------- host orchestration ----------------
extern "C" void kernel_launch(void* const* d_in, const int* in_sizes, int n_in,
                              void* d_out, int out_size)
{
    const float* hs    = (const float*)d_in[0];
    const float* mask  = (const float*)d_in[1];
    const float* rel   = (const float*)d_in[2];
    const float* rel2  = (const float*)d_in[3];
    const float* Wq    = (const float*)d_in[4];
    const float* bq    = (const float*)d_in[5];
    const float* Wk    = (const float*)d_in[6];
    const float* bk    = (const float*)d_in[7];
    const float* Wv    = (const float*)d_in[8];
    const float* bv    = (const float*)d_in[9];
    const float* Wo    = (const float*)d_in[10];
    const float* bo    = (const float*)d_in[11];
    const float* ln1g  = (const float*)d_in[12];
    const float* ln1b  = (const float*)d_in[13];
    const float* Wi    = (const float*)d_in[14];
    const float* bi    = (const float*)d_in[15];
    const float* Wo2   = (const float*)d_in[16];
    const float* bo2   = (const float*)d_in[17];
    const float* ln2g  = (const float*)d_in[18];
    const float* ln2b  = (const float*)d_in[19];
    float* out = (float*)d_out;

    float *p_bias, *p_scores, *p_q, *p_k, *p_v, *p_ctx, *p_h, *p_tmp, *p_attn, *p_ff;
    cudaGetSymbolAddress((void**)&p_bias,   g_bias);
    cudaGetSymbolAddress((void**)&p_scores, g_scores);
    cudaGetSymbolAddress((void**)&p_q,      g_q);
    cudaGetSymbolAddress((void**)&p_k,      g_k);
    cudaGetSymbolAddress((void**)&p_v,      g_v);
    cudaGetSymbolAddress((void**)&p_ctx,    g_ctx);
    cudaGetSymbolAddress((void**)&p_h,      g_h);
    cudaGetSymbolAddress((void**)&p_tmp,    g_tmp);
    cudaGetSymbolAddress((void**)&p_attn,   g_attn);
    cudaGetSymbolAddress((void**)&p_ff,     g_ff);

    long nb = (long)BH_ * SS_;
    bias_kernel<<<(unsigned)((nb + 255) / 256), 256>>>(rel, rel2, mask);
    copy_kernel<<<(MR_ * D_ + 255) / 256, 256>>>(hs, p_h, (long)MR_ * D_);

    dim3 gQKV(3 * D_ / 128, MR_ / 128, 1);  // 18 x 16 = 288 (fused Q,K,V)
    dim3 gS  (S_ / 128, S_ / 128, BH_);     // 4 x 4 x 48 = 768
    dim3 gC  (1, S_ / 128, BH_);            // 192
    dim3 gWo (D_ / 64, MR_ / 128, 1);       // 12 x 16 = 192 (BN=64)
    dim3 gF1 (FF_ / 128, MR_ / 128, 1);     // 24 x 16 = 384
    dim3 gF2 (D_ / 64, MR_ / 128, 1);       // 12 x 16 = 192 (BN=64)

    for (int l = 0; l < L_; l++) {
        const float* wq  = Wq  + (long)l * D_ * D_;
        const float* wk  = Wk  + (long)l * D_ * D_;
        const float* wv  = Wv  + (long)l * D_ * D_;
        const float* wo  = Wo  + (long)l * D_ * D_;
        const float* wi  = Wi  + (long)l * D_ * FF_;
        const float* wo2 = Wo2 + (long)l * FF_ * D_;

        // fused QKV projections (q folds 1/sqrt(DH)), scattered to [B,H,S,DH]
        gemm_tc<128,2,4,1,false><<<gQKV, 256>>>(
            p_h, wq, p_q, bq + l * D_, nullptr,
            wk, bk + l * D_, p_k,
            wv, bv + l * D_, p_v,
            MR_, D_, D_, 0, 0, 0, 0, 0.125f);

        // scores = q @ k^T + bias ; softmax
        gemm_tc<128,2,4,5,true><<<gS, 256>>>(
            p_q, p_k, p_scores, nullptr, p_bias,
            nullptr, nullptr, nullptr, nullptr, nullptr, nullptr,
            S_, S_, DH_, (long)S_ * DH_, (long)S_ * DH_,
            (long)SS_, (long)SS_, 1.0f);
        softmax512<<<BH_ * S_, 256>>>(p_scores);

        // ctx = probs @ v, gathered back to [B,S,D]
        gemm_tc<64,4,2,4,false><<<gC, 256>>>(
            p_scores, p_v, p_ctx, nullptr, nullptr,
            nullptr, nullptr, nullptr, nullptr, nullptr, nullptr,
            S_, DH_, S_, (long)SS_, (long)S_ * DH_, 0, 0, 1.0f);

        // attn_out = LN1(ctx @ Wo + bo + h)
        gemm_tc<64,4,2,2,false><<<gWo, 256>>>(
            p_ctx, wo, p_tmp, bo + l * D_, p_h,
            nullptr, nullptr, nullptr, nullptr, nullptr, nullptr,
            MR_, D_, D_, 0, 0, 0, 0, 1.0f);
        layernorm768<<<MR_, 256>>>(p_tmp, ln1g + l * D_, ln1b + l * D_, p_attn);

        // ff = gelu(attn @ Wi + bi)
        gemm_tc<128,2,4,3,false><<<gF1, 256>>>(
            p_attn, wi, p_ff, bi + l * FF_, nullptr,
            nullptr, nullptr, nullptr, nullptr, nullptr, nullptr,
            MR_, FF_, D_, 0, 0, 0, 0, 1.0f);

        // out = LN2(ff @ Wo2 + bo2 + attn_out)
        gemm_tc<64,4,2,2,false><<<gF2, 256>>>(
            p_ff, wo2, p_tmp, bo2 + l * D_, p_attn,
            nullptr, nullptr, nullptr, nullptr, nullptr, nullptr,
            MR_, D_, FF_, 0, 0, 0, 0, 1.0f);
        float* dst = (l == L_ - 1) ? out : p_h;
        layernorm768<<<MR_, 256>>>(p_tmp, ln2g + l * D_, ln2b + l * D_, dst);
    }
}

// round 9
// speedup vs baseline: 1.0249x; 1.0249x over previous
#include <cuda_runtime.h>
#include <math.h>
#include <stdint.h>

// ---------------- problem constants ----------------
#define L_   12
#define B_   4
#define S_   512
#define D_   768
#define H_   12
#define DH_  64
#define FF_  3072
#define BH_  (B_*H_)        // 48
#define MR_  (B_*S_)        // 2048 rows of hidden
#define SS_  (S_*S_)        // 262144

// ---------------- scratch (device globals; allocation-free) ----------------
__device__ float g_bias  [BH_*SS_];
__device__ float g_q  [BH_*S_*DH_];
__device__ float g_k  [BH_*S_*DH_];
__device__ float g_v  [BH_*S_*DH_];
__device__ float g_ctx [MR_*D_];
__device__ float g_h   [MR_*D_];
__device__ float g_tmp [MR_*D_];
__device__ float g_attn[MR_*D_];
__device__ float g_ff  [MR_*FF_];

// ---------------- helpers ----------------
__device__ __forceinline__ float to_tf32(float x)
{
    float r;
    asm("cvt.rna.tf32.f32 %0, %1;" : "=f"(r) : "f"(x));
    return r;
}

__device__ __forceinline__ void mma_tf32(float* c, const uint32_t* a, const uint32_t* b)
{
    asm("mma.sync.aligned.m16n8k8.row.col.f32.tf32.tf32.f32 "
        "{%0,%1,%2,%3}, {%4,%5,%6,%7}, {%8,%9}, {%0,%1,%2,%3};"
        : "+f"(c[0]), "+f"(c[1]), "+f"(c[2]), "+f"(c[3])
        : "r"(a[0]), "r"(a[1]), "r"(a[2]), "r"(a[3]),
          "r"(b[0]), "r"(b[1]));
}

// ---------------- small kernels ----------------
__global__ void bias_kernel(const float* __restrict__ rel,
                            const float* __restrict__ rel2,
                            const float* __restrict__ mask)
{
    long i = (long)blockIdx.x * 256 + threadIdx.x;
    if (i >= (long)BH_ * SS_) return;
    int b = (int)(i / ((long)H_ * SS_));
    int kcol = (int)(i & (S_ - 1));
    g_bias[i] = (rel[i] + rel2[i]) * 0.125f + mask[b * S_ + kcol];
}

__global__ void copy_kernel(const float* __restrict__ src, float* __restrict__ dst, long n)
{
    long i = (long)blockIdx.x * 256 + threadIdx.x;
    if (i < n) dst[i] = src[i];
}

// ---------------- fused flash attention ----------------
// Grid (S/64, BH). 128 threads / 4 warps. Each warp owns 16 q-rows.
// Per key-tile of 64: S = Q.K^T + bias (TF32 mma), online softmax (rows
// entirely warp-local -> shfl quad reductions), P staged in per-warp smem
// pane, ctx += P.V (TF32 mma). One normalized ctx write at the end.
// smem: Qs/Ks/Vs [64][72] (pad 8 -> conflict-free frag loads),
//       Ps per warp [64][24] (24 % 32 -> conflict-free A-frag loads).
#define QS_(c, m) smf[(c) * 72 + (m)]
#define KS_(c, n) smf[4608 + (c) * 72 + (n)]
#define VS_(k, d) smf[9216 + (k) * 72 + (d)]
#define PS_(w, k, r) smf[13824 + (w) * 1536 + (k) * 24 + (r)]
#define FLASH_SMEM ((13824 + 4 * 1536) * 4)

__global__ __launch_bounds__(128, 2)
void flash_attn(const float* __restrict__ Qg, const float* __restrict__ Kg,
                const float* __restrict__ Vg, const float* __restrict__ biasg,
                float* __restrict__ ctx)
{
    extern __shared__ float smf[];

    const int z  = blockIdx.y;              // b*H + h
    const int q0 = blockIdx.x * 64;
    const int tid  = threadIdx.x;
    const int warp = tid >> 5, lane = tid & 31;
    const int g = lane >> 2, tig = lane & 3;

    const float* Qz = Qg + (long)z * S_ * DH_;
    const float* Kz = Kg + (long)z * S_ * DH_;
    const float* Vz = Vg + (long)z * S_ * DH_;
    const float* bz = biasg + (long)z * SS_;

    // load Q tile [64 x 64] -> Qs[k][m] (tf32)
#pragma unroll
    for (int i = 0; i < 8; i++) {
        int idx = i * 128 + tid;
        int m = idx >> 4, c4 = (idx & 15) << 2;
        float4 v = *(const float4*)(Qz + (long)(q0 + m) * DH_ + c4);
        QS_(c4 + 0, m) = to_tf32(v.x);
        QS_(c4 + 1, m) = to_tf32(v.y);
        QS_(c4 + 2, m) = to_tf32(v.z);
        QS_(c4 + 3, m) = to_tf32(v.w);
    }

    float acc[8][4] = {};
    float mrow0 = -1e30f, mrow1 = -1e30f;
    float l0 = 0.0f, l1 = 0.0f;
    const int r = warp * 16 + g;            // warp-local row (g) of q-tile

    for (int kt = 0; kt < 8; kt++) {
        // load K tile (NT: Ks[c][n] = K[n][c]) and V tile (Vs[k][d])
#pragma unroll
        for (int i = 0; i < 8; i++) {
            int idx = i * 128 + tid;
            int n = idx >> 4, c4 = (idx & 15) << 2;
            float4 v = *(const float4*)(Kz + (long)(kt * 64 + n) * DH_ + c4);
            KS_(c4 + 0, n) = to_tf32(v.x);
            KS_(c4 + 1, n) = to_tf32(v.y);
            KS_(c4 + 2, n) = to_tf32(v.z);
            KS_(c4 + 3, n) = to_tf32(v.w);
        }
#pragma unroll
        for (int i = 0; i < 8; i++) {
            int idx = i * 128 + tid;
            int kk = idx >> 4, d4 = (idx & 15) << 2;
            float4 v = *(const float4*)(Vz + (long)(kt * 64 + kk) * DH_ + d4);
            VS_(kk, d4 + 0) = to_tf32(v.x);
            VS_(kk, d4 + 1) = to_tf32(v.y);
            VS_(kk, d4 + 2) = to_tf32(v.z);
            VS_(kk, d4 + 3) = to_tf32(v.w);
        }
        __syncthreads();

        // phase A: S = Q.K^T (q pre-scaled by 1/8 in qkv epilogue)
        float s[8][4] = {};
#pragma unroll
        for (int ks = 0; ks < 8; ks++) {
            const int kk = ks * 8;
            uint32_t af[4];
            af[0] = __float_as_uint(QS_(kk + tig,     r));
            af[1] = __float_as_uint(QS_(kk + tig,     r + 8));
            af[2] = __float_as_uint(QS_(kk + tig + 4, r));
            af[3] = __float_as_uint(QS_(kk + tig + 4, r + 8));
#pragma unroll
            for (int nt = 0; nt < 8; nt++) {
                uint32_t bf[2];
                bf[0] = __float_as_uint(KS_(kk + tig,     nt * 8 + g));
                bf[1] = __float_as_uint(KS_(kk + tig + 4, nt * 8 + g));
                mma_tf32(s[nt], af, bf);
            }
        }

        // bias + online softmax (rows g and g+8, warp-quad reductions)
        const float* brow0 = bz + (long)(q0 + r) * S_ + kt * 64;
        const float* brow1 = brow0 + 8 * S_;
        float nm0 = mrow0, nm1 = mrow1;
#pragma unroll
        for (int nt = 0; nt < 8; nt++) {
            int c = nt * 8 + 2 * tig;
            float2 b0 = *(const float2*)(brow0 + c);
            float2 b1 = *(const float2*)(brow1 + c);
            s[nt][0] += b0.x; s[nt][1] += b0.y;
            s[nt][2] += b1.x; s[nt][3] += b1.y;
            nm0 = fmaxf(nm0, fmaxf(s[nt][0], s[nt][1]));
            nm1 = fmaxf(nm1, fmaxf(s[nt][2], s[nt][3]));
        }
        nm0 = fmaxf(nm0, __shfl_xor_sync(0xffffffffu, nm0, 1));
        nm0 = fmaxf(nm0, __shfl_xor_sync(0xffffffffu, nm0, 2));
        nm1 = fmaxf(nm1, __shfl_xor_sync(0xffffffffu, nm1, 1));
        nm1 = fmaxf(nm1, __shfl_xor_sync(0xffffffffu, nm1, 2));

        float alpha0 = __expf(mrow0 - nm0);
        float alpha1 = __expf(mrow1 - nm1);
        mrow0 = nm0; mrow1 = nm1;

        float rs0 = 0.0f, rs1 = 0.0f;
#pragma unroll
        for (int nt = 0; nt < 8; nt++) {
            int c = nt * 8 + 2 * tig;
            float p0 = __expf(s[nt][0] - nm0);
            float p1 = __expf(s[nt][1] - nm0);
            float p2 = __expf(s[nt][2] - nm1);
            float p3 = __expf(s[nt][3] - nm1);
            rs0 += p0 + p1; rs1 += p2 + p3;
            PS_(warp, c,     g)     = to_tf32(p0);
            PS_(warp, c + 1, g)     = to_tf32(p1);
            PS_(warp, c,     g + 8) = to_tf32(p2);
            PS_(warp, c + 1, g + 8) = to_tf32(p3);
            acc[nt][0] *= alpha0; acc[nt][1] *= alpha0;
            acc[nt][2] *= alpha1; acc[nt][3] *= alpha1;
        }
        rs0 += __shfl_xor_sync(0xffffffffu, rs0, 1);
        rs0 += __shfl_xor_sync(0xffffffffu, rs0, 2);
        rs1 += __shfl_xor_sync(0xffffffffu, rs1, 1);
        rs1 += __shfl_xor_sync(0xffffffffu, rs1, 2);
        l0 = l0 * alpha0 + rs0;
        l1 = l1 * alpha1 + rs1;
        __syncwarp();

        // phase C: ctx += P.V
#pragma unroll
        for (int ks = 0; ks < 8; ks++) {
            const int kk = ks * 8;
            uint32_t af[4];
            af[0] = __float_as_uint(PS_(warp, kk + tig,     g));
            af[1] = __float_as_uint(PS_(warp, kk + tig,     g + 8));
            af[2] = __float_as_uint(PS_(warp, kk + tig + 4, g));
            af[3] = __float_as_uint(PS_(warp, kk + tig + 4, g + 8));
#pragma unroll
            for (int nt = 0; nt < 8; nt++) {
                uint32_t bf[2];
                bf[0] = __float_as_uint(VS_(kk + tig,     nt * 8 + g));
                bf[1] = __float_as_uint(VS_(kk + tig + 4, nt * 8 + g));
                mma_tf32(acc[nt], af, bf);
            }
        }
        __syncthreads();
    }

    // epilogue: normalize and gather to [B,S,D]
    const float inv0 = 1.0f / l0, inv1 = 1.0f / l1;
    const int b = z / H_, hh = z % H_;
    const int mg = q0 + r;
    float* out0 = ctx + (long)(b * S_ + mg) * D_ + hh * DH_;
    float* out1 = out0 + 8 * D_;
#pragma unroll
    for (int nt = 0; nt < 8; nt++) {
        int c = nt * 8 + 2 * tig;
        *(float2*)(out0 + c) = make_float2(acc[nt][0] * inv0, acc[nt][1] * inv0);
        *(float2*)(out1 + c) = make_float2(acc[nt][2] * inv1, acc[nt][3] * inv1);
    }
}

// ---------------- tensor-core TF32 GEMM (double-buffered) ----------------
// C = A[M,K] @ B[K,N] with fused epilogue.
// BM=128, BK=16, 256 threads / 8 warps, __launch_bounds__(256,2).
// EPI: 1 = fused QKV scatter to [B,H,S,DH]; block picks {Wq,Wk,Wv} by n-block
//      2 = acc + bias[n] + res[m*N+n]
//      3 = gelu(acc + bias[n])   (exact erf)
template<int BN, int WARPS_M, int WARPS_N, int EPI>
__global__ __launch_bounds__(256, 2)
void gemm_tc(const float* __restrict__ A, const float* __restrict__ Bg,
             float* __restrict__ C, const float* __restrict__ bias,
             const float* __restrict__ res,
             const float* __restrict__ Bg2, const float* __restrict__ bias2,
             float* __restrict__ C2,
             const float* __restrict__ Bg3, const float* __restrict__ bias3,
             float* __restrict__ C3,
             int M, int N, int K, float scaleval)
{
    constexpr int BM = 128, BK = 16;
    constexpr int WM = BM / WARPS_M, WN = BN / WARPS_N;
    constexpr int MT = WM / 16, NTL = WN / 8;
    constexpr int PAD = 8;

    int n0;
    if constexpr (EPI == 1) {
        const int nb = N / BN;
        const int which = blockIdx.x / nb;
        n0 = (blockIdx.x % nb) * BN;
        if (which == 1) { Bg = Bg2; bias = bias2; C = C2; scaleval = 1.0f; }
        else if (which == 2) { Bg = Bg3; bias = bias3; C = C3; scaleval = 1.0f; }
    } else {
        n0 = blockIdx.x * BN;
    }
    const int m0 = blockIdx.y * BM;

    __shared__ float As[2][BK][BM + PAD];
    __shared__ float Bs[2][BK][BN + PAD];

    const int tid  = threadIdx.x;
    const int warp = tid >> 5, lane = tid & 31;
    const int g = lane >> 2, tig = lane & 3;
    const int wm = warp % WARPS_M, wn = warp / WARPS_M;
    const int m_base = wm * WM, n_base = wn * WN;

    float acc[MT][NTL][4] = {};
    float4 areg[2];
    float4 breg[2];

    auto loadA = [&](int k0) {
#pragma unroll
        for (int i = 0; i < 2; i++) {
            int id = tid * 2 + i;
            int row = id >> 2, c4 = (id & 3) * 4;
            areg[i] = *(const float4*)(A + (long)(m0 + row) * K + k0 + c4);
        }
    };
    auto storeA = [&](int buf) {
#pragma unroll
        for (int i = 0; i < 2; i++) {
            int id = tid * 2 + i;
            int row = id >> 2, c4 = (id & 3) * 4;
            As[buf][c4 + 0][row] = to_tf32(areg[i].x);
            As[buf][c4 + 1][row] = to_tf32(areg[i].y);
            As[buf][c4 + 2][row] = to_tf32(areg[i].z);
            As[buf][c4 + 3][row] = to_tf32(areg[i].w);
        }
    };
    auto loadB = [&](int k0) {
        if constexpr (BN == 128) {
#pragma unroll
            for (int i = 0; i < 2; i++) {
                int id = tid * 2 + i;
                int k = id >> 5, n4 = (id & 31) * 4;
                breg[i] = *(const float4*)(Bg + (long)(k0 + k) * N + n0 + n4);
            }
        } else {  // BN == 64
            int k = tid >> 4, n4 = (tid & 15) * 4;
            breg[0] = *(const float4*)(Bg + (long)(k0 + k) * N + n0 + n4);
        }
    };
    auto storeB = [&](int buf) {
        if constexpr (BN == 128) {
#pragma unroll
            for (int i = 0; i < 2; i++) {
                int id = tid * 2 + i;
                int k = id >> 5, n4 = (id & 31) * 4;
                float4 v = breg[i];
                *(float4*)&Bs[buf][k][n4] = make_float4(to_tf32(v.x), to_tf32(v.y),
                                                        to_tf32(v.z), to_tf32(v.w));
            }
        } else {
            int k = tid >> 4, n4 = (tid & 15) * 4;
            float4 v = breg[0];
            *(float4*)&Bs[buf][k][n4] = make_float4(to_tf32(v.x), to_tf32(v.y),
                                                    to_tf32(v.z), to_tf32(v.w));
        }
    };
    auto compute = [&](int buf) {
#pragma unroll
        for (int ks = 0; ks < 2; ks++) {
            const int kk = ks * 8;
            uint32_t af[MT][4], bf[NTL][2];
#pragma unroll
            for (int mt = 0; mt < MT; mt++) {
                int rr = m_base + mt * 16 + g;
                af[mt][0] = __float_as_uint(As[buf][kk + tig][rr]);
                af[mt][1] = __float_as_uint(As[buf][kk + tig][rr + 8]);
                af[mt][2] = __float_as_uint(As[buf][kk + tig + 4][rr]);
                af[mt][3] = __float_as_uint(As[buf][kk + tig + 4][rr + 8]);
            }
#pragma unroll
            for (int nt = 0; nt < NTL; nt++) {
                int cc = n_base + nt * 8 + g;
                bf[nt][0] = __float_as_uint(Bs[buf][kk + tig][cc]);
                bf[nt][1] = __float_as_uint(Bs[buf][kk + tig + 4][cc]);
            }
#pragma unroll
            for (int mt = 0; mt < MT; mt++)
#pragma unroll
                for (int nt = 0; nt < NTL; nt++)
                    mma_tf32(acc[mt][nt], af[mt], bf[nt]);
        }
    };

    loadA(0); loadB(0);
    storeA(0); storeB(0);
    __syncthreads();
    int buf = 0;
    for (int k0 = BK; k0 < K; k0 += BK) {
        loadA(k0); loadB(k0);
        compute(buf);
        storeA(buf ^ 1); storeB(buf ^ 1);
        __syncthreads();
        buf ^= 1;
    }
    compute(buf);

    auto emit = [&](int m, int n, float v) {
        if constexpr (EPI == 1) {
            v = (v + bias[n]) * scaleval;
            int b = m >> 9, s = m & 511, hh = n >> 6, d = n & 63;
            C[((((long)b * H_ + hh) * S_ + s) * DH_) + d] = v;
        } else if constexpr (EPI == 2) {
            C[(long)m * N + n] = v + bias[n] + res[(long)m * N + n];
        } else if constexpr (EPI == 3) {
            float x = v + bias[n];
            C[(long)m * N + n] = 0.5f * x * (1.0f + erff(x * 0.70710678118654752f));
        }
    };
#pragma unroll
    for (int mt = 0; mt < MT; mt++) {
        int r0 = m0 + m_base + mt * 16 + g;
#pragma unroll
        for (int nt = 0; nt < NTL; nt++) {
            int c0 = n0 + n_base + nt * 8 + 2 * tig;
            emit(r0,     c0,     acc[mt][nt][0]);
            emit(r0,     c0 + 1, acc[mt][nt][1]);
            emit(r0 + 8, c0,     acc[mt][nt][2]);
            emit(r0 + 8, c0 + 1, acc[mt][nt][3]);
        }
    }
}

// ---------------- layernorm over rows of length 768 ----------------
__global__ __launch_bounds__(256)
void layernorm768(const float* __restrict__ x, const float* __restrict__ g,
                  const float* __restrict__ b, float* __restrict__ y)
{
    const float* row = x + (long)blockIdx.x * D_;
    float* orow = y + (long)blockIdx.x * D_;
    int tid = threadIdx.x;
    float a0 = row[tid], a1 = row[tid + 256], a2 = row[tid + 512];
    float s = a0 + a1 + a2;
    float q = a0 * a0 + a1 * a1 + a2 * a2;
    __shared__ float rs[8], rq[8];
#pragma unroll
    for (int o = 16; o; o >>= 1) {
        s += __shfl_xor_sync(0xffffffffu, s, o);
        q += __shfl_xor_sync(0xffffffffu, q, o);
    }
    if ((tid & 31) == 0) { rs[tid >> 5] = s; rq[tid >> 5] = q; }
    __syncthreads();
    s = (rs[0] + rs[1]) + (rs[2] + rs[3]) + (rs[4] + rs[5]) + (rs[6] + rs[7]);
    q = (rq[0] + rq[1]) + (rq[2] + rq[3]) + (rq[4] + rq[5]) + (rq[6] + rq[7]);
    float mean = s * (1.0f / D_);
    float var  = q * (1.0f / D_) - mean * mean;
    float r = rsqrtf(var + 1e-5f);
    orow[tid]       = (a0 - mean) * r * g[tid]       + b[tid];
    orow[tid + 256] = (a1 - mean) * r * g[tid + 256] + b[tid + 256];
    orow[tid + 512] = (a2 - mean) * r * g[tid + 512] + b[tid + 512];
}

// ---------------- host orchestration ----------------
extern "C" void kernel_launch(void* const* d_in, const int* in_sizes, int n_in,
                              void* d_out, int out_size)
{
    const float* hs    = (const float*)d_in[0];
    const float* mask  = (const float*)d_in[1];
    const float* rel   = (const float*)d_in[2];
    const float* rel2  = (const float*)d_in[3];
    const float* Wq    = (const float*)d_in[4];
    const float* bq    = (const float*)d_in[5];
    const float* Wk    = (const float*)d_in[6];
    const float* bk    = (const float*)d_in[7];
    const float* Wv    = (const float*)d_in[8];
    const float* bv    = (const float*)d_in[9];
    const float* Wo    = (const float*)d_in[10];
    const float* bo    = (const float*)d_in[11];
    const float* ln1g  = (const float*)d_in[12];
    const float* ln1b  = (const float*)d_in[13];
    const float* Wi    = (const float*)d_in[14];
    const float* bi    = (const float*)d_in[15];
    const float* Wo2   = (const float*)d_in[16];
    const float* bo2   = (const float*)d_in[17];
    const float* ln2g  = (const float*)d_in[18];
    const float* ln2b  = (const float*)d_in[19];
    float* out = (float*)d_out;

    float *p_bias, *p_q, *p_k, *p_v, *p_ctx, *p_h, *p_tmp, *p_attn, *p_ff;
    cudaGetSymbolAddress((void**)&p_bias,   g_bias);
    cudaGetSymbolAddress((void**)&p_q,      g_q);
    cudaGetSymbolAddress((void**)&p_k,      g_k);
    cudaGetSymbolAddress((void**)&p_v,      g_v);
    cudaGetSymbolAddress((void**)&p_ctx,    g_ctx);
    cudaGetSymbolAddress((void**)&p_h,      g_h);
    cudaGetSymbolAddress((void**)&p_tmp,    g_tmp);
    cudaGetSymbolAddress((void**)&p_attn,   g_attn);
    cudaGetSymbolAddress((void**)&p_ff,     g_ff);

    cudaFuncSetAttribute(flash_attn,
                         cudaFuncAttributeMaxDynamicSharedMemorySize, FLASH_SMEM);

    long nb = (long)BH_ * SS_;
    bias_kernel<<<(unsigned)((nb + 255) / 256), 256>>>(rel, rel2, mask);
    copy_kernel<<<(MR_ * D_ + 255) / 256, 256>>>(hs, p_h, (long)MR_ * D_);

    dim3 gQKV(3 * D_ / 128, MR_ / 128, 1);  // 18 x 16 = 288 (fused Q,K,V)
    dim3 gFA (S_ / 64, BH_, 1);             // 8 x 48 = 384
    dim3 gWo (D_ / 64, MR_ / 128, 1);       // 192
    dim3 gF1 (FF_ / 128, MR_ / 128, 1);     // 384
    dim3 gF2 (D_ / 64, MR_ / 128, 1);       // 192

    for (int l = 0; l < L_; l++) {
        const float* wq  = Wq  + (long)l * D_ * D_;
        const float* wk  = Wk  + (long)l * D_ * D_;
        const float* wv  = Wv  + (long)l * D_ * D_;
        const float* wo  = Wo  + (long)l * D_ * D_;
        const float* wi  = Wi  + (long)l * D_ * FF_;
        const float* wo2 = Wo2 + (long)l * FF_ * D_;

        // fused QKV projections (q folds 1/sqrt(DH)), scattered to [B,H,S,DH]
        gemm_tc<128,2,4,1><<<gQKV, 256>>>(
            p_h, wq, p_q, bq + l * D_, nullptr,
            wk, bk + l * D_, p_k,
            wv, bv + l * D_, p_v,
            MR_, D_, D_, 0.125f);

        // fused attention: scores + bias + softmax + P.V -> ctx [B,S,D]
        flash_attn<<<gFA, 128, FLASH_SMEM>>>(p_q, p_k, p_v, p_bias, p_ctx);

        // attn_out = LN1(ctx @ Wo + bo + h)
        gemm_tc<64,4,2,2><<<gWo, 256>>>(
            p_ctx, wo, p_tmp, bo + l * D_, p_h,
            nullptr, nullptr, nullptr, nullptr, nullptr, nullptr,
            MR_, D_, D_, 1.0f);
        layernorm768<<<MR_, 256>>>(p_tmp, ln1g + l * D_, ln1b + l * D_, p_attn);

        // ff = gelu(attn @ Wi + bi)
        gemm_tc<128,2,4,3><<<gF1, 256>>>(
            p_attn, wi, p_ff, bi + l * FF_, nullptr,
            nullptr, nullptr, nullptr, nullptr, nullptr, nullptr,
            MR_, FF_, D_, 1.0f);

        // out = LN2(ff @ Wo2 + bo2 + attn_out)
        gemm_tc<64,4,2,2><<<gF2, 256>>>(
            p_ff, wo2, p_tmp, bo2 + l * D_, p_attn,
            nullptr, nullptr, nullptr, nullptr, nullptr, nullptr,
            MR_, D_, FF_, 1.0f);
        float* dst = (l == L_ - 1) ? out : p_h;
        layernorm768<<<MR_, 256>>>(p_tmp, ln2g + l * D_, ln2b + l * D_, dst);
    }
}

// round 10
// speedup vs baseline: 1.2096x; 1.1802x over previous
#include <cuda_runtime.h>
#include <math.h>
#include <stdint.h>

// ---------------- problem constants ----------------
#define L_   12
#define B_   4
#define S_   512
#define D_   768
#define H_   12
#define DH_  64
#define FF_  3072
#define BH_  (B_*H_)        // 48
#define MR_  (B_*S_)        // 2048
#define SS_  (S_*S_)        // 262144

// ---------------- scratch (device globals; allocation-free) ----------------
__device__ float g_bias [BH_*SS_];     // fp32 attention bias
__device__ float g_q  [BH_*S_*DH_];    // tf32
__device__ float g_k  [BH_*S_*DH_];    // tf32
__device__ float g_v  [BH_*S_*DH_];    // tf32
__device__ float g_ctx [MR_*D_];       // tf32
__device__ float g_h   [MR_*D_];       // fp32 (residual)
__device__ float g_h32 [MR_*D_];       // tf32 shadow
__device__ float g_tmp [MR_*D_];       // fp32 (LN input)
__device__ float g_attn[MR_*D_];       // fp32 (residual)
__device__ float g_attn32[MR_*D_];     // tf32 shadow
__device__ float g_ff  [MR_*FF_];      // tf32 (gelu out)
// pre-converted tf32 weights
__device__ float g_wq32 [L_*D_*D_];
__device__ float g_wk32 [L_*D_*D_];
__device__ float g_wv32 [L_*D_*D_];
__device__ float g_wo32 [L_*D_*D_];
__device__ float g_wi32 [L_*D_*FF_];
__device__ float g_wo232[L_*FF_*D_];

// ---------------- helpers ----------------
__device__ __forceinline__ float to_tf32(float x)
{
    float r;
    asm("cvt.rna.tf32.f32 %0, %1;" : "=f"(r) : "f"(x));
    return r;
}

__device__ __forceinline__ void mma_tf32(float* c, const uint32_t* a, const uint32_t* b)
{
    asm("mma.sync.aligned.m16n8k8.row.col.f32.tf32.tf32.f32 "
        "{%0,%1,%2,%3}, {%4,%5,%6,%7}, {%8,%9}, {%0,%1,%2,%3};"
        : "+f"(c[0]), "+f"(c[1]), "+f"(c[2]), "+f"(c[3])
        : "r"(a[0]), "r"(a[1]), "r"(a[2]), "r"(a[3]),
          "r"(b[0]), "r"(b[1]));
}

__device__ __forceinline__ void cp16(void* dst, const void* src)
{
    uint32_t d = (uint32_t)__cvta_generic_to_shared(dst);
    asm volatile("cp.async.cg.shared.global [%0], [%1], 16;" :: "r"(d), "l"(src));
}
#define CP_COMMIT() asm volatile("cp.async.commit_group;")

// ---------------- small kernels ----------------
__global__ void bias_kernel(const float* __restrict__ rel,
                            const float* __restrict__ rel2,
                            const float* __restrict__ mask)
{
    long i = (long)blockIdx.x * 256 + threadIdx.x;
    if (i >= (long)BH_ * SS_) return;
    int b = (int)(i / ((long)H_ * SS_));
    int kcol = (int)(i & (S_ - 1));
    g_bias[i] = (rel[i] + rel2[i]) * 0.125f + mask[b * S_ + kcol];
}

__global__ void cvt_kernel(const float* __restrict__ src, float* __restrict__ dst, long n)
{
    long i = (long)blockIdx.x * 256 + threadIdx.x;
    if (i < n) dst[i] = to_tf32(src[i]);
}

__global__ void copy2_kernel(const float* __restrict__ src, float* __restrict__ dst,
                             float* __restrict__ dst32, long n)
{
    long i = (long)blockIdx.x * 256 + threadIdx.x;
    if (i < n) { float v = src[i]; dst[i] = v; dst32[i] = to_tf32(v); }
}

// ---------------- fused flash attention (v2: cp.async, double-buffered K/V) ----
// Grid (S/64, BH). 128 threads / 4 warps, warp owns 16 q-rows.
// Inputs q/k/v already tf32. smem layouts (all conflict-free for frag reads):
//   Q [64][68] row-major (m,c)   : A-frag banks 4g+tig -> distinct
//   K [2][64][68] row-major (n,c): B-frag banks 4g+tig -> distinct
//   V [2][64][72] row-major (k,d): B-frag banks 8tig+g -> distinct
//   P [64][72]    (c,r)          : A-frag banks 8tig+g -> distinct
#define FQ(m,c)   smf[(m)*68 + (c)]
#define FK(s,n,c) smf[4352 + (s)*4352 + (n)*68 + (c)]
#define FV(s,k,d) smf[13056 + (s)*4608 + (k)*72 + (d)]
#define FP(c,r)   smf[22272 + (c)*72 + (r)]
#define FLASH_SMEM (26880 * 4)

__global__ __launch_bounds__(128, 2)
void flash_attn(const float* __restrict__ Qg, const float* __restrict__ Kg,
                const float* __restrict__ Vg, const float* __restrict__ biasg,
                float* __restrict__ ctx)
{
    extern __shared__ float smf[];

    const int z  = blockIdx.y;
    const int q0 = blockIdx.x * 64;
    const int tid  = threadIdx.x;
    const int warp = tid >> 5, lane = tid & 31;
    const int g = lane >> 2, tig = lane & 3;

    const float* Qz = Qg + (long)z * S_ * DH_;
    const float* Kz = Kg + (long)z * S_ * DH_;
    const float* Vz = Vg + (long)z * S_ * DH_;
    const float* bz = biasg + (long)z * SS_;

    // async prologue: Q tile + K0/V0
#pragma unroll
    for (int i = 0; i < 8; i++) {
        int idx = i * 128 + tid;
        int m = idx >> 4, c4 = (idx & 15) << 2;
        cp16(&FQ(m, c4), Qz + (long)(q0 + m) * DH_ + c4);
    }
#pragma unroll
    for (int i = 0; i < 8; i++) {
        int idx = i * 128 + tid;
        int n = idx >> 4, c4 = (idx & 15) << 2;
        cp16(&FK(0, n, c4), Kz + (long)n * DH_ + c4);
        cp16(&FV(0, n, c4), Vz + (long)n * DH_ + c4);
    }
    CP_COMMIT();

    float acc[8][4] = {};
    float mrow0 = -1e30f, mrow1 = -1e30f;
    float l0 = 0.0f, l1 = 0.0f;
    const int r = warp * 16 + g;
    int buf = 0;

    for (int kt = 0; kt < 8; kt++) {
        asm volatile("cp.async.wait_group 0;");
        __syncthreads();
        if (kt < 7) {
#pragma unroll
            for (int i = 0; i < 8; i++) {
                int idx = i * 128 + tid;
                int n = idx >> 4, c4 = (idx & 15) << 2;
                cp16(&FK(buf ^ 1, n, c4), Kz + (long)((kt + 1) * 64 + n) * DH_ + c4);
                cp16(&FV(buf ^ 1, n, c4), Vz + (long)((kt + 1) * 64 + n) * DH_ + c4);
            }
        }
        CP_COMMIT();

        // phase A: S = Q.K^T (q pre-scaled by 1/8)
        float s[8][4] = {};
#pragma unroll
        for (int ks = 0; ks < 8; ks++) {
            const int kk = ks * 8;
            uint32_t af[4];
            af[0] = __float_as_uint(FQ(r,     kk + tig));
            af[1] = __float_as_uint(FQ(r + 8, kk + tig));
            af[2] = __float_as_uint(FQ(r,     kk + tig + 4));
            af[3] = __float_as_uint(FQ(r + 8, kk + tig + 4));
#pragma unroll
            for (int nt = 0; nt < 8; nt++) {
                uint32_t bf[2];
                bf[0] = __float_as_uint(FK(buf, nt * 8 + g, kk + tig));
                bf[1] = __float_as_uint(FK(buf, nt * 8 + g, kk + tig + 4));
                mma_tf32(s[nt], af, bf);
            }
        }

        // bias + online softmax
        const float* brow0 = bz + (long)(q0 + r) * S_ + kt * 64;
        const float* brow1 = brow0 + 8 * S_;
        float nm0 = mrow0, nm1 = mrow1;
#pragma unroll
        for (int nt = 0; nt < 8; nt++) {
            int c = nt * 8 + 2 * tig;
            float2 b0 = *(const float2*)(brow0 + c);
            float2 b1 = *(const float2*)(brow1 + c);
            s[nt][0] += b0.x; s[nt][1] += b0.y;
            s[nt][2] += b1.x; s[nt][3] += b1.y;
            nm0 = fmaxf(nm0, fmaxf(s[nt][0], s[nt][1]));
            nm1 = fmaxf(nm1, fmaxf(s[nt][2], s[nt][3]));
        }
        nm0 = fmaxf(nm0, __shfl_xor_sync(0xffffffffu, nm0, 1));
        nm0 = fmaxf(nm0, __shfl_xor_sync(0xffffffffu, nm0, 2));
        nm1 = fmaxf(nm1, __shfl_xor_sync(0xffffffffu, nm1, 1));
        nm1 = fmaxf(nm1, __shfl_xor_sync(0xffffffffu, nm1, 2));

        float alpha0 = __expf(mrow0 - nm0);
        float alpha1 = __expf(mrow1 - nm1);
        mrow0 = nm0; mrow1 = nm1;

        float rs0 = 0.0f, rs1 = 0.0f;
#pragma unroll
        for (int nt = 0; nt < 8; nt++) {
            int c = nt * 8 + 2 * tig;
            float p0 = __expf(s[nt][0] - nm0);
            float p1 = __expf(s[nt][1] - nm0);
            float p2 = __expf(s[nt][2] - nm1);
            float p3 = __expf(s[nt][3] - nm1);
            rs0 += p0 + p1; rs1 += p2 + p3;
            FP(c,     r)     = to_tf32(p0);
            FP(c + 1, r)     = to_tf32(p1);
            FP(c,     r + 8) = to_tf32(p2);
            FP(c + 1, r + 8) = to_tf32(p3);
            acc[nt][0] *= alpha0; acc[nt][1] *= alpha0;
            acc[nt][2] *= alpha1; acc[nt][3] *= alpha1;
        }
        rs0 += __shfl_xor_sync(0xffffffffu, rs0, 1);
        rs0 += __shfl_xor_sync(0xffffffffu, rs0, 2);
        rs1 += __shfl_xor_sync(0xffffffffu, rs1, 1);
        rs1 += __shfl_xor_sync(0xffffffffu, rs1, 2);
        l0 = l0 * alpha0 + rs0;
        l1 = l1 * alpha1 + rs1;
        __syncwarp();

        // phase C: ctx += P.V
#pragma unroll
        for (int ks = 0; ks < 8; ks++) {
            const int kk = ks * 8;
            uint32_t af[4];
            af[0] = __float_as_uint(FP(kk + tig,     r));
            af[1] = __float_as_uint(FP(kk + tig,     r + 8));
            af[2] = __float_as_uint(FP(kk + tig + 4, r));
            af[3] = __float_as_uint(FP(kk + tig + 4, r + 8));
#pragma unroll
            for (int nt = 0; nt < 8; nt++) {
                uint32_t bf[2];
                bf[0] = __float_as_uint(FV(buf, kk + tig,     nt * 8 + g));
                bf[1] = __float_as_uint(FV(buf, kk + tig + 4, nt * 8 + g));
                mma_tf32(acc[nt], af, bf);
            }
        }
        buf ^= 1;
    }

    // epilogue: normalize, convert to tf32, gather to [B,S,D]
    const float inv0 = 1.0f / l0, inv1 = 1.0f / l1;
    const int b = z / H_, hh = z % H_;
    const int mg = q0 + r;
    float* out0 = ctx + (long)(b * S_ + mg) * D_ + hh * DH_;
    float* out1 = out0 + 8 * D_;
#pragma unroll
    for (int nt = 0; nt < 8; nt++) {
        int c = nt * 8 + 2 * tig;
        *(float2*)(out0 + c) = make_float2(to_tf32(acc[nt][0] * inv0),
                                           to_tf32(acc[nt][1] * inv0));
        *(float2*)(out1 + c) = make_float2(to_tf32(acc[nt][2] * inv1),
                                           to_tf32(acc[nt][3] * inv1));
    }
}

// ---------------- tensor-core TF32 GEMM (cp.async, 4-stage) ----------------
// C = A[M,K] @ B[K,N], all inputs pre-converted tf32. BM=128, BK=16,
// 256 threads / 8 warps. A smem [m][20] (banks 4g+tig), B smem [k][BN+8].
// EPI: 1 = fused QKV scatter (tf32 out), block picks {Wq,Wk,Wv} by n-block
//      2 = acc + bias[n] + res[m*N+n]  (fp32 out)
//      3 = tf32(gelu(acc + bias[n]))
template<int BN, int WARPS_M, int WARPS_N, int EPI>
__global__ __launch_bounds__(256, 2)
void gemm_ca(const float* __restrict__ A, const float* __restrict__ Bg,
             float* __restrict__ C, const float* __restrict__ bias,
             const float* __restrict__ res,
             const float* __restrict__ Bg2, const float* __restrict__ bias2,
             float* __restrict__ C2,
             const float* __restrict__ Bg3, const float* __restrict__ bias3,
             float* __restrict__ C3,
             int M, int N, int K, float scaleval)
{
    constexpr int BM = 128, BK = 16, STAGES = 4;
    constexpr int WM = BM / WARPS_M, WN = BN / WARPS_N;
    constexpr int MT = WM / 16, NTL = WN / 8;
    constexpr int ASTRIDE = BK + 4;       // 20
    constexpr int BSTRIDE = BN + 8;
    constexpr int ASZ = BM * ASTRIDE;     // 2560
    constexpr int BSZ = BK * BSTRIDE;

    extern __shared__ float sm[];
    float* AsB = sm;                       // [STAGES][BM][ASTRIDE]
    float* BsB = sm + STAGES * ASZ;        // [STAGES][BK][BSTRIDE]

    int n0;
    if constexpr (EPI == 1) {
        const int nb = N / BN;
        const int which = blockIdx.x / nb;
        n0 = (blockIdx.x % nb) * BN;
        if (which == 1) { Bg = Bg2; bias = bias2; C = C2; scaleval = 1.0f; }
        else if (which == 2) { Bg = Bg3; bias = bias3; C = C3; scaleval = 1.0f; }
    } else {
        n0 = blockIdx.x * BN;
    }
    const int m0 = blockIdx.y * BM;

    const int tid  = threadIdx.x;
    const int warp = tid >> 5, lane = tid & 31;
    const int g = lane >> 2, tig = lane & 3;
    const int wm = warp % WARPS_M, wn = warp / WARPS_M;
    const int m_base = wm * WM, n_base = wn * WN;

    float acc[MT][NTL][4] = {};

    auto loadTiles = [&](int stage, int kt) {
        const int k0 = kt * BK;
        float* as = AsB + stage * ASZ;
        float* bs = BsB + stage * BSZ;
#pragma unroll
        for (int i = 0; i < 2; i++) {
            int id = tid * 2 + i;
            int m = id >> 2, c4 = (id & 3) * 4;
            cp16(&as[m * ASTRIDE + c4], A + (long)(m0 + m) * K + k0 + c4);
        }
        if constexpr (BN == 128) {
#pragma unroll
            for (int i = 0; i < 2; i++) {
                int id = tid * 2 + i;
                int k = id >> 5, n4 = (id & 31) * 4;
                cp16(&bs[k * BSTRIDE + n4], Bg + (long)(k0 + k) * N + n0 + n4);
            }
        } else {  // BN == 64
            int k = tid >> 4, n4 = (tid & 15) * 4;
            cp16(&bs[k * BSTRIDE + n4], Bg + (long)(k0 + k) * N + n0 + n4);
        }
    };

    auto compute = [&](int stage) {
        const float* as = AsB + stage * ASZ;
        const float* bs = BsB + stage * BSZ;
#pragma unroll
        for (int ks = 0; ks < 2; ks++) {
            const int kk = ks * 8;
            uint32_t af[MT][4], bf[NTL][2];
#pragma unroll
            for (int mt = 0; mt < MT; mt++) {
                int rr = m_base + mt * 16 + g;
                af[mt][0] = __float_as_uint(as[rr * ASTRIDE + kk + tig]);
                af[mt][1] = __float_as_uint(as[(rr + 8) * ASTRIDE + kk + tig]);
                af[mt][2] = __float_as_uint(as[rr * ASTRIDE + kk + tig + 4]);
                af[mt][3] = __float_as_uint(as[(rr + 8) * ASTRIDE + kk + tig + 4]);
            }
#pragma unroll
            for (int nt = 0; nt < NTL; nt++) {
                int cc = n_base + nt * 8 + g;
                bf[nt][0] = __float_as_uint(bs[(kk + tig) * BSTRIDE + cc]);
                bf[nt][1] = __float_as_uint(bs[(kk + tig + 4) * BSTRIDE + cc]);
            }
#pragma unroll
            for (int mt = 0; mt < MT; mt++)
#pragma unroll
                for (int nt = 0; nt < NTL; nt++)
                    mma_tf32(acc[mt][nt], af[mt], bf[nt]);
        }
    };

    const int KT = K / BK;
#pragma unroll
    for (int s = 0; s < STAGES - 1; s++) { loadTiles(s, s); CP_COMMIT(); }

    for (int kt = 0; kt < KT; kt++) {
        asm volatile("cp.async.wait_group 2;");
        __syncthreads();
        const int pf = kt + STAGES - 1;
        if (pf < KT) loadTiles(pf & (STAGES - 1), pf);
        CP_COMMIT();
        compute(kt & (STAGES - 1));
    }

    auto emit = [&](int m, int n, float v) {
        if constexpr (EPI == 1) {
            v = to_tf32((v + bias[n]) * scaleval);
            int b = m >> 9, s = m & 511, hh = n >> 6, d = n & 63;
            C[((((long)b * H_ + hh) * S_ + s) * DH_) + d] = v;
        } else if constexpr (EPI == 2) {
            C[(long)m * N + n] = v + bias[n] + res[(long)m * N + n];
        } else if constexpr (EPI == 3) {
            float x = v + bias[n];
            C[(long)m * N + n] = to_tf32(0.5f * x * (1.0f + erff(x * 0.70710678118654752f)));
        }
    };
#pragma unroll
    for (int mt = 0; mt < MT; mt++) {
        int r0 = m0 + m_base + mt * 16 + g;
#pragma unroll
        for (int nt = 0; nt < NTL; nt++) {
            int c0 = n0 + n_base + nt * 8 + 2 * tig;
            emit(r0,     c0,     acc[mt][nt][0]);
            emit(r0,     c0 + 1, acc[mt][nt][1]);
            emit(r0 + 8, c0,     acc[mt][nt][2]);
            emit(r0 + 8, c0 + 1, acc[mt][nt][3]);
        }
    }
}

// ---------------- layernorm over rows of length 768 (+ tf32 shadow) --------
__global__ __launch_bounds__(256)
void layernorm768(const float* __restrict__ x, const float* __restrict__ g,
                  const float* __restrict__ b, float* __restrict__ y,
                  float* __restrict__ y32)
{
    const float* row = x + (long)blockIdx.x * D_;
    float* orow  = y   + (long)blockIdx.x * D_;
    float* orow2 = y32 + (long)blockIdx.x * D_;
    int tid = threadIdx.x;
    float a0 = row[tid], a1 = row[tid + 256], a2 = row[tid + 512];
    float s = a0 + a1 + a2;
    float q = a0 * a0 + a1 * a1 + a2 * a2;
    __shared__ float rs[8], rq[8];
#pragma unroll
    for (int o = 16; o; o >>= 1) {
        s += __shfl_xor_sync(0xffffffffu, s, o);
        q += __shfl_xor_sync(0xffffffffu, q, o);
    }
    if ((tid & 31) == 0) { rs[tid >> 5] = s; rq[tid >> 5] = q; }
    __syncthreads();
    s = (rs[0] + rs[1]) + (rs[2] + rs[3]) + (rs[4] + rs[5]) + (rs[6] + rs[7]);
    q = (rq[0] + rq[1]) + (rq[2] + rq[3]) + (rq[4] + rq[5]) + (rq[6] + rq[7]);
    float mean = s * (1.0f / D_);
    float var  = q * (1.0f / D_) - mean * mean;
    float r = rsqrtf(var + 1e-5f);
    float v0 = (a0 - mean) * r * g[tid]       + b[tid];
    float v1 = (a1 - mean) * r * g[tid + 256] + b[tid + 256];
    float v2 = (a2 - mean) * r * g[tid + 512] + b[tid + 512];
    orow[tid]        = v0;  orow[tid + 256]  = v1;  orow[tid + 512]  = v2;
    orow2[tid]       = to_tf32(v0);
    orow2[tid + 256] = to_tf32(v1);
    orow2[tid + 512] = to_tf32(v2);
}

// ---------------- host orchestration ----------------
extern "C" void kernel_launch(void* const* d_in, const int* in_sizes, int n_in,
                              void* d_out, int out_size)
{
    const float* hs    = (const float*)d_in[0];
    const float* mask  = (const float*)d_in[1];
    const float* rel   = (const float*)d_in[2];
    const float* rel2  = (const float*)d_in[3];
    const float* Wq    = (const float*)d_in[4];
    const float* bq    = (const float*)d_in[5];
    const float* Wk    = (const float*)d_in[6];
    const float* bk    = (const float*)d_in[7];
    const float* Wv    = (const float*)d_in[8];
    const float* bv    = (const float*)d_in[9];
    const float* Wo    = (const float*)d_in[10];
    const float* bo    = (const float*)d_in[11];
    const float* ln1g  = (const float*)d_in[12];
    const float* ln1b  = (const float*)d_in[13];
    const float* Wi    = (const float*)d_in[14];
    const float* bi    = (const float*)d_in[15];
    const float* Wo2   = (const float*)d_in[16];
    const float* bo2   = (const float*)d_in[17];
    const float* ln2g  = (const float*)d_in[18];
    const float* ln2b  = (const float*)d_in[19];
    float* out = (float*)d_out;

    float *p_bias, *p_q, *p_k, *p_v, *p_ctx, *p_h, *p_h32, *p_tmp,
          *p_attn, *p_attn32, *p_ff;
    float *p_wq, *p_wk, *p_wv, *p_wo, *p_wi, *p_wo2;
    cudaGetSymbolAddress((void**)&p_bias,   g_bias);
    cudaGetSymbolAddress((void**)&p_q,      g_q);
    cudaGetSymbolAddress((void**)&p_k,      g_k);
    cudaGetSymbolAddress((void**)&p_v,      g_v);
    cudaGetSymbolAddress((void**)&p_ctx,    g_ctx);
    cudaGetSymbolAddress((void**)&p_h,      g_h);
    cudaGetSymbolAddress((void**)&p_h32,    g_h32);
    cudaGetSymbolAddress((void**)&p_tmp,    g_tmp);
    cudaGetSymbolAddress((void**)&p_attn,   g_attn);
    cudaGetSymbolAddress((void**)&p_attn32, g_attn32);
    cudaGetSymbolAddress((void**)&p_ff,     g_ff);
    cudaGetSymbolAddress((void**)&p_wq,     g_wq32);
    cudaGetSymbolAddress((void**)&p_wk,     g_wk32);
    cudaGetSymbolAddress((void**)&p_wv,     g_wv32);
    cudaGetSymbolAddress((void**)&p_wo,     g_wo32);
    cudaGetSymbolAddress((void**)&p_wi,     g_wi32);
    cudaGetSymbolAddress((void**)&p_wo2,    g_wo232);

    cudaFuncSetAttribute(flash_attn,
                         cudaFuncAttributeMaxDynamicSharedMemorySize, FLASH_SMEM);
    const int SM_BN128 = (4 * (2560 + 16 * 136)) * 4;   // 75776
    const int SM_BN64  = (4 * (2560 + 16 * 72))  * 4;   // 59392
    cudaFuncSetAttribute(gemm_ca<128,2,4,1>,
                         cudaFuncAttributeMaxDynamicSharedMemorySize, SM_BN128);
    cudaFuncSetAttribute(gemm_ca<128,2,4,3>,
                         cudaFuncAttributeMaxDynamicSharedMemorySize, SM_BN128);
    cudaFuncSetAttribute(gemm_ca<64,4,2,2>,
                         cudaFuncAttributeMaxDynamicSharedMemorySize, SM_BN64);

    // ---- prep: weight tf32 conversion, bias, h/h32 ----
    const long nDD = (long)L_ * D_ * D_;     // 7,077,888
    const long nDF = (long)L_ * D_ * FF_;    // 28,311,552
    cvt_kernel<<<(unsigned)((nDD + 255) / 256), 256>>>(Wq,  p_wq,  nDD);
    cvt_kernel<<<(unsigned)((nDD + 255) / 256), 256>>>(Wk,  p_wk,  nDD);
    cvt_kernel<<<(unsigned)((nDD + 255) / 256), 256>>>(Wv,  p_wv,  nDD);
    cvt_kernel<<<(unsigned)((nDD + 255) / 256), 256>>>(Wo,  p_wo,  nDD);
    cvt_kernel<<<(unsigned)((nDF + 255) / 256), 256>>>(Wi,  p_wi,  nDF);
    cvt_kernel<<<(unsigned)((nDF + 255) / 256), 256>>>(Wo2, p_wo2, nDF);

    long nb = (long)BH_ * SS_;
    bias_kernel<<<(unsigned)((nb + 255) / 256), 256>>>(rel, rel2, mask);
    copy2_kernel<<<(MR_ * D_ + 255) / 256, 256>>>(hs, p_h, p_h32, (long)MR_ * D_);

    dim3 gQKV(3 * D_ / 128, MR_ / 128, 1);  // 288
    dim3 gFA (S_ / 64, BH_, 1);             // 384
    dim3 gWo (D_ / 64, MR_ / 128, 1);       // 192
    dim3 gF1 (FF_ / 128, MR_ / 128, 1);     // 384
    dim3 gF2 (D_ / 64, MR_ / 128, 1);       // 192

    for (int l = 0; l < L_; l++) {
        const float* wq  = p_wq  + (long)l * D_ * D_;
        const float* wk  = p_wk  + (long)l * D_ * D_;
        const float* wv  = p_wv  + (long)l * D_ * D_;
        const float* wo  = p_wo  + (long)l * D_ * D_;
        const float* wi  = p_wi  + (long)l * D_ * FF_;
        const float* wo2 = p_wo2 + (long)l * FF_ * D_;

        // fused QKV projections (q folds 1/8), tf32 scatter to [B,H,S,DH]
        gemm_ca<128,2,4,1><<<gQKV, 256, SM_BN128>>>(
            p_h32, wq, p_q, bq + l * D_, nullptr,
            wk, bk + l * D_, p_k,
            wv, bv + l * D_, p_v,
            MR_, D_, D_, 0.125f);

        // fused attention -> ctx (tf32) [B,S,D]
        flash_attn<<<gFA, 128, FLASH_SMEM>>>(p_q, p_k, p_v, p_bias, p_ctx);

        // attn_out = LN1(ctx @ Wo + bo + h)
        gemm_ca<64,4,2,2><<<gWo, 256, SM_BN64>>>(
            p_ctx, wo, p_tmp, bo + l * D_, p_h,
            nullptr, nullptr, nullptr, nullptr, nullptr, nullptr,
            MR_, D_, D_, 1.0f);
        layernorm768<<<MR_, 256>>>(p_tmp, ln1g + l * D_, ln1b + l * D_,
                                   p_attn, p_attn32);

        // ff = tf32(gelu(attn @ Wi + bi))
        gemm_ca<128,2,4,3><<<gF1, 256, SM_BN128>>>(
            p_attn32, wi, p_ff, bi + l * FF_, nullptr,
            nullptr, nullptr, nullptr, nullptr, nullptr, nullptr,
            MR_, FF_, D_, 1.0f);

        // out = LN2(ff @ Wo2 + bo2 + attn_out)
        gemm_ca<64,4,2,2><<<gF2, 256, SM_BN64>>>(
            p_ff, wo2, p_tmp, bo2 + l * D_, p_attn,
            nullptr, nullptr, nullptr, nullptr, nullptr, nullptr,
            MR_, D_, FF_, 1.0f);
        float* dst = (l == L_ - 1) ? out : p_h;
        layernorm768<<<MR_, 256>>>(p_tmp, ln2g + l * D_, ln2b + l * D_,
                                   dst, p_h32);
    }
}

// round 11
// speedup vs baseline: 1.2396x; 1.0249x over previous
#include <cuda_runtime.h>
#include <cuda_fp16.h>
#include <math.h>
#include <stdint.h>

// ---------------- problem constants ----------------
#define L_   12
#define B_   4
#define S_   512
#define D_   768
#define H_   12
#define DH_  64
#define FF_  3072
#define BH_  (B_*H_)        // 48
#define MR_  (B_*S_)        // 2048
#define SS_  (S_*S_)        // 262144

// ---------------- scratch (device globals; allocation-free) ----------------
__device__ __half g_bias16[BH_*SS_];   // fp16 attention bias (layer-invariant)
__device__ float g_q  [BH_*S_*DH_];    // tf32
__device__ float g_k  [BH_*S_*DH_];    // tf32
__device__ float g_v  [BH_*S_*DH_];    // tf32
__device__ float g_ctx [MR_*D_];       // tf32
__device__ float g_h   [MR_*D_];       // fp32 (residual)
__device__ float g_h32 [MR_*D_];       // tf32 shadow
__device__ float g_tmp [MR_*D_];       // fp32 (LN input)
__device__ float g_attn[MR_*D_];       // fp32 (residual)
__device__ float g_attn32[MR_*D_];     // tf32 shadow
__device__ float g_ff  [MR_*FF_];      // tf32 (gelu out)
// pre-converted tf32 weights
__device__ float g_wq32 [L_*D_*D_];
__device__ float g_wk32 [L_*D_*D_];
__device__ float g_wv32 [L_*D_*D_];
__device__ float g_wo32 [L_*D_*D_];
__device__ float g_wi32 [L_*D_*FF_];
__device__ float g_wo232[L_*FF_*D_];

// ---------------- helpers ----------------
__device__ __forceinline__ float to_tf32(float x)
{
    float r;
    asm("cvt.rna.tf32.f32 %0, %1;" : "=f"(r) : "f"(x));
    return r;
}

__device__ __forceinline__ void mma_tf32(float* c, const uint32_t* a, const uint32_t* b)
{
    asm("mma.sync.aligned.m16n8k8.row.col.f32.tf32.tf32.f32 "
        "{%0,%1,%2,%3}, {%4,%5,%6,%7}, {%8,%9}, {%0,%1,%2,%3};"
        : "+f"(c[0]), "+f"(c[1]), "+f"(c[2]), "+f"(c[3])
        : "r"(a[0]), "r"(a[1]), "r"(a[2]), "r"(a[3]),
          "r"(b[0]), "r"(b[1]));
}

__device__ __forceinline__ void cp16(void* dst, const void* src)
{
    uint32_t d = (uint32_t)__cvta_generic_to_shared(dst);
    asm volatile("cp.async.cg.shared.global [%0], [%1], 16;" :: "r"(d), "l"(src));
}
#define CP_COMMIT() asm volatile("cp.async.commit_group;")

// ---------------- small kernels ----------------
__global__ void bias_kernel(const float* __restrict__ rel,
                            const float* __restrict__ rel2,
                            const float* __restrict__ mask)
{
    long i = (long)blockIdx.x * 256 + threadIdx.x;
    if (i >= (long)BH_ * SS_) return;
    int b = (int)(i / ((long)H_ * SS_));
    int kcol = (int)(i & (S_ - 1));
    g_bias16[i] = __float2half((rel[i] + rel2[i]) * 0.125f + mask[b * S_ + kcol]);
}

__global__ void cvt_kernel(const float* __restrict__ src, float* __restrict__ dst, long n)
{
    long i = (long)blockIdx.x * 256 + threadIdx.x;
    if (i < n) dst[i] = to_tf32(src[i]);
}

__global__ void copy2_kernel(const float* __restrict__ src, float* __restrict__ dst,
                             float* __restrict__ dst32, long n)
{
    long i = (long)blockIdx.x * 256 + threadIdx.x;
    if (i < n) { float v = src[i]; dst[i] = v; dst32[i] = to_tf32(v); }
}

// ---------------- fused flash attention (v3) --------------------------------
// Grid (S/64, BH). 128 threads / 4 warps, warp owns 16 q-rows.
// Changes vs v2: Q fragments hoisted to registers (kt-invariant); Q smem pane
// reused for P; bias stored fp16 and cp.async-prefetched (double-buffered).
// smem (floats):
//   K [2][64][68]  @0      : bf banks (4g+tig+kk)    -> conflict-free
//   V [2][64][72]  @8704   : bf banks (8tig+8nt+g)   -> conflict-free
//   Q  [64][68]    @17920  : af banks (4g+tig)       -> conflict-free (staging)
//   P  [64][72]    @17920  : af banks (8tig+g)       -> conflict-free (reuses Q)
//   bias half [2][64][72]h @22528 : half2 banks (4g+tig+4nt) -> conflict-free
#define FK(s,n,c)  smf[(s)*4352 + (n)*68 + (c)]
#define FV(s,k,d)  smf[8704 + (s)*4608 + (k)*72 + (d)]
#define FQ(m,c)    smf[17920 + (m)*68 + (c)]
#define FP(c,r)    smf[17920 + (c)*72 + (r)]
#define FB_OFF     22528
#define FLASH_SMEM (27136 * 4)   // 108544 B -> 2 CTAs/SM

__global__ __launch_bounds__(128, 2)
void flash_attn(const float* __restrict__ Qg, const float* __restrict__ Kg,
                const float* __restrict__ Vg, const __half* __restrict__ biasg,
                float* __restrict__ ctx)
{
    extern __shared__ float smf[];
    __half* bsm = (__half*)(smf + FB_OFF);   // [2][64][72] halves

    const int z  = blockIdx.y;
    const int q0 = blockIdx.x * 64;
    const int tid  = threadIdx.x;
    const int warp = tid >> 5, lane = tid & 31;
    const int g = lane >> 2, tig = lane & 3;

    const float*  Qz = Qg + (long)z * S_ * DH_;
    const float*  Kz = Kg + (long)z * S_ * DH_;
    const float*  Vz = Vg + (long)z * S_ * DH_;
    const __half* bz = biasg + (long)z * SS_;

    auto loadKVB = [&](int s, int kt) {
#pragma unroll
        for (int i = 0; i < 8; i++) {
            int idx = i * 128 + tid;
            int n = idx >> 4, c4 = (idx & 15) << 2;
            cp16(&FK(s, n, c4), Kz + (long)(kt * 64 + n) * DH_ + c4);
            cp16(&FV(s, n, c4), Vz + (long)(kt * 64 + n) * DH_ + c4);
        }
#pragma unroll
        for (int i = 0; i < 4; i++) {
            int idx = i * 128 + tid;
            int rr = idx >> 3, h8 = (idx & 7) * 8;
            cp16(&bsm[s * 4608 + rr * 72 + h8],
                 bz + (long)(q0 + rr) * S_ + kt * 64 + h8);
        }
    };

    // prologue: Q tile + K0/V0/B0
#pragma unroll
    for (int i = 0; i < 8; i++) {
        int idx = i * 128 + tid;
        int m = idx >> 4, c4 = (idx & 15) << 2;
        cp16(&FQ(m, c4), Qz + (long)(q0 + m) * DH_ + c4);
    }
    loadKVB(0, 0);
    CP_COMMIT();
    asm volatile("cp.async.wait_group 0;");
    __syncthreads();

    const int r = warp * 16 + g;

    // hoist Q fragments to registers (kt-invariant)
    uint32_t afq[8][4];
#pragma unroll
    for (int ks = 0; ks < 8; ks++) {
        const int kk = ks * 8;
        afq[ks][0] = __float_as_uint(FQ(r,     kk + tig));
        afq[ks][1] = __float_as_uint(FQ(r + 8, kk + tig));
        afq[ks][2] = __float_as_uint(FQ(r,     kk + tig + 4));
        afq[ks][3] = __float_as_uint(FQ(r + 8, kk + tig + 4));
    }
    __syncthreads();   // all Q reads done before P overwrites the pane

    float acc[8][4] = {};
    float mrow0 = -1e30f, mrow1 = -1e30f;
    float l0 = 0.0f, l1 = 0.0f;
    int buf = 0;

    for (int kt = 0; kt < 8; kt++) {
        // prefetch next K/V/bias while computing this tile
        if (kt < 7) loadKVB(buf ^ 1, kt + 1);
        CP_COMMIT();

        // phase A: S = Q.K^T (q pre-scaled by 1/8)
        float s[8][4] = {};
#pragma unroll
        for (int ks = 0; ks < 8; ks++) {
            const int kk = ks * 8;
#pragma unroll
            for (int nt = 0; nt < 8; nt++) {
                uint32_t bf[2];
                bf[0] = __float_as_uint(FK(buf, nt * 8 + g, kk + tig));
                bf[1] = __float_as_uint(FK(buf, nt * 8 + g, kk + tig + 4));
                mma_tf32(s[nt], afq[ks], bf);
            }
        }

        // bias (fp16, smem-prefetched) + online softmax
        const __half* bp = bsm + buf * 4608;
        float nm0 = mrow0, nm1 = mrow1;
#pragma unroll
        for (int nt = 0; nt < 8; nt++) {
            int c = nt * 8 + 2 * tig;
            float2 b0 = __half22float2(*(const half2*)(bp + r * 72 + c));
            float2 b1 = __half22float2(*(const half2*)(bp + (r + 8) * 72 + c));
            s[nt][0] += b0.x; s[nt][1] += b0.y;
            s[nt][2] += b1.x; s[nt][3] += b1.y;
            nm0 = fmaxf(nm0, fmaxf(s[nt][0], s[nt][1]));
            nm1 = fmaxf(nm1, fmaxf(s[nt][2], s[nt][3]));
        }
        nm0 = fmaxf(nm0, __shfl_xor_sync(0xffffffffu, nm0, 1));
        nm0 = fmaxf(nm0, __shfl_xor_sync(0xffffffffu, nm0, 2));
        nm1 = fmaxf(nm1, __shfl_xor_sync(0xffffffffu, nm1, 1));
        nm1 = fmaxf(nm1, __shfl_xor_sync(0xffffffffu, nm1, 2));

        float alpha0 = __expf(mrow0 - nm0);
        float alpha1 = __expf(mrow1 - nm1);
        mrow0 = nm0; mrow1 = nm1;

        float rs0 = 0.0f, rs1 = 0.0f;
#pragma unroll
        for (int nt = 0; nt < 8; nt++) {
            int c = nt * 8 + 2 * tig;
            float p0 = __expf(s[nt][0] - nm0);
            float p1 = __expf(s[nt][1] - nm0);
            float p2 = __expf(s[nt][2] - nm1);
            float p3 = __expf(s[nt][3] - nm1);
            rs0 += p0 + p1; rs1 += p2 + p3;
            FP(c,     r)     = to_tf32(p0);
            FP(c + 1, r)     = to_tf32(p1);
            FP(c,     r + 8) = to_tf32(p2);
            FP(c + 1, r + 8) = to_tf32(p3);
            acc[nt][0] *= alpha0; acc[nt][1] *= alpha0;
            acc[nt][2] *= alpha1; acc[nt][3] *= alpha1;
        }
        rs0 += __shfl_xor_sync(0xffffffffu, rs0, 1);
        rs0 += __shfl_xor_sync(0xffffffffu, rs0, 2);
        rs1 += __shfl_xor_sync(0xffffffffu, rs1, 1);
        rs1 += __shfl_xor_sync(0xffffffffu, rs1, 2);
        l0 = l0 * alpha0 + rs0;
        l1 = l1 * alpha1 + rs1;
        __syncwarp();

        // phase C: ctx += P.V
#pragma unroll
        for (int ks = 0; ks < 8; ks++) {
            const int kk = ks * 8;
            uint32_t af[4];
            af[0] = __float_as_uint(FP(kk + tig,     r));
            af[1] = __float_as_uint(FP(kk + tig,     r + 8));
            af[2] = __float_as_uint(FP(kk + tig + 4, r));
            af[3] = __float_as_uint(FP(kk + tig + 4, r + 8));
#pragma unroll
            for (int nt = 0; nt < 8; nt++) {
                uint32_t bf[2];
                bf[0] = __float_as_uint(FV(buf, kk + tig,     nt * 8 + g));
                bf[1] = __float_as_uint(FV(buf, kk + tig + 4, nt * 8 + g));
                mma_tf32(acc[nt], af, bf);
            }
        }

        if (kt < 7) {
            asm volatile("cp.async.wait_group 0;");
            __syncthreads();   // next tiles ready; all warps done with buf
        }
        buf ^= 1;
    }

    // epilogue: normalize, convert to tf32, gather to [B,S,D]
    const float inv0 = 1.0f / l0, inv1 = 1.0f / l1;
    const int b = z / H_, hh = z % H_;
    const int mg = q0 + r;
    float* out0 = ctx + (long)(b * S_ + mg) * D_ + hh * DH_;
    float* out1 = out0 + 8 * D_;
#pragma unroll
    for (int nt = 0; nt < 8; nt++) {
        int c = nt * 8 + 2 * tig;
        *(float2*)(out0 + c) = make_float2(to_tf32(acc[nt][0] * inv0),
                                           to_tf32(acc[nt][1] * inv0));
        *(float2*)(out1 + c) = make_float2(to_tf32(acc[nt][2] * inv1),
                                           to_tf32(acc[nt][3] * inv1));
    }
}

// ---------------- tensor-core TF32 GEMM (cp.async, 4-stage) ----------------
// C = A[M,K] @ B[K,N], all inputs pre-converted tf32. BM=128, BK=16,
// 256 threads / 8 warps. A smem [m][20] (banks 4g+tig), B smem [k][BN+8].
// EPI: 1 = fused QKV scatter (tf32 out), block picks {Wq,Wk,Wv} by n-block
//      2 = acc + bias[n] + res[m*N+n]  (fp32 out)
//      3 = tf32(gelu(acc + bias[n]))
template<int BN, int WARPS_M, int WARPS_N, int EPI>
__global__ __launch_bounds__(256, 2)
void gemm_ca(const float* __restrict__ A, const float* __restrict__ Bg,
             float* __restrict__ C, const float* __restrict__ bias,
             const float* __restrict__ res,
             const float* __restrict__ Bg2, const float* __restrict__ bias2,
             float* __restrict__ C2,
             const float* __restrict__ Bg3, const float* __restrict__ bias3,
             float* __restrict__ C3,
             int M, int N, int K, float scaleval)
{
    constexpr int BM = 128, BK = 16, STAGES = 4;
    constexpr int WM = BM / WARPS_M, WN = BN / WARPS_N;
    constexpr int MT = WM / 16, NTL = WN / 8;
    constexpr int ASTRIDE = BK + 4;       // 20
    constexpr int BSTRIDE = BN + 8;
    constexpr int ASZ = BM * ASTRIDE;     // 2560
    constexpr int BSZ = BK * BSTRIDE;

    extern __shared__ float sm[];
    float* AsB = sm;                       // [STAGES][BM][ASTRIDE]
    float* BsB = sm + STAGES * ASZ;        // [STAGES][BK][BSTRIDE]

    int n0;
    if constexpr (EPI == 1) {
        const int nb = N / BN;
        const int which = blockIdx.x / nb;
        n0 = (blockIdx.x % nb) * BN;
        if (which == 1) { Bg = Bg2; bias = bias2; C = C2; scaleval = 1.0f; }
        else if (which == 2) { Bg = Bg3; bias = bias3; C = C3; scaleval = 1.0f; }
    } else {
        n0 = blockIdx.x * BN;
    }
    const int m0 = blockIdx.y * BM;

    const int tid  = threadIdx.x;
    const int warp = tid >> 5, lane = tid & 31;
    const int g = lane >> 2, tig = lane & 3;
    const int wm = warp % WARPS_M, wn = warp / WARPS_M;
    const int m_base = wm * WM, n_base = wn * WN;

    float acc[MT][NTL][4] = {};

    auto loadTiles = [&](int stage, int kt) {
        const int k0 = kt * BK;
        float* as = AsB + stage * ASZ;
        float* bs = BsB + stage * BSZ;
#pragma unroll
        for (int i = 0; i < 2; i++) {
            int id = tid * 2 + i;
            int m = id >> 2, c4 = (id & 3) * 4;
            cp16(&as[m * ASTRIDE + c4], A + (long)(m0 + m) * K + k0 + c4);
        }
        if constexpr (BN == 128) {
#pragma unroll
            for (int i = 0; i < 2; i++) {
                int id = tid * 2 + i;
                int k = id >> 5, n4 = (id & 31) * 4;
                cp16(&bs[k * BSTRIDE + n4], Bg + (long)(k0 + k) * N + n0 + n4);
            }
        } else {  // BN == 64
            int k = tid >> 4, n4 = (tid & 15) * 4;
            cp16(&bs[k * BSTRIDE + n4], Bg + (long)(k0 + k) * N + n0 + n4);
        }
    };

    auto compute = [&](int stage) {
        const float* as = AsB + stage * ASZ;
        const float* bs = BsB + stage * BSZ;
#pragma unroll
        for (int ks = 0; ks < 2; ks++) {
            const int kk = ks * 8;
            uint32_t af[MT][4], bf[NTL][2];
#pragma unroll
            for (int mt = 0; mt < MT; mt++) {
                int rr = m_base + mt * 16 + g;
                af[mt][0] = __float_as_uint(as[rr * ASTRIDE + kk + tig]);
                af[mt][1] = __float_as_uint(as[(rr + 8) * ASTRIDE + kk + tig]);
                af[mt][2] = __float_as_uint(as[rr * ASTRIDE + kk + tig + 4]);
                af[mt][3] = __float_as_uint(as[(rr + 8) * ASTRIDE + kk + tig + 4]);
            }
#pragma unroll
            for (int nt = 0; nt < NTL; nt++) {
                int cc = n_base + nt * 8 + g;
                bf[nt][0] = __float_as_uint(bs[(kk + tig) * BSTRIDE + cc]);
                bf[nt][1] = __float_as_uint(bs[(kk + tig + 4) * BSTRIDE + cc]);
            }
#pragma unroll
            for (int mt = 0; mt < MT; mt++)
#pragma unroll
                for (int nt = 0; nt < NTL; nt++)
                    mma_tf32(acc[mt][nt], af[mt], bf[nt]);
        }
    };

    const int KT = K / BK;
#pragma unroll
    for (int s = 0; s < STAGES - 1; s++) { loadTiles(s, s); CP_COMMIT(); }

    for (int kt = 0; kt < KT; kt++) {
        asm volatile("cp.async.wait_group 2;");
        __syncthreads();
        const int pf = kt + STAGES - 1;
        if (pf < KT) loadTiles(pf & (STAGES - 1), pf);
        CP_COMMIT();
        compute(kt & (STAGES - 1));
    }

    auto emit = [&](int m, int n, float v) {
        if constexpr (EPI == 1) {
            v = to_tf32((v + bias[n]) * scaleval);
            int b = m >> 9, s = m & 511, hh = n >> 6, d = n & 63;
            C[((((long)b * H_ + hh) * S_ + s) * DH_) + d] = v;
        } else if constexpr (EPI == 2) {
            C[(long)m * N + n] = v + bias[n] + res[(long)m * N + n];
        } else if constexpr (EPI == 3) {
            float x = v + bias[n];
            C[(long)m * N + n] = to_tf32(0.5f * x * (1.0f + erff(x * 0.70710678118654752f)));
        }
    };
#pragma unroll
    for (int mt = 0; mt < MT; mt++) {
        int r0 = m0 + m_base + mt * 16 + g;
#pragma unroll
        for (int nt = 0; nt < NTL; nt++) {
            int c0 = n0 + n_base + nt * 8 + 2 * tig;
            emit(r0,     c0,     acc[mt][nt][0]);
            emit(r0,     c0 + 1, acc[mt][nt][1]);
            emit(r0 + 8, c0,     acc[mt][nt][2]);
            emit(r0 + 8, c0 + 1, acc[mt][nt][3]);
        }
    }
}

// ---------------- layernorm over rows of length 768 (+ tf32 shadow) --------
__global__ __launch_bounds__(256)
void layernorm768(const float* __restrict__ x, const float* __restrict__ g,
                  const float* __restrict__ b, float* __restrict__ y,
                  float* __restrict__ y32)
{
    const float* row = x + (long)blockIdx.x * D_;
    float* orow  = y   + (long)blockIdx.x * D_;
    float* orow2 = y32 + (long)blockIdx.x * D_;
    int tid = threadIdx.x;
    float a0 = row[tid], a1 = row[tid + 256], a2 = row[tid + 512];
    float s = a0 + a1 + a2;
    float q = a0 * a0 + a1 * a1 + a2 * a2;
    __shared__ float rs[8], rq[8];
#pragma unroll
    for (int o = 16; o; o >>= 1) {
        s += __shfl_xor_sync(0xffffffffu, s, o);
        q += __shfl_xor_sync(0xffffffffu, q, o);
    }
    if ((tid & 31) == 0) { rs[tid >> 5] = s; rq[tid >> 5] = q; }
    __syncthreads();
    s = (rs[0] + rs[1]) + (rs[2] + rs[3]) + (rs[4] + rs[5]) + (rs[6] + rs[7]);
    q = (rq[0] + rq[1]) + (rq[2] + rq[3]) + (rq[4] + rq[5]) + (rq[6] + rq[7]);
    float mean = s * (1.0f / D_);
    float var  = q * (1.0f / D_) - mean * mean;
    float r = rsqrtf(var + 1e-5f);
    float v0 = (a0 - mean) * r * g[tid]       + b[tid];
    float v1 = (a1 - mean) * r * g[tid + 256] + b[tid + 256];
    float v2 = (a2 - mean) * r * g[tid + 512] + b[tid + 512];
    orow[tid]        = v0;  orow[tid + 256]  = v1;  orow[tid + 512]  = v2;
    orow2[tid]       = to_tf32(v0);
    orow2[tid + 256] = to_tf32(v1);
    orow2[tid + 512] = to_tf32(v2);
}

// ---------------- host orchestration ----------------
extern "C" void kernel_launch(void* const* d_in, const int* in_sizes, int n_in,
                              void* d_out, int out_size)
{
    const float* hs    = (const float*)d_in[0];
    const float* mask  = (const float*)d_in[1];
    const float* rel   = (const float*)d_in[2];
    const float* rel2  = (const float*)d_in[3];
    const float* Wq    = (const float*)d_in[4];
    const float* bq    = (const float*)d_in[5];
    const float* Wk    = (const float*)d_in[6];
    const float* bk    = (const float*)d_in[7];
    const float* Wv    = (const float*)d_in[8];
    const float* bv    = (const float*)d_in[9];
    const float* Wo    = (const float*)d_in[10];
    const float* bo    = (const float*)d_in[11];
    const float* ln1g  = (const float*)d_in[12];
    const float* ln1b  = (const float*)d_in[13];
    const float* Wi    = (const float*)d_in[14];
    const float* bi    = (const float*)d_in[15];
    const float* Wo2   = (const float*)d_in[16];
    const float* bo2   = (const float*)d_in[17];
    const float* ln2g  = (const float*)d_in[18];
    const float* ln2b  = (const float*)d_in[19];
    float* out = (float*)d_out;

    float *p_q, *p_k, *p_v, *p_ctx, *p_h, *p_h32, *p_tmp,
          *p_attn, *p_attn32, *p_ff;
    float *p_wq, *p_wk, *p_wv, *p_wo, *p_wi, *p_wo2;
    __half* p_bias16;
    cudaGetSymbolAddress((void**)&p_bias16, g_bias16);
    cudaGetSymbolAddress((void**)&p_q,      g_q);
    cudaGetSymbolAddress((void**)&p_k,      g_k);
    cudaGetSymbolAddress((void**)&p_v,      g_v);
    cudaGetSymbolAddress((void**)&p_ctx,    g_ctx);
    cudaGetSymbolAddress((void**)&p_h,      g_h);
    cudaGetSymbolAddress((void**)&p_h32,    g_h32);
    cudaGetSymbolAddress((void**)&p_tmp,    g_tmp);
    cudaGetSymbolAddress((void**)&p_attn,   g_attn);
    cudaGetSymbolAddress((void**)&p_attn32, g_attn32);
    cudaGetSymbolAddress((void**)&p_ff,     g_ff);
    cudaGetSymbolAddress((void**)&p_wq,     g_wq32);
    cudaGetSymbolAddress((void**)&p_wk,     g_wk32);
    cudaGetSymbolAddress((void**)&p_wv,     g_wv32);
    cudaGetSymbolAddress((void**)&p_wo,     g_wo32);
    cudaGetSymbolAddress((void**)&p_wi,     g_wi32);
    cudaGetSymbolAddress((void**)&p_wo2,    g_wo232);

    cudaFuncSetAttribute(flash_attn,
                         cudaFuncAttributeMaxDynamicSharedMemorySize, FLASH_SMEM);
    const int SM_BN128 = (4 * (2560 + 16 * 136)) * 4;   // 75776
    const int SM_BN64  = (4 * (2560 + 16 * 72))  * 4;   // 59392
    cudaFuncSetAttribute(gemm_ca<128,2,4,1>,
                         cudaFuncAttributeMaxDynamicSharedMemorySize, SM_BN128);
    cudaFuncSetAttribute(gemm_ca<128,2,4,3>,
                         cudaFuncAttributeMaxDynamicSharedMemorySize, SM_BN128);
    cudaFuncSetAttribute(gemm_ca<64,4,2,2>,
                         cudaFuncAttributeMaxDynamicSharedMemorySize, SM_BN64);

    // ---- prep: weight tf32 conversion, bias (fp16), h/h32 ----
    const long nDD = (long)L_ * D_ * D_;
    const long nDF = (long)L_ * D_ * FF_;
    cvt_kernel<<<(unsigned)((nDD + 255) / 256), 256>>>(Wq,  p_wq,  nDD);
    cvt_kernel<<<(unsigned)((nDD + 255) / 256), 256>>>(Wk,  p_wk,  nDD);
    cvt_kernel<<<(unsigned)((nDD + 255) / 256), 256>>>(Wv,  p_wv,  nDD);
    cvt_kernel<<<(unsigned)((nDD + 255) / 256), 256>>>(Wo,  p_wo,  nDD);
    cvt_kernel<<<(unsigned)((nDF + 255) / 256), 256>>>(Wi,  p_wi,  nDF);
    cvt_kernel<<<(unsigned)((nDF + 255) / 256), 256>>>(Wo2, p_wo2, nDF);

    long nb = (long)BH_ * SS_;
    bias_kernel<<<(unsigned)((nb + 255) / 256), 256>>>(rel, rel2, mask);
    copy2_kernel<<<(MR_ * D_ + 255) / 256, 256>>>(hs, p_h, p_h32, (long)MR_ * D_);

    dim3 gQKV(3 * D_ / 128, MR_ / 128, 1);  // 288
    dim3 gFA (S_ / 64, BH_, 1);             // 384
    dim3 gWo (D_ / 64, MR_ / 128, 1);       // 192
    dim3 gF1 (FF_ / 128, MR_ / 128, 1);     // 384
    dim3 gF2 (D_ / 64, MR_ / 128, 1);       // 192

    for (int l = 0; l < L_; l++) {
        const float* wq  = p_wq  + (long)l * D_ * D_;
        const float* wk  = p_wk  + (long)l * D_ * D_;
        const float* wv  = p_wv  + (long)l * D_ * D_;
        const float* wo  = p_wo  + (long)l * D_ * D_;
        const float* wi  = p_wi  + (long)l * D_ * FF_;
        const float* wo2 = p_wo2 + (long)l * FF_ * D_;

        // fused QKV projections (q folds 1/8), tf32 scatter to [B,H,S,DH]
        gemm_ca<128,2,4,1><<<gQKV, 256, SM_BN128>>>(
            p_h32, wq, p_q, bq + l * D_, nullptr,
            wk, bk + l * D_, p_k,
            wv, bv + l * D_, p_v,
            MR_, D_, D_, 0.125f);

        // fused attention -> ctx (tf32) [B,S,D]
        flash_attn<<<gFA, 128, FLASH_SMEM>>>(p_q, p_k, p_v, p_bias16, p_ctx);

        // attn_out = LN1(ctx @ Wo + bo + h)
        gemm_ca<64,4,2,2><<<gWo, 256, SM_BN64>>>(
            p_ctx, wo, p_tmp, bo + l * D_, p_h,
            nullptr, nullptr, nullptr, nullptr, nullptr, nullptr,
            MR_, D_, D_, 1.0f);
        layernorm768<<<MR_, 256>>>(p_tmp, ln1g + l * D_, ln1b + l * D_,
                                   p_attn, p_attn32);

        // ff = tf32(gelu(attn @ Wi + bi))
        gemm_ca<128,2,4,3><<<gF1, 256, SM_BN128>>>(
            p_attn32, wi, p_ff, bi + l * FF_, nullptr,
            nullptr, nullptr, nullptr, nullptr, nullptr, nullptr,
            MR_, FF_, D_, 1.0f);

        // out = LN2(ff @ Wo2 + bo2 + attn_out)
        gemm_ca<64,4,2,2><<<gF2, 256, SM_BN64>>>(
            p_ff, wo2, p_tmp, bo2 + l * D_, p_attn,
            nullptr, nullptr, nullptr, nullptr, nullptr, nullptr,
            MR_, D_, FF_, 1.0f);
        float* dst = (l == L_ - 1) ? out : p_h;
        layernorm768<<<MR_, 256>>>(p_tmp, ln2g + l * D_, ln2b + l * D_,
                                   dst, p_h32);
    }
}

// round 12
// speedup vs baseline: 1.4219x; 1.1470x over previous
#include <cuda_runtime.h>
#include <cuda_fp16.h>
#include <math.h>
#include <stdint.h>

// ---------------- problem constants ----------------
#define L_   12
#define B_   4
#define S_   512
#define D_   768
#define H_   12
#define DH_  64
#define FF_  3072
#define BH_  (B_*H_)        // 48
#define MR_  (B_*S_)        // 2048
#define SS_  (S_*S_)        // 262144

// ---------------- scratch (device globals; allocation-free) ----------------
__device__ __half g_bias16[BH_*SS_];   // fp16 attention bias (layer-invariant)
__device__ float g_q  [BH_*S_*DH_];    // tf32
__device__ float g_k  [BH_*S_*DH_];    // tf32
__device__ float g_v  [BH_*S_*DH_];    // tf32
__device__ float g_ctx [MR_*D_];       // tf32
__device__ float g_h   [MR_*D_];       // fp32 (residual)
__device__ float g_h32 [MR_*D_];       // tf32 shadow
__device__ float g_attn[MR_*D_];       // fp32 (residual)
__device__ float g_attn32[MR_*D_];     // tf32 shadow
__device__ float g_ff  [MR_*FF_];      // tf32 (gelu out)
__device__ float g_part[2*MR_*D_];     // split-K partials
// pre-converted tf32 weights
__device__ float g_wq32 [L_*D_*D_];
__device__ float g_wk32 [L_*D_*D_];
__device__ float g_wv32 [L_*D_*D_];
__device__ float g_wo32 [L_*D_*D_];
__device__ float g_wi32 [L_*D_*FF_];
__device__ float g_wo232[L_*FF_*D_];

// ---------------- helpers ----------------
__device__ __forceinline__ float to_tf32(float x)
{
    float r;
    asm("cvt.rna.tf32.f32 %0, %1;" : "=f"(r) : "f"(x));
    return r;
}

__device__ __forceinline__ void mma_tf32(float* c, const uint32_t* a, const uint32_t* b)
{
    asm("mma.sync.aligned.m16n8k8.row.col.f32.tf32.tf32.f32 "
        "{%0,%1,%2,%3}, {%4,%5,%6,%7}, {%8,%9}, {%0,%1,%2,%3};"
        : "+f"(c[0]), "+f"(c[1]), "+f"(c[2]), "+f"(c[3])
        : "r"(a[0]), "r"(a[1]), "r"(a[2]), "r"(a[3]),
          "r"(b[0]), "r"(b[1]));
}

__device__ __forceinline__ void cp16(void* dst, const void* src)
{
    uint32_t d = (uint32_t)__cvta_generic_to_shared(dst);
    asm volatile("cp.async.cg.shared.global [%0], [%1], 16;" :: "r"(d), "l"(src));
}
#define CP_COMMIT() asm volatile("cp.async.commit_group;")

// ---------------- small kernels ----------------
__global__ void bias_kernel(const float* __restrict__ rel,
                            const float* __restrict__ rel2,
                            const float* __restrict__ mask)
{
    long i = (long)blockIdx.x * 256 + threadIdx.x;
    if (i >= (long)BH_ * SS_) return;
    int b = (int)(i / ((long)H_ * SS_));
    int kcol = (int)(i & (S_ - 1));
    g_bias16[i] = __float2half((rel[i] + rel2[i]) * 0.125f + mask[b * S_ + kcol]);
}

__global__ void cvt_kernel(const float* __restrict__ src, float* __restrict__ dst, long n)
{
    long i = (long)blockIdx.x * 256 + threadIdx.x;
    if (i < n) dst[i] = to_tf32(src[i]);
}

__global__ void copy2_kernel(const float* __restrict__ src, float* __restrict__ dst,
                             float* __restrict__ dst32, long n)
{
    long i = (long)blockIdx.x * 256 + threadIdx.x;
    if (i < n) { float v = src[i]; dst[i] = v; dst32[i] = to_tf32(v); }
}

// ---------------- fused flash attention (v3) --------------------------------
#define FK(s,n,c)  smf[(s)*4352 + (n)*68 + (c)]
#define FV(s,k,d)  smf[8704 + (s)*4608 + (k)*72 + (d)]
#define FQ(m,c)    smf[17920 + (m)*68 + (c)]
#define FP(c,r)    smf[17920 + (c)*72 + (r)]
#define FB_OFF     22528
#define FLASH_SMEM (27136 * 4)   // 108544 B -> 2 CTAs/SM

__global__ __launch_bounds__(128, 2)
void flash_attn(const float* __restrict__ Qg, const float* __restrict__ Kg,
                const float* __restrict__ Vg, const __half* __restrict__ biasg,
                float* __restrict__ ctx)
{
    extern __shared__ float smf[];
    __half* bsm = (__half*)(smf + FB_OFF);   // [2][64][72] halves

    const int z  = blockIdx.y;
    const int q0 = blockIdx.x * 64;
    const int tid  = threadIdx.x;
    const int warp = tid >> 5, lane = tid & 31;
    const int g = lane >> 2, tig = lane & 3;

    const float*  Qz = Qg + (long)z * S_ * DH_;
    const float*  Kz = Kg + (long)z * S_ * DH_;
    const float*  Vz = Vg + (long)z * S_ * DH_;
    const __half* bz = biasg + (long)z * SS_;

    auto loadKVB = [&](int s, int kt) {
#pragma unroll
        for (int i = 0; i < 8; i++) {
            int idx = i * 128 + tid;
            int n = idx >> 4, c4 = (idx & 15) << 2;
            cp16(&FK(s, n, c4), Kz + (long)(kt * 64 + n) * DH_ + c4);
            cp16(&FV(s, n, c4), Vz + (long)(kt * 64 + n) * DH_ + c4);
        }
#pragma unroll
        for (int i = 0; i < 4; i++) {
            int idx = i * 128 + tid;
            int rr = idx >> 3, h8 = (idx & 7) * 8;
            cp16(&bsm[s * 4608 + rr * 72 + h8],
                 bz + (long)(q0 + rr) * S_ + kt * 64 + h8);
        }
    };

    // prologue: Q tile + K0/V0/B0
#pragma unroll
    for (int i = 0; i < 8; i++) {
        int idx = i * 128 + tid;
        int m = idx >> 4, c4 = (idx & 15) << 2;
        cp16(&FQ(m, c4), Qz + (long)(q0 + m) * DH_ + c4);
    }
    loadKVB(0, 0);
    CP_COMMIT();
    asm volatile("cp.async.wait_group 0;");
    __syncthreads();

    const int r = warp * 16 + g;

    // hoist Q fragments to registers (kt-invariant)
    uint32_t afq[8][4];
#pragma unroll
    for (int ks = 0; ks < 8; ks++) {
        const int kk = ks * 8;
        afq[ks][0] = __float_as_uint(FQ(r,     kk + tig));
        afq[ks][1] = __float_as_uint(FQ(r + 8, kk + tig));
        afq[ks][2] = __float_as_uint(FQ(r,     kk + tig + 4));
        afq[ks][3] = __float_as_uint(FQ(r + 8, kk + tig + 4));
    }
    __syncthreads();   // all Q reads done before P overwrites the pane

    float acc[8][4] = {};
    float mrow0 = -1e30f, mrow1 = -1e30f;
    float l0 = 0.0f, l1 = 0.0f;
    int buf = 0;

    for (int kt = 0; kt < 8; kt++) {
        if (kt < 7) loadKVB(buf ^ 1, kt + 1);
        CP_COMMIT();

        // phase A: S = Q.K^T (q pre-scaled by 1/8)
        float s[8][4] = {};
#pragma unroll
        for (int ks = 0; ks < 8; ks++) {
            const int kk = ks * 8;
#pragma unroll
            for (int nt = 0; nt < 8; nt++) {
                uint32_t bf[2];
                bf[0] = __float_as_uint(FK(buf, nt * 8 + g, kk + tig));
                bf[1] = __float_as_uint(FK(buf, nt * 8 + g, kk + tig + 4));
                mma_tf32(s[nt], afq[ks], bf);
            }
        }

        // bias (fp16, smem-prefetched) + online softmax
        const __half* bp = bsm + buf * 4608;
        float nm0 = mrow0, nm1 = mrow1;
#pragma unroll
        for (int nt = 0; nt < 8; nt++) {
            int c = nt * 8 + 2 * tig;
            float2 b0 = __half22float2(*(const half2*)(bp + r * 72 + c));
            float2 b1 = __half22float2(*(const half2*)(bp + (r + 8) * 72 + c));
            s[nt][0] += b0.x; s[nt][1] += b0.y;
            s[nt][2] += b1.x; s[nt][3] += b1.y;
            nm0 = fmaxf(nm0, fmaxf(s[nt][0], s[nt][1]));
            nm1 = fmaxf(nm1, fmaxf(s[nt][2], s[nt][3]));
        }
        nm0 = fmaxf(nm0, __shfl_xor_sync(0xffffffffu, nm0, 1));
        nm0 = fmaxf(nm0, __shfl_xor_sync(0xffffffffu, nm0, 2));
        nm1 = fmaxf(nm1, __shfl_xor_sync(0xffffffffu, nm1, 1));
        nm1 = fmaxf(nm1, __shfl_xor_sync(0xffffffffu, nm1, 2));

        float alpha0 = __expf(mrow0 - nm0);
        float alpha1 = __expf(mrow1 - nm1);
        mrow0 = nm0; mrow1 = nm1;

        float rs0 = 0.0f, rs1 = 0.0f;
#pragma unroll
        for (int nt = 0; nt < 8; nt++) {
            int c = nt * 8 + 2 * tig;
            float p0 = __expf(s[nt][0] - nm0);
            float p1 = __expf(s[nt][1] - nm0);
            float p2 = __expf(s[nt][2] - nm1);
            float p3 = __expf(s[nt][3] - nm1);
            rs0 += p0 + p1; rs1 += p2 + p3;
            FP(c,     r)     = to_tf32(p0);
            FP(c + 1, r)     = to_tf32(p1);
            FP(c,     r + 8) = to_tf32(p2);
            FP(c + 1, r + 8) = to_tf32(p3);
            acc[nt][0] *= alpha0; acc[nt][1] *= alpha0;
            acc[nt][2] *= alpha1; acc[nt][3] *= alpha1;
        }
        rs0 += __shfl_xor_sync(0xffffffffu, rs0, 1);
        rs0 += __shfl_xor_sync(0xffffffffu, rs0, 2);
        rs1 += __shfl_xor_sync(0xffffffffu, rs1, 1);
        rs1 += __shfl_xor_sync(0xffffffffu, rs1, 2);
        l0 = l0 * alpha0 + rs0;
        l1 = l1 * alpha1 + rs1;
        __syncwarp();

        // phase C: ctx += P.V
#pragma unroll
        for (int ks = 0; ks < 8; ks++) {
            const int kk = ks * 8;
            uint32_t af[4];
            af[0] = __float_as_uint(FP(kk + tig,     r));
            af[1] = __float_as_uint(FP(kk + tig,     r + 8));
            af[2] = __float_as_uint(FP(kk + tig + 4, r));
            af[3] = __float_as_uint(FP(kk + tig + 4, r + 8));
#pragma unroll
            for (int nt = 0; nt < 8; nt++) {
                uint32_t bf[2];
                bf[0] = __float_as_uint(FV(buf, kk + tig,     nt * 8 + g));
                bf[1] = __float_as_uint(FV(buf, kk + tig + 4, nt * 8 + g));
                mma_tf32(acc[nt], af, bf);
            }
        }

        if (kt < 7) {
            asm volatile("cp.async.wait_group 0;");
            __syncthreads();
        }
        buf ^= 1;
    }

    // epilogue: normalize, convert to tf32, gather to [B,S,D]
    const float inv0 = 1.0f / l0, inv1 = 1.0f / l1;
    const int b = z / H_, hh = z % H_;
    const int mg = q0 + r;
    float* out0 = ctx + (long)(b * S_ + mg) * D_ + hh * DH_;
    float* out1 = out0 + 8 * D_;
#pragma unroll
    for (int nt = 0; nt < 8; nt++) {
        int c = nt * 8 + 2 * tig;
        *(float2*)(out0 + c) = make_float2(to_tf32(acc[nt][0] * inv0),
                                           to_tf32(acc[nt][1] * inv0));
        *(float2*)(out1 + c) = make_float2(to_tf32(acc[nt][2] * inv1),
                                           to_tf32(acc[nt][3] * inv1));
    }
}

// ---------------- tensor-core TF32 GEMM (cp.async, 4-stage, split-K) --------
// C = A[M,K_total] @ B[K_total,N]; grid.z = split index, each split does K
// columns starting at z*K. lda = A row stride (full K_total).
// EPI: 0 = raw partial store to C + z*M*N (for fused LN reduce)
//      1 = fused QKV scatter (tf32 out), block picks {Wq,Wk,Wv} by n-block
//      3 = tf32(gelu(acc + bias[n]))
template<int BN, int WARPS_M, int WARPS_N, int EPI>
__global__ __launch_bounds__(256, 2)
void gemm_ca(const float* __restrict__ A, const float* __restrict__ Bg,
             float* __restrict__ C, const float* __restrict__ bias,
             const float* __restrict__ Bg2, const float* __restrict__ bias2,
             float* __restrict__ C2,
             const float* __restrict__ Bg3, const float* __restrict__ bias3,
             float* __restrict__ C3,
             int M, int N, int K, int lda, float scaleval)
{
    constexpr int BM = 128, BK = 16, STAGES = 4;
    constexpr int WM = BM / WARPS_M, WN = BN / WARPS_N;
    constexpr int MT = WM / 16, NTL = WN / 8;
    constexpr int ASTRIDE = BK + 4;       // 20
    constexpr int BSTRIDE = BN + 8;
    constexpr int ASZ = BM * ASTRIDE;
    constexpr int BSZ = BK * BSTRIDE;

    extern __shared__ float sm[];
    float* AsB = sm;
    float* BsB = sm + STAGES * ASZ;

    const int zz = blockIdx.z;
    A  += (long)zz * K;          // K-split column offset (lda is full stride)
    Bg += (long)zz * K * N;      // K-split row offset

    int n0;
    if constexpr (EPI == 1) {
        const int nb = N / BN;
        const int which = blockIdx.x / nb;
        n0 = (blockIdx.x % nb) * BN;
        if (which == 1) { Bg = Bg2; bias = bias2; C = C2; scaleval = 1.0f; }
        else if (which == 2) { Bg = Bg3; bias = bias3; C = C3; scaleval = 1.0f; }
    } else {
        n0 = blockIdx.x * BN;
    }
    float* Cw = C;
    if constexpr (EPI == 0) Cw = C + (long)zz * M * N;

    const int m0 = blockIdx.y * BM;
    const int tid  = threadIdx.x;
    const int warp = tid >> 5, lane = tid & 31;
    const int g = lane >> 2, tig = lane & 3;
    const int wm = warp % WARPS_M, wn = warp / WARPS_M;
    const int m_base = wm * WM, n_base = wn * WN;

    float acc[MT][NTL][4] = {};

    auto loadTiles = [&](int stage, int kt) {
        const int k0 = kt * BK;
        float* as = AsB + stage * ASZ;
        float* bs = BsB + stage * BSZ;
#pragma unroll
        for (int i = 0; i < 2; i++) {
            int id = tid * 2 + i;
            int m = id >> 2, c4 = (id & 3) * 4;
            cp16(&as[m * ASTRIDE + c4], A + (long)(m0 + m) * lda + k0 + c4);
        }
        if constexpr (BN == 128) {
#pragma unroll
            for (int i = 0; i < 2; i++) {
                int id = tid * 2 + i;
                int k = id >> 5, n4 = (id & 31) * 4;
                cp16(&bs[k * BSTRIDE + n4], Bg + (long)(k0 + k) * N + n0 + n4);
            }
        } else {  // BN == 64
            int k = tid >> 4, n4 = (tid & 15) * 4;
            cp16(&bs[k * BSTRIDE + n4], Bg + (long)(k0 + k) * N + n0 + n4);
        }
    };

    auto compute = [&](int stage) {
        const float* as = AsB + stage * ASZ;
        const float* bs = BsB + stage * BSZ;
#pragma unroll
        for (int ks = 0; ks < 2; ks++) {
            const int kk = ks * 8;
            uint32_t af[MT][4], bf[NTL][2];
#pragma unroll
            for (int mt = 0; mt < MT; mt++) {
                int rr = m_base + mt * 16 + g;
                af[mt][0] = __float_as_uint(as[rr * ASTRIDE + kk + tig]);
                af[mt][1] = __float_as_uint(as[(rr + 8) * ASTRIDE + kk + tig]);
                af[mt][2] = __float_as_uint(as[rr * ASTRIDE + kk + tig + 4]);
                af[mt][3] = __float_as_uint(as[(rr + 8) * ASTRIDE + kk + tig + 4]);
            }
#pragma unroll
            for (int nt = 0; nt < NTL; nt++) {
                int cc = n_base + nt * 8 + g;
                bf[nt][0] = __float_as_uint(bs[(kk + tig) * BSTRIDE + cc]);
                bf[nt][1] = __float_as_uint(bs[(kk + tig + 4) * BSTRIDE + cc]);
            }
#pragma unroll
            for (int mt = 0; mt < MT; mt++)
#pragma unroll
                for (int nt = 0; nt < NTL; nt++)
                    mma_tf32(acc[mt][nt], af[mt], bf[nt]);
        }
    };

    const int KT = K / BK;
#pragma unroll
    for (int s = 0; s < STAGES - 1; s++) { loadTiles(s, s); CP_COMMIT(); }

    for (int kt = 0; kt < KT; kt++) {
        asm volatile("cp.async.wait_group 2;");
        __syncthreads();
        const int pf = kt + STAGES - 1;
        if (pf < KT) loadTiles(pf & (STAGES - 1), pf);
        CP_COMMIT();
        compute(kt & (STAGES - 1));
    }

    // vectorized epilogue (pairs are adjacent columns)
#pragma unroll
    for (int mt = 0; mt < MT; mt++) {
        int r0 = m0 + m_base + mt * 16 + g;
#pragma unroll
        for (int nt = 0; nt < NTL; nt++) {
            int c0 = n0 + n_base + nt * 8 + 2 * tig;
            float v0 = acc[mt][nt][0], v1 = acc[mt][nt][1];
            float v2 = acc[mt][nt][2], v3 = acc[mt][nt][3];
            if constexpr (EPI == 0) {
                *(float2*)&Cw[(long)r0 * N + c0]       = make_float2(v0, v1);
                *(float2*)&Cw[(long)(r0 + 8) * N + c0] = make_float2(v2, v3);
            } else if constexpr (EPI == 1) {
                float2 bb = *(const float2*)&bias[c0];
                float w0 = to_tf32((v0 + bb.x) * scaleval);
                float w1 = to_tf32((v1 + bb.y) * scaleval);
                float w2 = to_tf32((v2 + bb.x) * scaleval);
                float w3 = to_tf32((v3 + bb.y) * scaleval);
                int bq = r0 >> 9, s = r0 & 511, hh = c0 >> 6, d = c0 & 63;
                long o0 = ((((long)bq * H_ + hh) * S_ + s) * DH_) + d;
                *(float2*)&Cw[o0]           = make_float2(w0, w1);
                *(float2*)&Cw[o0 + 8 * DH_] = make_float2(w2, w3);
            } else if constexpr (EPI == 3) {
                float2 bb = *(const float2*)&bias[c0];
                float x0 = v0 + bb.x, x1 = v1 + bb.y;
                float x2 = v2 + bb.x, x3 = v3 + bb.y;
                float w0 = to_tf32(0.5f * x0 * (1.0f + erff(x0 * 0.70710678118654752f)));
                float w1 = to_tf32(0.5f * x1 * (1.0f + erff(x1 * 0.70710678118654752f)));
                float w2 = to_tf32(0.5f * x2 * (1.0f + erff(x2 * 0.70710678118654752f)));
                float w3 = to_tf32(0.5f * x3 * (1.0f + erff(x3 * 0.70710678118654752f)));
                *(float2*)&Cw[(long)r0 * N + c0]       = make_float2(w0, w1);
                *(float2*)&Cw[(long)(r0 + 8) * N + c0] = make_float2(w2, w3);
            }
        }
    }
}

// ---- layernorm 768 with fused split-K reduce: x = p0 + p1 + bias + res ----
__global__ __launch_bounds__(256)
void layernorm768_red(const float* __restrict__ part, const float* __restrict__ bvec,
                      const float* __restrict__ res, const float* __restrict__ g,
                      const float* __restrict__ b, float* __restrict__ y,
                      float* __restrict__ y32)
{
    const long off = (long)blockIdx.x * D_;
    const float* p0 = part + off;
    const float* p1 = part + (long)MR_ * D_ + off;
    const float* rr = res + off;
    float* orow  = y   + off;
    float* orow2 = y32 + off;
    int tid = threadIdx.x;
    float a0 = p0[tid]       + p1[tid]       + bvec[tid]       + rr[tid];
    float a1 = p0[tid + 256] + p1[tid + 256] + bvec[tid + 256] + rr[tid + 256];
    float a2 = p0[tid + 512] + p1[tid + 512] + bvec[tid + 512] + rr[tid + 512];
    float s = a0 + a1 + a2;
    float q = a0 * a0 + a1 * a1 + a2 * a2;
    __shared__ float rs[8], rq[8];
#pragma unroll
    for (int o = 16; o; o >>= 1) {
        s += __shfl_xor_sync(0xffffffffu, s, o);
        q += __shfl_xor_sync(0xffffffffu, q, o);
    }
    if ((tid & 31) == 0) { rs[tid >> 5] = s; rq[tid >> 5] = q; }
    __syncthreads();
    s = (rs[0] + rs[1]) + (rs[2] + rs[3]) + (rs[4] + rs[5]) + (rs[6] + rs[7]);
    q = (rq[0] + rq[1]) + (rq[2] + rq[3]) + (rq[4] + rq[5]) + (rq[6] + rq[7]);
    float mean = s * (1.0f / D_);
    float var  = q * (1.0f / D_) - mean * mean;
    float r = rsqrtf(var + 1e-5f);
    float v0 = (a0 - mean) * r * g[tid]       + b[tid];
    float v1 = (a1 - mean) * r * g[tid + 256] + b[tid + 256];
    float v2 = (a2 - mean) * r * g[tid + 512] + b[tid + 512];
    orow[tid]        = v0;  orow[tid + 256]  = v1;  orow[tid + 512]  = v2;
    orow2[tid]       = to_tf32(v0);
    orow2[tid + 256] = to_tf32(v1);
    orow2[tid + 512] = to_tf32(v2);
}

// ---------------- host orchestration ----------------
extern "C" void kernel_launch(void* const* d_in, const int* in_sizes, int n_in,
                              void* d_out, int out_size)
{
    const float* hs    = (const float*)d_in[0];
    const float* mask  = (const float*)d_in[1];
    const float* rel   = (const float*)d_in[2];
    const float* rel2  = (const float*)d_in[3];
    const float* Wq    = (const float*)d_in[4];
    const float* bq    = (const float*)d_in[5];
    const float* Wk    = (const float*)d_in[6];
    const float* bk    = (const float*)d_in[7];
    const float* Wv    = (const float*)d_in[8];
    const float* bv    = (const float*)d_in[9];
    const float* Wo    = (const float*)d_in[10];
    const float* bo    = (const float*)d_in[11];
    const float* ln1g  = (const float*)d_in[12];
    const float* ln1b  = (const float*)d_in[13];
    const float* Wi    = (const float*)d_in[14];
    const float* bi    = (const float*)d_in[15];
    const float* Wo2   = (const float*)d_in[16];
    const float* bo2   = (const float*)d_in[17];
    const float* ln2g  = (const float*)d_in[18];
    const float* ln2b  = (const float*)d_in[19];
    float* out = (float*)d_out;

    float *p_q, *p_k, *p_v, *p_ctx, *p_h, *p_h32, *p_attn, *p_attn32, *p_ff, *p_part;
    float *p_wq, *p_wk, *p_wv, *p_wo, *p_wi, *p_wo2;
    __half* p_bias16;
    cudaGetSymbolAddress((void**)&p_bias16, g_bias16);
    cudaGetSymbolAddress((void**)&p_q,      g_q);
    cudaGetSymbolAddress((void**)&p_k,      g_k);
    cudaGetSymbolAddress((void**)&p_v,      g_v);
    cudaGetSymbolAddress((void**)&p_ctx,    g_ctx);
    cudaGetSymbolAddress((void**)&p_h,      g_h);
    cudaGetSymbolAddress((void**)&p_h32,    g_h32);
    cudaGetSymbolAddress((void**)&p_attn,   g_attn);
    cudaGetSymbolAddress((void**)&p_attn32, g_attn32);
    cudaGetSymbolAddress((void**)&p_ff,     g_ff);
    cudaGetSymbolAddress((void**)&p_part,   g_part);
    cudaGetSymbolAddress((void**)&p_wq,     g_wq32);
    cudaGetSymbolAddress((void**)&p_wk,     g_wk32);
    cudaGetSymbolAddress((void**)&p_wv,     g_wv32);
    cudaGetSymbolAddress((void**)&p_wo,     g_wo32);
    cudaGetSymbolAddress((void**)&p_wi,     g_wi32);
    cudaGetSymbolAddress((void**)&p_wo2,    g_wo232);

    cudaFuncSetAttribute(flash_attn,
                         cudaFuncAttributeMaxDynamicSharedMemorySize, FLASH_SMEM);
    const int SM_BN128 = (4 * (2560 + 16 * 136)) * 4;   // 75776
    const int SM_BN64  = (4 * (2560 + 16 * 72))  * 4;   // 59392
    cudaFuncSetAttribute(gemm_ca<128,2,4,1>,
                         cudaFuncAttributeMaxDynamicSharedMemorySize, SM_BN128);
    cudaFuncSetAttribute(gemm_ca<128,2,4,3>,
                         cudaFuncAttributeMaxDynamicSharedMemorySize, SM_BN128);
    cudaFuncSetAttribute(gemm_ca<64,4,2,0>,
                         cudaFuncAttributeMaxDynamicSharedMemorySize, SM_BN64);

    // ---- prep: weight tf32 conversion, bias (fp16), h/h32 ----
    const long nDD = (long)L_ * D_ * D_;
    const long nDF = (long)L_ * D_ * FF_;
    cvt_kernel<<<(unsigned)((nDD + 255) / 256), 256>>>(Wq,  p_wq,  nDD);
    cvt_kernel<<<(unsigned)((nDD + 255) / 256), 256>>>(Wk,  p_wk,  nDD);
    cvt_kernel<<<(unsigned)((nDD + 255) / 256), 256>>>(Wv,  p_wv,  nDD);
    cvt_kernel<<<(unsigned)((nDD + 255) / 256), 256>>>(Wo,  p_wo,  nDD);
    cvt_kernel<<<(unsigned)((nDF + 255) / 256), 256>>>(Wi,  p_wi,  nDF);
    cvt_kernel<<<(unsigned)((nDF + 255) / 256), 256>>>(Wo2, p_wo2, nDF);

    long nb = (long)BH_ * SS_;
    bias_kernel<<<(unsigned)((nb + 255) / 256), 256>>>(rel, rel2, mask);
    copy2_kernel<<<(MR_ * D_ + 255) / 256, 256>>>(hs, p_h, p_h32, (long)MR_ * D_);

    dim3 gQKV(3 * D_ / 128, MR_ / 128, 1);  // 288
    dim3 gFA (S_ / 64, BH_, 1);             // 384
    dim3 gWo (D_ / 64, MR_ / 128, 2);       // 384 (split-K=2, K=384 each)
    dim3 gF1 (FF_ / 128, MR_ / 128, 1);     // 384
    dim3 gF2 (D_ / 64, MR_ / 128, 2);       // 384 (split-K=2, K=1536 each)

    for (int l = 0; l < L_; l++) {
        const float* wq  = p_wq  + (long)l * D_ * D_;
        const float* wk  = p_wk  + (long)l * D_ * D_;
        const float* wv  = p_wv  + (long)l * D_ * D_;
        const float* wo  = p_wo  + (long)l * D_ * D_;
        const float* wi  = p_wi  + (long)l * D_ * FF_;
        const float* wo2 = p_wo2 + (long)l * FF_ * D_;

        // fused QKV projections (q folds 1/8), tf32 scatter to [B,H,S,DH]
        gemm_ca<128,2,4,1><<<gQKV, 256, SM_BN128>>>(
            p_h32, wq, p_q, bq + l * D_,
            wk, bk + l * D_, p_k,
            wv, bv + l * D_, p_v,
            MR_, D_, D_, D_, 0.125f);

        // fused attention -> ctx (tf32) [B,S,D]
        flash_attn<<<gFA, 128, FLASH_SMEM>>>(p_q, p_k, p_v, p_bias16, p_ctx);

        // ctx @ Wo (split-K=2, raw partials) -> LN1 fused reduce + bias + res
        gemm_ca<64,4,2,0><<<gWo, 256, SM_BN64>>>(
            p_ctx, wo, p_part, nullptr,
            nullptr, nullptr, nullptr, nullptr, nullptr, nullptr,
            MR_, D_, D_ / 2, D_, 1.0f);
        layernorm768_red<<<MR_, 256>>>(p_part, bo + l * D_, p_h,
                                       ln1g + l * D_, ln1b + l * D_,
                                       p_attn, p_attn32);

        // ff = tf32(gelu(attn @ Wi + bi))
        gemm_ca<128,2,4,3><<<gF1, 256, SM_BN128>>>(
            p_attn32, wi, p_ff, bi + l * FF_,
            nullptr, nullptr, nullptr, nullptr, nullptr, nullptr,
            MR_, FF_, D_, D_, 1.0f);

        // ff @ Wo2 (split-K=2, raw partials) -> LN2 fused reduce + bias + res
        gemm_ca<64,4,2,0><<<gF2, 256, SM_BN64>>>(
            p_ff, wo2, p_part, nullptr,
            nullptr, nullptr, nullptr, nullptr, nullptr, nullptr,
            MR_, D_, FF_ / 2, FF_, 1.0f);
        float* dst = (l == L_ - 1) ? out : p_h;
        layernorm768_red<<<MR_, 256>>>(p_part, bo2 + l * D_, p_attn,
                                       ln2g + l * D_, ln2b + l * D_,
                                       dst, p_h32);
    }
}

// round 13
// speedup vs baseline: 2.2858x; 1.6076x over previous
#include <cuda_runtime.h>
#include <cuda_fp16.h>
#include <math.h>
#include <stdint.h>

// ---------------- problem constants ----------------
#define L_   12
#define B_   4
#define S_   512
#define D_   768
#define H_   12
#define DH_  64
#define FF_  3072
#define BH_  (B_*H_)        // 48
#define MR_  (B_*S_)        // 2048
#define SS_  (S_*S_)        // 262144

// ---------------- scratch (device globals; allocation-free) ----------------
__device__ __half g_bias16[BH_*SS_];   // fp16 attention bias (layer-invariant)
__device__ float  g_q  [BH_*S_*DH_];   // tf32 (flash input)
__device__ float  g_k  [BH_*S_*DH_];
__device__ float  g_v  [BH_*S_*DH_];
__device__ __half g_ctx16[MR_*D_];     // flash output (fp16)
__device__ float  g_h   [MR_*D_];      // fp32 residual
__device__ __half g_h16 [MR_*D_];      // fp16 shadow
__device__ float  g_attn[MR_*D_];      // fp32 residual
__device__ __half g_attn16[MR_*D_];    // fp16 shadow
__device__ __half g_ff16[MR_*FF_];     // gelu out (fp16)
__device__ float  g_part[2*MR_*D_];    // split-K partials (fp32)
// pre-transposed fp16 weights [N][K]
__device__ __half g_wq16 [L_*D_*D_];
__device__ __half g_wk16 [L_*D_*D_];
__device__ __half g_wv16 [L_*D_*D_];
__device__ __half g_wo16 [L_*D_*D_];
__device__ __half g_wi16 [L_*D_*FF_];
__device__ __half g_wo216[L_*FF_*D_];

// ---------------- helpers ----------------
__device__ __forceinline__ float to_tf32(float x)
{
    float r;
    asm("cvt.rna.tf32.f32 %0, %1;" : "=f"(r) : "f"(x));
    return r;
}

__device__ __forceinline__ void mma_tf32(float* c, const uint32_t* a, const uint32_t* b)
{
    asm("mma.sync.aligned.m16n8k8.row.col.f32.tf32.tf32.f32 "
        "{%0,%1,%2,%3}, {%4,%5,%6,%7}, {%8,%9}, {%0,%1,%2,%3};"
        : "+f"(c[0]), "+f"(c[1]), "+f"(c[2]), "+f"(c[3])
        : "r"(a[0]), "r"(a[1]), "r"(a[2]), "r"(a[3]),
          "r"(b[0]), "r"(b[1]));
}

__device__ __forceinline__ void mma_f16(float* c, const uint32_t* a, const uint32_t* b)
{
    asm("mma.sync.aligned.m16n8k16.row.col.f32.f16.f16.f32 "
        "{%0,%1,%2,%3}, {%4,%5,%6,%7}, {%8,%9}, {%0,%1,%2,%3};"
        : "+f"(c[0]), "+f"(c[1]), "+f"(c[2]), "+f"(c[3])
        : "r"(a[0]), "r"(a[1]), "r"(a[2]), "r"(a[3]),
          "r"(b[0]), "r"(b[1]));
}

__device__ __forceinline__ void cp16(void* dst, const void* src)
{
    uint32_t d = (uint32_t)__cvta_generic_to_shared(dst);
    asm volatile("cp.async.cg.shared.global [%0], [%1], 16;" :: "r"(d), "l"(src));
}
#define CP_COMMIT() asm volatile("cp.async.commit_group;")

// ---------------- small kernels ----------------
__global__ void bias_kernel(const float* __restrict__ rel,
                            const float* __restrict__ rel2,
                            const float* __restrict__ mask)
{
    long i = (long)blockIdx.x * 256 + threadIdx.x;
    if (i >= (long)BH_ * SS_) return;
    int b = (int)(i / ((long)H_ * SS_));
    int kcol = (int)(i & (S_ - 1));
    g_bias16[i] = __float2half((rel[i] + rel2[i]) * 0.125f + mask[b * S_ + kcol]);
}

// transpose + fp16 convert: src [K][N] fp32 -> dst [N][K] fp16, per layer (z)
__global__ void transpose_cvt_kernel(const float* __restrict__ src,
                                     __half* __restrict__ dst, int K, int N)
{
    __shared__ float tile[32][33];
    const long lz = (long)blockIdx.z * K * N;
    const int k0 = blockIdx.y * 32, n0 = blockIdx.x * 32;
    const int tx = threadIdx.x, ty = threadIdx.y;   // 32 x 8
#pragma unroll
    for (int i = 0; i < 32; i += 8)
        tile[ty + i][tx] = src[lz + (long)(k0 + ty + i) * N + n0 + tx];
    __syncthreads();
#pragma unroll
    for (int i = 0; i < 32; i += 8)
        dst[lz + (long)(n0 + ty + i) * K + k0 + tx] = __float2half(tile[tx][ty + i]);
}

__global__ void copy2_kernel(const float* __restrict__ src, float* __restrict__ dst,
                             __half* __restrict__ dst16, long n)
{
    long i = (long)blockIdx.x * 256 + threadIdx.x;
    if (i < n) { float v = src[i]; dst[i] = v; dst16[i] = __float2half(v); }
}

// ---------------- fused flash attention (tf32, unchanged core) --------------
#define FK(s,n,c)  smf[(s)*4352 + (n)*68 + (c)]
#define FV(s,k,d)  smf[8704 + (s)*4608 + (k)*72 + (d)]
#define FQ(m,c)    smf[17920 + (m)*68 + (c)]
#define FP(c,r)    smf[17920 + (c)*72 + (r)]
#define FB_OFF     22528
#define FLASH_SMEM (27136 * 4)   // 108544 B -> 2 CTAs/SM

__global__ __launch_bounds__(128, 2)
void flash_attn(const float* __restrict__ Qg, const float* __restrict__ Kg,
                const float* __restrict__ Vg, const __half* __restrict__ biasg,
                __half* __restrict__ ctx)
{
    extern __shared__ float smf[];
    __half* bsm = (__half*)(smf + FB_OFF);

    const int z  = blockIdx.y;
    const int q0 = blockIdx.x * 64;
    const int tid  = threadIdx.x;
    const int warp = tid >> 5, lane = tid & 31;
    const int g = lane >> 2, tig = lane & 3;

    const float*  Qz = Qg + (long)z * S_ * DH_;
    const float*  Kz = Kg + (long)z * S_ * DH_;
    const float*  Vz = Vg + (long)z * S_ * DH_;
    const __half* bz = biasg + (long)z * SS_;

    auto loadKVB = [&](int s, int kt) {
#pragma unroll
        for (int i = 0; i < 8; i++) {
            int idx = i * 128 + tid;
            int n = idx >> 4, c4 = (idx & 15) << 2;
            cp16(&FK(s, n, c4), Kz + (long)(kt * 64 + n) * DH_ + c4);
            cp16(&FV(s, n, c4), Vz + (long)(kt * 64 + n) * DH_ + c4);
        }
#pragma unroll
        for (int i = 0; i < 4; i++) {
            int idx = i * 128 + tid;
            int rr = idx >> 3, h8 = (idx & 7) * 8;
            cp16(&bsm[s * 4608 + rr * 72 + h8],
                 bz + (long)(q0 + rr) * S_ + kt * 64 + h8);
        }
    };

#pragma unroll
    for (int i = 0; i < 8; i++) {
        int idx = i * 128 + tid;
        int m = idx >> 4, c4 = (idx & 15) << 2;
        cp16(&FQ(m, c4), Qz + (long)(q0 + m) * DH_ + c4);
    }
    loadKVB(0, 0);
    CP_COMMIT();
    asm volatile("cp.async.wait_group 0;");
    __syncthreads();

    const int r = warp * 16 + g;

    uint32_t afq[8][4];
#pragma unroll
    for (int ks = 0; ks < 8; ks++) {
        const int kk = ks * 8;
        afq[ks][0] = __float_as_uint(FQ(r,     kk + tig));
        afq[ks][1] = __float_as_uint(FQ(r + 8, kk + tig));
        afq[ks][2] = __float_as_uint(FQ(r,     kk + tig + 4));
        afq[ks][3] = __float_as_uint(FQ(r + 8, kk + tig + 4));
    }
    __syncthreads();

    float acc[8][4] = {};
    float mrow0 = -1e30f, mrow1 = -1e30f;
    float l0 = 0.0f, l1 = 0.0f;
    int buf = 0;

    for (int kt = 0; kt < 8; kt++) {
        if (kt < 7) loadKVB(buf ^ 1, kt + 1);
        CP_COMMIT();

        float s[8][4] = {};
#pragma unroll
        for (int ks = 0; ks < 8; ks++) {
            const int kk = ks * 8;
#pragma unroll
            for (int nt = 0; nt < 8; nt++) {
                uint32_t bf[2];
                bf[0] = __float_as_uint(FK(buf, nt * 8 + g, kk + tig));
                bf[1] = __float_as_uint(FK(buf, nt * 8 + g, kk + tig + 4));
                mma_tf32(s[nt], afq[ks], bf);
            }
        }

        const __half* bp = bsm + buf * 4608;
        float nm0 = mrow0, nm1 = mrow1;
#pragma unroll
        for (int nt = 0; nt < 8; nt++) {
            int c = nt * 8 + 2 * tig;
            float2 b0 = __half22float2(*(const half2*)(bp + r * 72 + c));
            float2 b1 = __half22float2(*(const half2*)(bp + (r + 8) * 72 + c));
            s[nt][0] += b0.x; s[nt][1] += b0.y;
            s[nt][2] += b1.x; s[nt][3] += b1.y;
            nm0 = fmaxf(nm0, fmaxf(s[nt][0], s[nt][1]));
            nm1 = fmaxf(nm1, fmaxf(s[nt][2], s[nt][3]));
        }
        nm0 = fmaxf(nm0, __shfl_xor_sync(0xffffffffu, nm0, 1));
        nm0 = fmaxf(nm0, __shfl_xor_sync(0xffffffffu, nm0, 2));
        nm1 = fmaxf(nm1, __shfl_xor_sync(0xffffffffu, nm1, 1));
        nm1 = fmaxf(nm1, __shfl_xor_sync(0xffffffffu, nm1, 2));

        float alpha0 = __expf(mrow0 - nm0);
        float alpha1 = __expf(mrow1 - nm1);
        mrow0 = nm0; mrow1 = nm1;

        float rs0 = 0.0f, rs1 = 0.0f;
#pragma unroll
        for (int nt = 0; nt < 8; nt++) {
            int c = nt * 8 + 2 * tig;
            float p0 = __expf(s[nt][0] - nm0);
            float p1 = __expf(s[nt][1] - nm0);
            float p2 = __expf(s[nt][2] - nm1);
            float p3 = __expf(s[nt][3] - nm1);
            rs0 += p0 + p1; rs1 += p2 + p3;
            FP(c,     r)     = to_tf32(p0);
            FP(c + 1, r)     = to_tf32(p1);
            FP(c,     r + 8) = to_tf32(p2);
            FP(c + 1, r + 8) = to_tf32(p3);
            acc[nt][0] *= alpha0; acc[nt][1] *= alpha0;
            acc[nt][2] *= alpha1; acc[nt][3] *= alpha1;
        }
        rs0 += __shfl_xor_sync(0xffffffffu, rs0, 1);
        rs0 += __shfl_xor_sync(0xffffffffu, rs0, 2);
        rs1 += __shfl_xor_sync(0xffffffffu, rs1, 1);
        rs1 += __shfl_xor_sync(0xffffffffu, rs1, 2);
        l0 = l0 * alpha0 + rs0;
        l1 = l1 * alpha1 + rs1;
        __syncwarp();

#pragma unroll
        for (int ks = 0; ks < 8; ks++) {
            const int kk = ks * 8;
            uint32_t af[4];
            af[0] = __float_as_uint(FP(kk + tig,     r));
            af[1] = __float_as_uint(FP(kk + tig,     r + 8));
            af[2] = __float_as_uint(FP(kk + tig + 4, r));
            af[3] = __float_as_uint(FP(kk + tig + 4, r + 8));
#pragma unroll
            for (int nt = 0; nt < 8; nt++) {
                uint32_t bf[2];
                bf[0] = __float_as_uint(FV(buf, kk + tig,     nt * 8 + g));
                bf[1] = __float_as_uint(FV(buf, kk + tig + 4, nt * 8 + g));
                mma_tf32(acc[nt], af, bf);
            }
        }

        if (kt < 7) {
            asm volatile("cp.async.wait_group 0;");
            __syncthreads();
        }
        buf ^= 1;
    }

    // epilogue: normalize, write fp16 ctx gathered to [B,S,D]
    const float inv0 = 1.0f / l0, inv1 = 1.0f / l1;
    const int b = z / H_, hh = z % H_;
    const int mg = q0 + r;
    __half* out0 = ctx + (long)(b * S_ + mg) * D_ + hh * DH_;
    __half* out1 = out0 + 8 * D_;
#pragma unroll
    for (int nt = 0; nt < 8; nt++) {
        int c = nt * 8 + 2 * tig;
        *(half2*)(out0 + c) = __floats2half2_rn(acc[nt][0] * inv0, acc[nt][1] * inv0);
        *(half2*)(out1 + c) = __floats2half2_rn(acc[nt][2] * inv1, acc[nt][3] * inv1);
    }
}

// ---------------- tensor-core FP16 GEMM (cp.async, 4-stage, split-K) --------
// C = A[M,K_total] @ W (A fp16 row-major [M][K]; W pre-transposed fp16 [N][K]).
// BK=32 halves, mma m16n8k16, fp32 accum. grid.z = split index.
// Smem half2 stride 20 (==4 mod 32) -> conflict-free frags for A and B^T.
// EPI: 0 = raw fp32 partial store to C + z*M*N
//      1 = fused QKV scatter (fp32 tf32 out for flash); picks {Wq,Wk,Wv}
//      3 = fp16 gelu(acc + bias[n]) to (half*)C
template<int BN, int WARPS_M, int WARPS_N, int EPI>
__global__ __launch_bounds__(256, 2)
void gemm_h(const __half* __restrict__ A, const __half* __restrict__ Bt,
            float* __restrict__ C, const float* __restrict__ bias,
            const __half* __restrict__ Bt2, const float* __restrict__ bias2,
            float* __restrict__ C2,
            const __half* __restrict__ Bt3, const float* __restrict__ bias3,
            float* __restrict__ C3,
            int M, int N, int K, int lda, int ldb, float scaleval)
{
    constexpr int BM = 128, BK = 32, STAGES = 4;
    constexpr int WM = BM / WARPS_M, WN = BN / WARPS_N;
    constexpr int MT = WM / 16, NTL = WN / 8;
    constexpr int STR2 = BK / 2 + 4;      // 20 half2 words, ==4 mod 32
    constexpr int ASZ = BM * STR2;        // 2560 words
    constexpr int BSZ = BN * STR2;

    extern __shared__ uint32_t sm2[];
    uint32_t* AsB = sm2;                  // [STAGES][BM][STR2]
    uint32_t* BsB = sm2 + STAGES * ASZ;   // [STAGES][BN][STR2]

    const int zz = blockIdx.z;
    A  += (long)zz * K;                   // split-K column offset (lda full)
    Bt += (long)zz * K;                   // W^T column offset   (ldb full)

    int n0;
    if constexpr (EPI == 1) {
        const int nb = N / BN;
        const int which = blockIdx.x / nb;
        n0 = (blockIdx.x % nb) * BN;
        if (which == 1) { Bt = Bt2; bias = bias2; C = C2; scaleval = 1.0f; }
        else if (which == 2) { Bt = Bt3; bias = bias3; C = C3; scaleval = 1.0f; }
    } else {
        n0 = blockIdx.x * BN;
    }
    float* Cw = C;
    if constexpr (EPI == 0) Cw = C + (long)zz * M * N;

    const int m0 = blockIdx.y * BM;
    const int tid  = threadIdx.x;
    const int warp = tid >> 5, lane = tid & 31;
    const int g = lane >> 2, tig = lane & 3;
    const int wm = warp % WARPS_M, wn = warp / WARPS_M;
    const int m_base = wm * WM, n_base = wn * WN;

    float acc[MT][NTL][4] = {};

    auto loadTiles = [&](int stage, int kt) {
        const int k0 = kt * BK;
        uint32_t* as = AsB + stage * ASZ;
        uint32_t* bs = BsB + stage * BSZ;
#pragma unroll
        for (int i = 0; i < 2; i++) {      // A: 128 rows x 4 x 16B
            int id = tid * 2 + i;
            int m = id >> 2, j = id & 3;
            cp16(&as[m * STR2 + 4 * j], A + (long)(m0 + m) * lda + k0 + 8 * j);
        }
        if constexpr (BN == 128) {
#pragma unroll
            for (int i = 0; i < 2; i++) {
                int id = tid * 2 + i;
                int n = id >> 2, j = id & 3;
                cp16(&bs[n * STR2 + 4 * j], Bt + (long)(n0 + n) * ldb + k0 + 8 * j);
            }
        } else {                           // BN == 64: 64 rows x 4 chunks
            int n = tid >> 2, j = tid & 3;
            cp16(&bs[n * STR2 + 4 * j], Bt + (long)(n0 + n) * ldb + k0 + 8 * j);
        }
    };

    auto compute = [&](int stage) {
        const uint32_t* as = AsB + stage * ASZ;
        const uint32_t* bs = BsB + stage * BSZ;
#pragma unroll
        for (int ks = 0; ks < 2; ks++) {   // two k16 steps per BK=32
            const int kk2 = ks * 8;        // half2 offset
            uint32_t af[MT][4], bf[NTL][2];
#pragma unroll
            for (int mt = 0; mt < MT; mt++) {
                int rr = m_base + mt * 16 + g;
                af[mt][0] = as[rr * STR2 + kk2 + tig];
                af[mt][1] = as[(rr + 8) * STR2 + kk2 + tig];
                af[mt][2] = as[rr * STR2 + kk2 + tig + 4];
                af[mt][3] = as[(rr + 8) * STR2 + kk2 + tig + 4];
            }
#pragma unroll
            for (int nt = 0; nt < NTL; nt++) {
                int cc = n_base + nt * 8 + g;
                bf[nt][0] = bs[cc * STR2 + kk2 + tig];
                bf[nt][1] = bs[cc * STR2 + kk2 + tig + 4];
            }
#pragma unroll
            for (int mt = 0; mt < MT; mt++)
#pragma unroll
                for (int nt = 0; nt < NTL; nt++)
                    mma_f16(acc[mt][nt], af[mt], bf[nt]);
        }
    };

    const int KT = K / BK;
#pragma unroll
    for (int s = 0; s < STAGES - 1; s++) { loadTiles(s, s); CP_COMMIT(); }

    for (int kt = 0; kt < KT; kt++) {
        asm volatile("cp.async.wait_group 2;");
        __syncthreads();
        const int pf = kt + STAGES - 1;
        if (pf < KT) loadTiles(pf & (STAGES - 1), pf);
        CP_COMMIT();
        compute(kt & (STAGES - 1));
    }

#pragma unroll
    for (int mt = 0; mt < MT; mt++) {
        int r0 = m0 + m_base + mt * 16 + g;
#pragma unroll
        for (int nt = 0; nt < NTL; nt++) {
            int c0 = n0 + n_base + nt * 8 + 2 * tig;
            float v0 = acc[mt][nt][0], v1 = acc[mt][nt][1];
            float v2 = acc[mt][nt][2], v3 = acc[mt][nt][3];
            if constexpr (EPI == 0) {
                *(float2*)&Cw[(long)r0 * N + c0]       = make_float2(v0, v1);
                *(float2*)&Cw[(long)(r0 + 8) * N + c0] = make_float2(v2, v3);
            } else if constexpr (EPI == 1) {
                float2 bb = *(const float2*)&bias[c0];
                float w0 = to_tf32((v0 + bb.x) * scaleval);
                float w1 = to_tf32((v1 + bb.y) * scaleval);
                float w2 = to_tf32((v2 + bb.x) * scaleval);
                float w3 = to_tf32((v3 + bb.y) * scaleval);
                int bq = r0 >> 9, s = r0 & 511, hh = c0 >> 6, d = c0 & 63;
                long o0 = ((((long)bq * H_ + hh) * S_ + s) * DH_) + d;
                *(float2*)&Cw[o0]           = make_float2(w0, w1);
                *(float2*)&Cw[o0 + 8 * DH_] = make_float2(w2, w3);
            } else if constexpr (EPI == 3) {
                __half* Ch = (__half*)C;
                float2 bb = *(const float2*)&bias[c0];
                float x0 = v0 + bb.x, x1 = v1 + bb.y;
                float x2 = v2 + bb.x, x3 = v3 + bb.y;
                float w0 = 0.5f * x0 * (1.0f + erff(x0 * 0.70710678118654752f));
                float w1 = 0.5f * x1 * (1.0f + erff(x1 * 0.70710678118654752f));
                float w2 = 0.5f * x2 * (1.0f + erff(x2 * 0.70710678118654752f));
                float w3 = 0.5f * x3 * (1.0f + erff(x3 * 0.70710678118654752f));
                *(half2*)&Ch[(long)r0 * N + c0]       = __floats2half2_rn(w0, w1);
                *(half2*)&Ch[(long)(r0 + 8) * N + c0] = __floats2half2_rn(w2, w3);
            }
        }
    }
}

// ---- layernorm 768 with fused split-K reduce: x = p0 + p1 + bias + res ----
__global__ __launch_bounds__(256)
void layernorm768_red(const float* __restrict__ part, const float* __restrict__ bvec,
                      const float* __restrict__ res, const float* __restrict__ g,
                      const float* __restrict__ b, float* __restrict__ y,
                      __half* __restrict__ y16)
{
    const long off = (long)blockIdx.x * D_;
    const float* p0 = part + off;
    const float* p1 = part + (long)MR_ * D_ + off;
    const float* rr = res + off;
    float*  orow  = y   + off;
    __half* orow2 = y16 + off;
    int tid = threadIdx.x;
    float a0 = p0[tid]       + p1[tid]       + bvec[tid]       + rr[tid];
    float a1 = p0[tid + 256] + p1[tid + 256] + bvec[tid + 256] + rr[tid + 256];
    float a2 = p0[tid + 512] + p1[tid + 512] + bvec[tid + 512] + rr[tid + 512];
    float s = a0 + a1 + a2;
    float q = a0 * a0 + a1 * a1 + a2 * a2;
    __shared__ float rs[8], rq[8];
#pragma unroll
    for (int o = 16; o; o >>= 1) {
        s += __shfl_xor_sync(0xffffffffu, s, o);
        q += __shfl_xor_sync(0xffffffffu, q, o);
    }
    if ((tid & 31) == 0) { rs[tid >> 5] = s; rq[tid >> 5] = q; }
    __syncthreads();
    s = (rs[0] + rs[1]) + (rs[2] + rs[3]) + (rs[4] + rs[5]) + (rs[6] + rs[7]);
    q = (rq[0] + rq[1]) + (rq[2] + rq[3]) + (rq[4] + rq[5]) + (rq[6] + rq[7]);
    float mean = s * (1.0f / D_);
    float var  = q * (1.0f / D_) - mean * mean;
    float r = rsqrtf(var + 1e-5f);
    float v0 = (a0 - mean) * r * g[tid]       + b[tid];
    float v1 = (a1 - mean) * r * g[tid + 256] + b[tid + 256];
    float v2 = (a2 - mean) * r * g[tid + 512] + b[tid + 512];
    orow[tid]        = v0;  orow[tid + 256]  = v1;  orow[tid + 512]  = v2;
    orow2[tid]       = __float2half(v0);
    orow2[tid + 256] = __float2half(v1);
    orow2[tid + 512] = __float2half(v2);
}

// ---------------- host orchestration ----------------
extern "C" void kernel_launch(void* const* d_in, const int* in_sizes, int n_in,
                              void* d_out, int out_size)
{
    const float* hs    = (const float*)d_in[0];
    const float* mask  = (const float*)d_in[1];
    const float* rel   = (const float*)d_in[2];
    const float* rel2  = (const float*)d_in[3];
    const float* Wq    = (const float*)d_in[4];
    const float* bq    = (const float*)d_in[5];
    const float* Wk    = (const float*)d_in[6];
    const float* bk    = (const float*)d_in[7];
    const float* Wv    = (const float*)d_in[8];
    const float* bv    = (const float*)d_in[9];
    const float* Wo    = (const float*)d_in[10];
    const float* bo    = (const float*)d_in[11];
    const float* ln1g  = (const float*)d_in[12];
    const float* ln1b  = (const float*)d_in[13];
    const float* Wi    = (const float*)d_in[14];
    const float* bi    = (const float*)d_in[15];
    const float* Wo2   = (const float*)d_in[16];
    const float* bo2   = (const float*)d_in[17];
    const float* ln2g  = (const float*)d_in[18];
    const float* ln2b  = (const float*)d_in[19];
    float* out = (float*)d_out;

    float *p_q, *p_k, *p_v, *p_h, *p_attn, *p_part;
    __half *p_bias16, *p_ctx16, *p_h16, *p_attn16, *p_ff16;
    __half *p_wq, *p_wk, *p_wv, *p_wo, *p_wi, *p_wo2;
    cudaGetSymbolAddress((void**)&p_bias16, g_bias16);
    cudaGetSymbolAddress((void**)&p_q,      g_q);
    cudaGetSymbolAddress((void**)&p_k,      g_k);
    cudaGetSymbolAddress((void**)&p_v,      g_v);
    cudaGetSymbolAddress((void**)&p_ctx16,  g_ctx16);
    cudaGetSymbolAddress((void**)&p_h,      g_h);
    cudaGetSymbolAddress((void**)&p_h16,    g_h16);
    cudaGetSymbolAddress((void**)&p_attn,   g_attn);
    cudaGetSymbolAddress((void**)&p_attn16, g_attn16);
    cudaGetSymbolAddress((void**)&p_ff16,   g_ff16);
    cudaGetSymbolAddress((void**)&p_part,   g_part);
    cudaGetSymbolAddress((void**)&p_wq,     g_wq16);
    cudaGetSymbolAddress((void**)&p_wk,     g_wk16);
    cudaGetSymbolAddress((void**)&p_wv,     g_wv16);
    cudaGetSymbolAddress((void**)&p_wo,     g_wo16);
    cudaGetSymbolAddress((void**)&p_wi,     g_wi16);
    cudaGetSymbolAddress((void**)&p_wo2,    g_wo216);

    cudaFuncSetAttribute(flash_attn,
                         cudaFuncAttributeMaxDynamicSharedMemorySize, FLASH_SMEM);
    const int SM_BN128 = 4 * (2560 + 128 * 20) * 4;   // 81920 B
    const int SM_BN64  = 4 * (2560 + 64 * 20) * 4;    // 61440 B
    cudaFuncSetAttribute(gemm_h<128,2,4,1>,
                         cudaFuncAttributeMaxDynamicSharedMemorySize, SM_BN128);
    cudaFuncSetAttribute(gemm_h<128,2,4,3>,
                         cudaFuncAttributeMaxDynamicSharedMemorySize, SM_BN128);
    cudaFuncSetAttribute(gemm_h<64,4,2,0>,
                         cudaFuncAttributeMaxDynamicSharedMemorySize, SM_BN64);

    // ---- prep: weight transpose->fp16, bias fp16, h/h16 ----
    dim3 tb(32, 8);
    dim3 gDD(D_ / 32, D_ / 32, L_);
    dim3 gWi(FF_ / 32, D_ / 32, L_);    // Wi: [768][3072] -> [3072][768]
    dim3 gWo2(D_ / 32, FF_ / 32, L_);   // Wo2: [3072][768] -> [768][3072]
    transpose_cvt_kernel<<<gDD, tb>>>(Wq,  p_wq,  D_, D_);
    transpose_cvt_kernel<<<gDD, tb>>>(Wk,  p_wk,  D_, D_);
    transpose_cvt_kernel<<<gDD, tb>>>(Wv,  p_wv,  D_, D_);
    transpose_cvt_kernel<<<gDD, tb>>>(Wo,  p_wo,  D_, D_);
    transpose_cvt_kernel<<<gWi, tb>>>(Wi,  p_wi,  D_, FF_);
    transpose_cvt_kernel<<<gWo2, tb>>>(Wo2, p_wo2, FF_, D_);

    long nb = (long)BH_ * SS_;
    bias_kernel<<<(unsigned)((nb + 255) / 256), 256>>>(rel, rel2, mask);
    copy2_kernel<<<(MR_ * D_ + 255) / 256, 256>>>(hs, p_h, p_h16, (long)MR_ * D_);

    dim3 gQKV(3 * D_ / 128, MR_ / 128, 1);  // 288
    dim3 gFA (S_ / 64, BH_, 1);             // 384
    dim3 gWoG(D_ / 64, MR_ / 128, 2);       // 384 (split-K=2, K=384 each)
    dim3 gF1 (FF_ / 128, MR_ / 128, 1);     // 384
    dim3 gF2 (D_ / 64, MR_ / 128, 2);       // 384 (split-K=2, K=1536 each)

    for (int l = 0; l < L_; l++) {
        const __half* wq  = p_wq  + (long)l * D_ * D_;
        const __half* wk  = p_wk  + (long)l * D_ * D_;
        const __half* wv  = p_wv  + (long)l * D_ * D_;
        const __half* wo  = p_wo  + (long)l * D_ * D_;
        const __half* wi  = p_wi  + (long)l * D_ * FF_;
        const __half* wo2 = p_wo2 + (long)l * FF_ * D_;

        // fused QKV projections (q folds 1/8), tf32 scatter to [B,H,S,DH]
        gemm_h<128,2,4,1><<<gQKV, 256, SM_BN128>>>(
            p_h16, wq, p_q, bq + l * D_,
            wk, bk + l * D_, p_k,
            wv, bv + l * D_, p_v,
            MR_, D_, D_, D_, D_, 0.125f);

        // fused attention -> ctx (fp16) [B,S,D]
        flash_attn<<<gFA, 128, FLASH_SMEM>>>(p_q, p_k, p_v, p_bias16, p_ctx16);

        // ctx @ Wo (split-K=2, raw partials) -> LN1 fused reduce + bias + res
        gemm_h<64,4,2,0><<<gWoG, 256, SM_BN64>>>(
            p_ctx16, wo, p_part, nullptr,
            nullptr, nullptr, nullptr, nullptr, nullptr, nullptr,
            MR_, D_, D_ / 2, D_, D_, 1.0f);
        layernorm768_red<<<MR_, 256>>>(p_part, bo + l * D_, p_h,
                                       ln1g + l * D_, ln1b + l * D_,
                                       p_attn, p_attn16);

        // ff16 = fp16(gelu(attn @ Wi + bi))
        gemm_h<128,2,4,3><<<gF1, 256, SM_BN128>>>(
            p_attn16, wi, (float*)p_ff16, bi + l * FF_,
            nullptr, nullptr, nullptr, nullptr, nullptr, nullptr,
            MR_, FF_, D_, D_, D_, 1.0f);

        // ff @ Wo2 (split-K=2, raw partials) -> LN2 fused reduce + bias + res
        gemm_h<64,4,2,0><<<gF2, 256, SM_BN64>>>(
            p_ff16, wo2, p_part, nullptr,
            nullptr, nullptr, nullptr, nullptr, nullptr, nullptr,
            MR_, D_, FF_ / 2, FF_, FF_, 1.0f);
        float* dst = (l == L_ - 1) ? out : p_h;
        layernorm768_red<<<MR_, 256>>>(p_part, bo2 + l * D_, p_attn,
                                       ln2g + l * D_, ln2b + l * D_,
                                       dst, p_h16);
    }
}

// round 14
// speedup vs baseline: 2.4502x; 1.0719x over previous
#include <cuda_runtime.h>
#include <cuda_fp16.h>
#include <math.h>
#include <stdint.h>

// ---------------- problem constants ----------------
#define L_   12
#define B_   4
#define S_   512
#define D_   768
#define H_   12
#define DH_  64
#define FF_  3072
#define BH_  (B_*H_)        // 48
#define MR_  (B_*S_)        // 2048
#define SS_  (S_*S_)        // 262144

// ---------------- scratch (device globals; allocation-free) ----------------
__device__ __half g_bias16[BH_*SS_];   // fp16 attention bias (layer-invariant)
__device__ __half g_q16 [BH_*S_*DH_];  // fp16 (flash input)
__device__ __half g_k16 [BH_*S_*DH_];
__device__ __half g_v16 [BH_*S_*DH_];
__device__ __half g_ctx16[MR_*D_];     // flash output (fp16)
__device__ float  g_h   [MR_*D_];      // fp32 residual
__device__ __half g_h16 [MR_*D_];      // fp16 shadow
__device__ float  g_attn[MR_*D_];      // fp32 residual
__device__ __half g_attn16[MR_*D_];    // fp16 shadow
__device__ __half g_ff16[MR_*FF_];     // gelu out (fp16)
__device__ float  g_part[2*MR_*D_];    // split-K partials (fp32)
// pre-transposed fp16 weights [N][K]
__device__ __half g_wq16 [L_*D_*D_];
__device__ __half g_wk16 [L_*D_*D_];
__device__ __half g_wv16 [L_*D_*D_];
__device__ __half g_wo16 [L_*D_*D_];
__device__ __half g_wi16 [L_*D_*FF_];
__device__ __half g_wo216[L_*FF_*D_];

// ---------------- helpers ----------------
__device__ __forceinline__ void mma_f16(float* c, const uint32_t* a, const uint32_t* b)
{
    asm("mma.sync.aligned.m16n8k16.row.col.f32.f16.f16.f32 "
        "{%0,%1,%2,%3}, {%4,%5,%6,%7}, {%8,%9}, {%0,%1,%2,%3};"
        : "+f"(c[0]), "+f"(c[1]), "+f"(c[2]), "+f"(c[3])
        : "r"(a[0]), "r"(a[1]), "r"(a[2]), "r"(a[3]),
          "r"(b[0]), "r"(b[1]));
}

__device__ __forceinline__ void ldsm4t(uint32_t& d0, uint32_t& d1,
                                       uint32_t& d2, uint32_t& d3, uint32_t addr)
{
    asm volatile("ldmatrix.sync.aligned.m8n8.x4.trans.shared.b16 "
                 "{%0,%1,%2,%3}, [%4];"
                 : "=r"(d0), "=r"(d1), "=r"(d2), "=r"(d3) : "r"(addr));
}

__device__ __forceinline__ void cp16(void* dst, const void* src)
{
    uint32_t d = (uint32_t)__cvta_generic_to_shared(dst);
    asm volatile("cp.async.cg.shared.global [%0], [%1], 16;" :: "r"(d), "l"(src));
}
#define CP_COMMIT() asm volatile("cp.async.commit_group;")

// ---------------- small kernels ----------------
__global__ void bias_kernel(const float* __restrict__ rel,
                            const float* __restrict__ rel2,
                            const float* __restrict__ mask)
{
    long i = (long)blockIdx.x * 256 + threadIdx.x;
    if (i >= (long)BH_ * SS_) return;
    int b = (int)(i / ((long)H_ * SS_));
    int kcol = (int)(i & (S_ - 1));
    g_bias16[i] = __float2half((rel[i] + rel2[i]) * 0.125f + mask[b * S_ + kcol]);
}

// transpose + fp16 convert: src [K][N] fp32 -> dst [N][K] fp16, per layer (z)
__global__ void transpose_cvt_kernel(const float* __restrict__ src,
                                     __half* __restrict__ dst, int K, int N)
{
    __shared__ float tile[32][33];
    const long lz = (long)blockIdx.z * K * N;
    const int k0 = blockIdx.y * 32, n0 = blockIdx.x * 32;
    const int tx = threadIdx.x, ty = threadIdx.y;   // 32 x 8
#pragma unroll
    for (int i = 0; i < 32; i += 8)
        tile[ty + i][tx] = src[lz + (long)(k0 + ty + i) * N + n0 + tx];
    __syncthreads();
#pragma unroll
    for (int i = 0; i < 32; i += 8)
        dst[lz + (long)(n0 + ty + i) * K + k0 + tx] = __float2half(tile[tx][ty + i]);
}

__global__ void copy2_kernel(const float* __restrict__ src, float* __restrict__ dst,
                             __half* __restrict__ dst16, long n)
{
    long i = (long)blockIdx.x * 256 + threadIdx.x;
    if (i < n) { float v = src[i]; dst[i] = v; dst16[i] = __float2half(v); }
}

// ---------------- fused flash attention (v4: full fp16 tensor path) ---------
// Grid (S/64, BH). 128 threads / 4 warps, warp owns 16 q-rows.
// q/k/v fp16 in gmem. Phase A: Q[m][k] x K[n][k] via m16n8k16 (frags from
// half2 smem, stride 36 words == 4 mod 32 -> conflict-free). Phase C:
// P[r][k] half2 x V via ldmatrix.x4.trans (V smem rows start 4 banks apart
// -> conflict-free). Q pane reused for P. 63KB smem -> 3 CTAs/SM, single wave.
// word offsets: K[2] @0 (2304 ea), V[2] @4608, Q/P @9216, bias[2] @11520
#define FLASH_SMEM (16128 * 4)   // 64512 B

__global__ __launch_bounds__(128, 3)
void flash_attn(const __half* __restrict__ Qg, const __half* __restrict__ Kg,
                const __half* __restrict__ Vg, const __half* __restrict__ biasg,
                __half* __restrict__ ctx)
{
    extern __shared__ uint32_t smw[];

    const int z  = blockIdx.y;
    const int q0 = blockIdx.x * 64;
    const int tid  = threadIdx.x;
    const int warp = tid >> 5, lane = tid & 31;
    const int g = lane >> 2, tig = lane & 3;

    const __half* Qz = Qg + (long)z * S_ * DH_;
    const __half* Kz = Kg + (long)z * S_ * DH_;
    const __half* Vz = Vg + (long)z * S_ * DH_;
    const __half* bz = biasg + (long)z * SS_;

    auto loadKVB = [&](int s, int kt) {
        __half* Kh = (__half*)(smw + s * 2304);
        __half* Vh = (__half*)(smw + 4608 + s * 2304);
        __half* Bh = (__half*)(smw + 11520 + s * 2304);
#pragma unroll
        for (int i = 0; i < 4; i++) {
            int idx = i * 128 + tid;
            int n = idx >> 3, c8 = (idx & 7) << 3;
            cp16(Kh + n * 72 + c8, Kz + (long)(kt * 64 + n) * DH_ + c8);
            cp16(Vh + n * 72 + c8, Vz + (long)(kt * 64 + n) * DH_ + c8);
            cp16(Bh + n * 72 + c8, bz + (long)(q0 + n) * S_ + kt * 64 + c8);
        }
    };

    // prologue: Q tile + K0/V0/B0
    {
        __half* Qh = (__half*)(smw + 9216);
#pragma unroll
        for (int i = 0; i < 4; i++) {
            int idx = i * 128 + tid;
            int m = idx >> 3, c8 = (idx & 7) << 3;
            cp16(Qh + m * 72 + c8, Qz + (long)(q0 + m) * DH_ + c8);
        }
    }
    loadKVB(0, 0);
    CP_COMMIT();
    asm volatile("cp.async.wait_group 0;");
    __syncthreads();

    const int r = warp * 16 + g;

    // hoist Q fragments (kt-invariant): 4 k16 steps
    uint32_t afq[4][4];
    {
        const uint32_t* Q2 = smw + 9216;
#pragma unroll
        for (int ks = 0; ks < 4; ks++) {
            afq[ks][0] = Q2[r * 36 + ks * 8 + tig];
            afq[ks][1] = Q2[(r + 8) * 36 + ks * 8 + tig];
            afq[ks][2] = Q2[r * 36 + ks * 8 + tig + 4];
            afq[ks][3] = Q2[(r + 8) * 36 + ks * 8 + tig + 4];
        }
    }
    __syncthreads();   // all Q reads done before P overwrites the pane

    float acc[8][4] = {};
    float mrow0 = -1e30f, mrow1 = -1e30f;
    float l0 = 0.0f, l1 = 0.0f;
    int buf = 0;

    uint32_t* P2 = smw + 9216;
    const int lm = lane & 15, hi8 = (lane >> 4) << 3;

    for (int kt = 0; kt < 8; kt++) {
        if (kt < 7) loadKVB(buf ^ 1, kt + 1);
        CP_COMMIT();

        // phase A: S = Q.K^T (q pre-scaled by 1/8)
        const uint32_t* K2 = smw + buf * 2304;
        float s[8][4] = {};
#pragma unroll
        for (int ks = 0; ks < 4; ks++) {
            const int kk2 = ks * 8;
#pragma unroll
            for (int nt = 0; nt < 8; nt++) {
                uint32_t bf[2];
                bf[0] = K2[(nt * 8 + g) * 36 + kk2 + tig];
                bf[1] = K2[(nt * 8 + g) * 36 + kk2 + tig + 4];
                mma_f16(s[nt], afq[ks], bf);
            }
        }

        // bias (fp16, smem-prefetched) + online softmax
        const __half* bp = (const __half*)(smw + 11520 + buf * 2304);
        float nm0 = mrow0, nm1 = mrow1;
#pragma unroll
        for (int nt = 0; nt < 8; nt++) {
            int c = nt * 8 + 2 * tig;
            float2 b0 = __half22float2(*(const half2*)(bp + r * 72 + c));
            float2 b1 = __half22float2(*(const half2*)(bp + (r + 8) * 72 + c));
            s[nt][0] += b0.x; s[nt][1] += b0.y;
            s[nt][2] += b1.x; s[nt][3] += b1.y;
            nm0 = fmaxf(nm0, fmaxf(s[nt][0], s[nt][1]));
            nm1 = fmaxf(nm1, fmaxf(s[nt][2], s[nt][3]));
        }
        nm0 = fmaxf(nm0, __shfl_xor_sync(0xffffffffu, nm0, 1));
        nm0 = fmaxf(nm0, __shfl_xor_sync(0xffffffffu, nm0, 2));
        nm1 = fmaxf(nm1, __shfl_xor_sync(0xffffffffu, nm1, 1));
        nm1 = fmaxf(nm1, __shfl_xor_sync(0xffffffffu, nm1, 2));

        float alpha0 = __expf(mrow0 - nm0);
        float alpha1 = __expf(mrow1 - nm1);
        mrow0 = nm0; mrow1 = nm1;

        float rs0 = 0.0f, rs1 = 0.0f;
#pragma unroll
        for (int nt = 0; nt < 8; nt++) {
            float p0 = __expf(s[nt][0] - nm0);
            float p1 = __expf(s[nt][1] - nm0);
            float p2 = __expf(s[nt][2] - nm1);
            float p3 = __expf(s[nt][3] - nm1);
            rs0 += p0 + p1; rs1 += p2 + p3;
            half2 h01 = __floats2half2_rn(p0, p1);
            half2 h23 = __floats2half2_rn(p2, p3);
            P2[r * 36 + nt * 4 + tig]       = *(uint32_t*)&h01;
            P2[(r + 8) * 36 + nt * 4 + tig] = *(uint32_t*)&h23;
            acc[nt][0] *= alpha0; acc[nt][1] *= alpha0;
            acc[nt][2] *= alpha1; acc[nt][3] *= alpha1;
        }
        rs0 += __shfl_xor_sync(0xffffffffu, rs0, 1);
        rs0 += __shfl_xor_sync(0xffffffffu, rs0, 2);
        rs1 += __shfl_xor_sync(0xffffffffu, rs1, 1);
        rs1 += __shfl_xor_sync(0xffffffffu, rs1, 2);
        l0 = l0 * alpha0 + rs0;
        l1 = l1 * alpha1 + rs1;
        __syncwarp();

        // phase C: ctx += P.V (V frags via ldmatrix.x4.trans)
        const uint32_t vsh =
            (uint32_t)__cvta_generic_to_shared(smw + 4608 + buf * 2304);
#pragma unroll
        for (int ks = 0; ks < 4; ks++) {
            const int kk = ks * 16;
            uint32_t af[4];
            af[0] = P2[r * 36 + ks * 8 + tig];
            af[1] = P2[(r + 8) * 36 + ks * 8 + tig];
            af[2] = P2[r * 36 + ks * 8 + tig + 4];
            af[3] = P2[(r + 8) * 36 + ks * 8 + tig + 4];
#pragma unroll
            for (int nt2 = 0; nt2 < 4; nt2++) {
                uint32_t b0, b1, b2, b3;
                uint32_t addr = vsh +
                    (((kk + lm) * 72 + nt2 * 16 + hi8) << 1);
                ldsm4t(b0, b1, b2, b3, addr);
                uint32_t bfA[2] = {b0, b1}, bfB[2] = {b2, b3};
                mma_f16(acc[nt2 * 2],     af, bfA);
                mma_f16(acc[nt2 * 2 + 1], af, bfB);
            }
        }

        if (kt < 7) {
            asm volatile("cp.async.wait_group 0;");
            __syncthreads();
        }
        buf ^= 1;
    }

    // epilogue: normalize, write fp16 ctx gathered to [B,S,D]
    const float inv0 = 1.0f / l0, inv1 = 1.0f / l1;
    const int b = z / H_, hh = z % H_;
    const int mg = q0 + r;
    __half* out0 = ctx + (long)(b * S_ + mg) * D_ + hh * DH_;
    __half* out1 = out0 + 8 * D_;
#pragma unroll
    for (int nt = 0; nt < 8; nt++) {
        int c = nt * 8 + 2 * tig;
        *(half2*)(out0 + c) = __floats2half2_rn(acc[nt][0] * inv0, acc[nt][1] * inv0);
        *(half2*)(out1 + c) = __floats2half2_rn(acc[nt][2] * inv1, acc[nt][3] * inv1);
    }
}

// ---------------- tensor-core FP16 GEMM (cp.async, 4-stage, split-K) --------
// C = A[M,K_total] @ W (A fp16 row-major [M][K]; W pre-transposed fp16 [N][K]).
// BK=32 halves, mma m16n8k16, fp32 accum. grid.z = split index.
// EPI: 0 = raw fp32 partial store to C + z*M*N
//      1 = fused QKV scatter, fp16 out; picks {Wq,Wk,Wv} by n-block
//      3 = fp16 gelu(acc + bias[n]) to (half*)C
template<int BN, int WARPS_M, int WARPS_N, int EPI>
__global__ __launch_bounds__(256, 2)
void gemm_h(const __half* __restrict__ A, const __half* __restrict__ Bt,
            float* __restrict__ C, const float* __restrict__ bias,
            const __half* __restrict__ Bt2, const float* __restrict__ bias2,
            float* __restrict__ C2,
            const __half* __restrict__ Bt3, const float* __restrict__ bias3,
            float* __restrict__ C3,
            int M, int N, int K, int lda, int ldb, float scaleval)
{
    constexpr int BM = 128, BK = 32, STAGES = 4;
    constexpr int WM = BM / WARPS_M, WN = BN / WARPS_N;
    constexpr int MT = WM / 16, NTL = WN / 8;
    constexpr int STR2 = BK / 2 + 4;      // 20 half2 words, ==4 mod 32
    constexpr int ASZ = BM * STR2;
    constexpr int BSZ = BN * STR2;

    extern __shared__ uint32_t sm2[];
    uint32_t* AsB = sm2;
    uint32_t* BsB = sm2 + STAGES * ASZ;

    const int zz = blockIdx.z;
    A  += (long)zz * K;
    Bt += (long)zz * K;

    int n0;
    if constexpr (EPI == 1) {
        const int nb = N / BN;
        const int which = blockIdx.x / nb;
        n0 = (blockIdx.x % nb) * BN;
        if (which == 1) { Bt = Bt2; bias = bias2; C = C2; scaleval = 1.0f; }
        else if (which == 2) { Bt = Bt3; bias = bias3; C = C3; scaleval = 1.0f; }
    } else {
        n0 = blockIdx.x * BN;
    }
    float* Cw = C;
    if constexpr (EPI == 0) Cw = C + (long)zz * M * N;

    const int m0 = blockIdx.y * BM;
    const int tid  = threadIdx.x;
    const int warp = tid >> 5, lane = tid & 31;
    const int g = lane >> 2, tig = lane & 3;
    const int wm = warp % WARPS_M, wn = warp / WARPS_M;
    const int m_base = wm * WM, n_base = wn * WN;

    float acc[MT][NTL][4] = {};

    auto loadTiles = [&](int stage, int kt) {
        const int k0 = kt * BK;
        uint32_t* as = AsB + stage * ASZ;
        uint32_t* bs = BsB + stage * BSZ;
#pragma unroll
        for (int i = 0; i < 2; i++) {
            int id = tid * 2 + i;
            int m = id >> 2, j = id & 3;
            cp16(&as[m * STR2 + 4 * j], A + (long)(m0 + m) * lda + k0 + 8 * j);
        }
        if constexpr (BN == 128) {
#pragma unroll
            for (int i = 0; i < 2; i++) {
                int id = tid * 2 + i;
                int n = id >> 2, j = id & 3;
                cp16(&bs[n * STR2 + 4 * j], Bt + (long)(n0 + n) * ldb + k0 + 8 * j);
            }
        } else {
            int n = tid >> 2, j = tid & 3;
            cp16(&bs[n * STR2 + 4 * j], Bt + (long)(n0 + n) * ldb + k0 + 8 * j);
        }
    };

    auto compute = [&](int stage) {
        const uint32_t* as = AsB + stage * ASZ;
        const uint32_t* bs = BsB + stage * BSZ;
#pragma unroll
        for (int ks = 0; ks < 2; ks++) {
            const int kk2 = ks * 8;
            uint32_t af[MT][4], bf[NTL][2];
#pragma unroll
            for (int mt = 0; mt < MT; mt++) {
                int rr = m_base + mt * 16 + g;
                af[mt][0] = as[rr * STR2 + kk2 + tig];
                af[mt][1] = as[(rr + 8) * STR2 + kk2 + tig];
                af[mt][2] = as[rr * STR2 + kk2 + tig + 4];
                af[mt][3] = as[(rr + 8) * STR2 + kk2 + tig + 4];
            }
#pragma unroll
            for (int nt = 0; nt < NTL; nt++) {
                int cc = n_base + nt * 8 + g;
                bf[nt][0] = bs[cc * STR2 + kk2 + tig];
                bf[nt][1] = bs[cc * STR2 + kk2 + tig + 4];
            }
#pragma unroll
            for (int mt = 0; mt < MT; mt++)
#pragma unroll
                for (int nt = 0; nt < NTL; nt++)
                    mma_f16(acc[mt][nt], af[mt], bf[nt]);
        }
    };

    const int KT = K / BK;
#pragma unroll
    for (int s = 0; s < STAGES - 1; s++) { loadTiles(s, s); CP_COMMIT(); }

    for (int kt = 0; kt < KT; kt++) {
        asm volatile("cp.async.wait_group 2;");
        __syncthreads();
        const int pf = kt + STAGES - 1;
        if (pf < KT) loadTiles(pf & (STAGES - 1), pf);
        CP_COMMIT();
        compute(kt & (STAGES - 1));
    }

#pragma unroll
    for (int mt = 0; mt < MT; mt++) {
        int r0 = m0 + m_base + mt * 16 + g;
#pragma unroll
        for (int nt = 0; nt < NTL; nt++) {
            int c0 = n0 + n_base + nt * 8 + 2 * tig;
            float v0 = acc[mt][nt][0], v1 = acc[mt][nt][1];
            float v2 = acc[mt][nt][2], v3 = acc[mt][nt][3];
            if constexpr (EPI == 0) {
                *(float2*)&Cw[(long)r0 * N + c0]       = make_float2(v0, v1);
                *(float2*)&Cw[(long)(r0 + 8) * N + c0] = make_float2(v2, v3);
            } else if constexpr (EPI == 1) {
                __half* Ch = (__half*)C;
                float2 bb = *(const float2*)&bias[c0];
                half2 w01 = __floats2half2_rn((v0 + bb.x) * scaleval,
                                              (v1 + bb.y) * scaleval);
                half2 w23 = __floats2half2_rn((v2 + bb.x) * scaleval,
                                              (v3 + bb.y) * scaleval);
                int bq = r0 >> 9, s = r0 & 511, hh = c0 >> 6, d = c0 & 63;
                long o0 = ((((long)bq * H_ + hh) * S_ + s) * DH_) + d;
                *(half2*)&Ch[o0]           = w01;
                *(half2*)&Ch[o0 + 8 * DH_] = w23;
            } else if constexpr (EPI == 3) {
                __half* Ch = (__half*)C;
                float2 bb = *(const float2*)&bias[c0];
                float x0 = v0 + bb.x, x1 = v1 + bb.y;
                float x2 = v2 + bb.x, x3 = v3 + bb.y;
                float w0 = 0.5f * x0 * (1.0f + erff(x0 * 0.70710678118654752f));
                float w1 = 0.5f * x1 * (1.0f + erff(x1 * 0.70710678118654752f));
                float w2 = 0.5f * x2 * (1.0f + erff(x2 * 0.70710678118654752f));
                float w3 = 0.5f * x3 * (1.0f + erff(x3 * 0.70710678118654752f));
                *(half2*)&Ch[(long)r0 * N + c0]       = __floats2half2_rn(w0, w1);
                *(half2*)&Ch[(long)(r0 + 8) * N + c0] = __floats2half2_rn(w2, w3);
            }
        }
    }
}

// ---- layernorm 768 with fused split-K reduce: x = p0 + p1 + bias + res ----
__global__ __launch_bounds__(256)
void layernorm768_red(const float* __restrict__ part, const float* __restrict__ bvec,
                      const float* __restrict__ res, const float* __restrict__ g,
                      const float* __restrict__ b, float* __restrict__ y,
                      __half* __restrict__ y16)
{
    const long off = (long)blockIdx.x * D_;
    const float* p0 = part + off;
    const float* p1 = part + (long)MR_ * D_ + off;
    const float* rr = res + off;
    float*  orow  = y   + off;
    __half* orow2 = y16 + off;
    int tid = threadIdx.x;
    float a0 = p0[tid]       + p1[tid]       + bvec[tid]       + rr[tid];
    float a1 = p0[tid + 256] + p1[tid + 256] + bvec[tid + 256] + rr[tid + 256];
    float a2 = p0[tid + 512] + p1[tid + 512] + bvec[tid + 512] + rr[tid + 512];
    float s = a0 + a1 + a2;
    float q = a0 * a0 + a1 * a1 + a2 * a2;
    __shared__ float rs[8], rq[8];
#pragma unroll
    for (int o = 16; o; o >>= 1) {
        s += __shfl_xor_sync(0xffffffffu, s, o);
        q += __shfl_xor_sync(0xffffffffu, q, o);
    }
    if ((tid & 31) == 0) { rs[tid >> 5] = s; rq[tid >> 5] = q; }
    __syncthreads();
    s = (rs[0] + rs[1]) + (rs[2] + rs[3]) + (rs[4] + rs[5]) + (rs[6] + rs[7]);
    q = (rq[0] + rq[1]) + (rq[2] + rq[3]) + (rq[4] + rq[5]) + (rq[6] + rq[7]);
    float mean = s * (1.0f / D_);
    float var  = q * (1.0f / D_) - mean * mean;
    float r = rsqrtf(var + 1e-5f);
    float v0 = (a0 - mean) * r * g[tid]       + b[tid];
    float v1 = (a1 - mean) * r * g[tid + 256] + b[tid + 256];
    float v2 = (a2 - mean) * r * g[tid + 512] + b[tid + 512];
    orow[tid]        = v0;  orow[tid + 256]  = v1;  orow[tid + 512]  = v2;
    orow2[tid]       = __float2half(v0);
    orow2[tid + 256] = __float2half(v1);
    orow2[tid + 512] = __float2half(v2);
}

// ---------------- host orchestration ----------------
extern "C" void kernel_launch(void* const* d_in, const int* in_sizes, int n_in,
                              void* d_out, int out_size)
{
    const float* hs    = (const float*)d_in[0];
    const float* mask  = (const float*)d_in[1];
    const float* rel   = (const float*)d_in[2];
    const float* rel2  = (const float*)d_in[3];
    const float* Wq    = (const float*)d_in[4];
    const float* bq    = (const float*)d_in[5];
    const float* Wk    = (const float*)d_in[6];
    const float* bk    = (const float*)d_in[7];
    const float* Wv    = (const float*)d_in[8];
    const float* bv    = (const float*)d_in[9];
    const float* Wo    = (const float*)d_in[10];
    const float* bo    = (const float*)d_in[11];
    const float* ln1g  = (const float*)d_in[12];
    const float* ln1b  = (const float*)d_in[13];
    const float* Wi    = (const float*)d_in[14];
    const float* bi    = (const float*)d_in[15];
    const float* Wo2   = (const float*)d_in[16];
    const float* bo2   = (const float*)d_in[17];
    const float* ln2g  = (const float*)d_in[18];
    const float* ln2b  = (const float*)d_in[19];
    float* out = (float*)d_out;

    float *p_h, *p_attn, *p_part;
    __half *p_bias16, *p_q16, *p_k16, *p_v16, *p_ctx16, *p_h16, *p_attn16, *p_ff16;
    __half *p_wq, *p_wk, *p_wv, *p_wo, *p_wi, *p_wo2;
    cudaGetSymbolAddress((void**)&p_bias16, g_bias16);
    cudaGetSymbolAddress((void**)&p_q16,    g_q16);
    cudaGetSymbolAddress((void**)&p_k16,    g_k16);
    cudaGetSymbolAddress((void**)&p_v16,    g_v16);
    cudaGetSymbolAddress((void**)&p_ctx16,  g_ctx16);
    cudaGetSymbolAddress((void**)&p_h,      g_h);
    cudaGetSymbolAddress((void**)&p_h16,    g_h16);
    cudaGetSymbolAddress((void**)&p_attn,   g_attn);
    cudaGetSymbolAddress((void**)&p_attn16, g_attn16);
    cudaGetSymbolAddress((void**)&p_ff16,   g_ff16);
    cudaGetSymbolAddress((void**)&p_part,   g_part);
    cudaGetSymbolAddress((void**)&p_wq,     g_wq16);
    cudaGetSymbolAddress((void**)&p_wk,     g_wk16);
    cudaGetSymbolAddress((void**)&p_wv,     g_wv16);
    cudaGetSymbolAddress((void**)&p_wo,     g_wo16);
    cudaGetSymbolAddress((void**)&p_wi,     g_wi16);
    cudaGetSymbolAddress((void**)&p_wo2,    g_wo216);

    cudaFuncSetAttribute(flash_attn,
                         cudaFuncAttributeMaxDynamicSharedMemorySize, FLASH_SMEM);
    const int SM_BN128 = 4 * (2560 + 128 * 20) * 4;   // 81920 B
    const int SM_BN64  = 4 * (2560 + 64 * 20) * 4;    // 61440 B
    cudaFuncSetAttribute(gemm_h<128,2,4,1>,
                         cudaFuncAttributeMaxDynamicSharedMemorySize, SM_BN128);
    cudaFuncSetAttribute(gemm_h<128,2,4,3>,
                         cudaFuncAttributeMaxDynamicSharedMemorySize, SM_BN128);
    cudaFuncSetAttribute(gemm_h<64,4,2,0>,
                         cudaFuncAttributeMaxDynamicSharedMemorySize, SM_BN64);

    // ---- prep: weight transpose->fp16, bias fp16, h/h16 ----
    dim3 tb(32, 8);
    dim3 gDD(D_ / 32, D_ / 32, L_);
    dim3 gWi(FF_ / 32, D_ / 32, L_);
    dim3 gWo2(D_ / 32, FF_ / 32, L_);
    transpose_cvt_kernel<<<gDD, tb>>>(Wq,  p_wq,  D_, D_);
    transpose_cvt_kernel<<<gDD, tb>>>(Wk,  p_wk,  D_, D_);
    transpose_cvt_kernel<<<gDD, tb>>>(Wv,  p_wv,  D_, D_);
    transpose_cvt_kernel<<<gDD, tb>>>(Wo,  p_wo,  D_, D_);
    transpose_cvt_kernel<<<gWi, tb>>>(Wi,  p_wi,  D_, FF_);
    transpose_cvt_kernel<<<gWo2, tb>>>(Wo2, p_wo2, FF_, D_);

    long nb = (long)BH_ * SS_;
    bias_kernel<<<(unsigned)((nb + 255) / 256), 256>>>(rel, rel2, mask);
    copy2_kernel<<<(MR_ * D_ + 255) / 256, 256>>>(hs, p_h, p_h16, (long)MR_ * D_);

    dim3 gQKV(3 * D_ / 128, MR_ / 128, 1);  // 288
    dim3 gFA (S_ / 64, BH_, 1);             // 384, 3 CTAs/SM -> single wave
    dim3 gWoG(D_ / 64, MR_ / 128, 2);       // 384 (split-K=2)
    dim3 gF1 (FF_ / 128, MR_ / 128, 1);     // 384
    dim3 gF2 (D_ / 64, MR_ / 128, 2);       // 384 (split-K=2)

    for (int l = 0; l < L_; l++) {
        const __half* wq  = p_wq  + (long)l * D_ * D_;
        const __half* wk  = p_wk  + (long)l * D_ * D_;
        const __half* wv  = p_wv  + (long)l * D_ * D_;
        const __half* wo  = p_wo  + (long)l * D_ * D_;
        const __half* wi  = p_wi  + (long)l * D_ * FF_;
        const __half* wo2 = p_wo2 + (long)l * FF_ * D_;

        // fused QKV projections (q folds 1/8), fp16 scatter to [B,H,S,DH]
        gemm_h<128,2,4,1><<<gQKV, 256, SM_BN128>>>(
            p_h16, wq, (float*)p_q16, bq + l * D_,
            wk, bk + l * D_, (float*)p_k16,
            wv, bv + l * D_, (float*)p_v16,
            MR_, D_, D_, D_, D_, 0.125f);

        // fused attention (full fp16) -> ctx (fp16) [B,S,D]
        flash_attn<<<gFA, 128, FLASH_SMEM>>>(p_q16, p_k16, p_v16,
                                             p_bias16, p_ctx16);

        // ctx @ Wo (split-K=2, raw partials) -> LN1 fused reduce + bias + res
        gemm_h<64,4,2,0><<<gWoG, 256, SM_BN64>>>(
            p_ctx16, wo, p_part, nullptr,
            nullptr, nullptr, nullptr, nullptr, nullptr, nullptr,
            MR_, D_, D_ / 2, D_, D_, 1.0f);
        layernorm768_red<<<MR_, 256>>>(p_part, bo + l * D_, p_h,
                                       ln1g + l * D_, ln1b + l * D_,
                                       p_attn, p_attn16);

        // ff16 = fp16(gelu(attn @ Wi + bi))
        gemm_h<128,2,4,3><<<gF1, 256, SM_BN128>>>(
            p_attn16, wi, (float*)p_ff16, bi + l * FF_,
            nullptr, nullptr, nullptr, nullptr, nullptr, nullptr,
            MR_, FF_, D_, D_, D_, 1.0f);

        // ff @ Wo2 (split-K=2, raw partials) -> LN2 fused reduce + bias + res
        gemm_h<64,4,2,0><<<gF2, 256, SM_BN64>>>(
            p_ff16, wo2, p_part, nullptr,
            nullptr, nullptr, nullptr, nullptr, nullptr, nullptr,
            MR_, D_, FF_ / 2, FF_, FF_, 1.0f);
        float* dst = (l == L_ - 1) ? out : p_h;
        layernorm768_red<<<MR_, 256>>>(p_part, bo2 + l * D_, p_attn,
                                       ln2g + l * D_, ln2b + l * D_,
                                       dst, p_h16);
    }
}

// round 15
// speedup vs baseline: 2.6997x; 1.1018x over previous
#include <cuda_runtime.h>
#include <cuda_fp16.h>
#include <math.h>
#include <stdint.h>

// ---------------- problem constants ----------------
#define L_   12
#define B_   4
#define S_   512
#define D_   768
#define H_   12
#define DH_  64
#define FF_  3072
#define BH_  (B_*H_)        // 48
#define MR_  (B_*S_)        // 2048
#define SS_  (S_*S_)        // 262144

// ---------------- scratch (device globals; allocation-free) ----------------
__device__ __half g_bias16[BH_*SS_];   // fp16 attention bias (layer-invariant)
__device__ __half g_q16 [BH_*S_*DH_];  // fp16 (flash input)
__device__ __half g_k16 [BH_*S_*DH_];
__device__ __half g_v16 [BH_*S_*DH_];
__device__ __half g_ctx16[MR_*D_];     // flash output (fp16)
__device__ float  g_h   [MR_*D_];      // fp32 residual
__device__ __half g_h16 [MR_*D_];      // fp16 shadow
__device__ float  g_attn[MR_*D_];      // fp32 residual
__device__ __half g_attn16[MR_*D_];    // fp16 shadow
__device__ __half g_ff16[MR_*FF_];     // gelu out (fp16)
__device__ float  g_part[2*MR_*D_];    // split-K partials (fp32)
// pre-transposed fp16 weights [N][K]
__device__ __half g_wq16 [L_*D_*D_];
__device__ __half g_wk16 [L_*D_*D_];
__device__ __half g_wv16 [L_*D_*D_];
__device__ __half g_wo16 [L_*D_*D_];
__device__ __half g_wi16 [L_*D_*FF_];
__device__ __half g_wo216[L_*FF_*D_];

// ---------------- helpers ----------------
__device__ __forceinline__ void mma_f16(float* c, const uint32_t* a, const uint32_t* b)
{
    asm("mma.sync.aligned.m16n8k16.row.col.f32.f16.f16.f32 "
        "{%0,%1,%2,%3}, {%4,%5,%6,%7}, {%8,%9}, {%0,%1,%2,%3};"
        : "+f"(c[0]), "+f"(c[1]), "+f"(c[2]), "+f"(c[3])
        : "r"(a[0]), "r"(a[1]), "r"(a[2]), "r"(a[3]),
          "r"(b[0]), "r"(b[1]));
}

__device__ __forceinline__ void ldsm4(uint32_t* d, uint32_t addr)
{
    asm volatile("ldmatrix.sync.aligned.m8n8.x4.shared.b16 {%0,%1,%2,%3}, [%4];"
                 : "=r"(d[0]), "=r"(d[1]), "=r"(d[2]), "=r"(d[3]) : "r"(addr));
}

__device__ __forceinline__ void ldsm4t(uint32_t& d0, uint32_t& d1,
                                       uint32_t& d2, uint32_t& d3, uint32_t addr)
{
    asm volatile("ldmatrix.sync.aligned.m8n8.x4.trans.shared.b16 "
                 "{%0,%1,%2,%3}, [%4];"
                 : "=r"(d0), "=r"(d1), "=r"(d2), "=r"(d3) : "r"(addr));
}

__device__ __forceinline__ void cp16(void* dst, const void* src)
{
    uint32_t d = (uint32_t)__cvta_generic_to_shared(dst);
    asm volatile("cp.async.cg.shared.global [%0], [%1], 16;" :: "r"(d), "l"(src));
}
#define CP_COMMIT() asm volatile("cp.async.commit_group;")

// ---------------- small kernels ----------------
__global__ void bias_kernel(const float* __restrict__ rel,
                            const float* __restrict__ rel2,
                            const float* __restrict__ mask)
{
    long i = (long)blockIdx.x * 256 + threadIdx.x;
    if (i >= (long)BH_ * SS_) return;
    int b = (int)(i / ((long)H_ * SS_));
    int kcol = (int)(i & (S_ - 1));
    g_bias16[i] = __float2half((rel[i] + rel2[i]) * 0.125f + mask[b * S_ + kcol]);
}

// batched transpose + fp16 cvt for the four DxD weights:
// z = which*L + layer; src [K][N] fp32 -> dst [N][K] fp16
__global__ void transpose_cvt4_kernel(const float* __restrict__ s0, __half* d0,
                                      const float* __restrict__ s1, __half* d1,
                                      const float* __restrict__ s2, __half* d2,
                                      const float* __restrict__ s3, __half* d3)
{
    __shared__ float tile[32][33];
    const int which = blockIdx.z / L_, layer = blockIdx.z % L_;
    const float* src = which == 0 ? s0 : which == 1 ? s1 : which == 2 ? s2 : s3;
    __half* dst = which == 0 ? d0 : which == 1 ? d1 : which == 2 ? d2 : d3;
    const long lz = (long)layer * D_ * D_;
    const int k0 = blockIdx.y * 32, n0 = blockIdx.x * 32;
    const int tx = threadIdx.x, ty = threadIdx.y;   // 32 x 8
#pragma unroll
    for (int i = 0; i < 32; i += 8)
        tile[ty + i][tx] = src[lz + (long)(k0 + ty + i) * D_ + n0 + tx];
    __syncthreads();
#pragma unroll
    for (int i = 0; i < 32; i += 8)
        dst[lz + (long)(n0 + ty + i) * D_ + k0 + tx] = __float2half(tile[tx][ty + i]);
}

// generic transpose + fp16 cvt: src [K][N] fp32 -> dst [N][K] fp16, per layer
__global__ void transpose_cvt_kernel(const float* __restrict__ src,
                                     __half* __restrict__ dst, int K, int N)
{
    __shared__ float tile[32][33];
    const long lz = (long)blockIdx.z * K * N;
    const int k0 = blockIdx.y * 32, n0 = blockIdx.x * 32;
    const int tx = threadIdx.x, ty = threadIdx.y;
#pragma unroll
    for (int i = 0; i < 32; i += 8)
        tile[ty + i][tx] = src[lz + (long)(k0 + ty + i) * N + n0 + tx];
    __syncthreads();
#pragma unroll
    for (int i = 0; i < 32; i += 8)
        dst[lz + (long)(n0 + ty + i) * K + k0 + tx] = __float2half(tile[tx][ty + i]);
}

__global__ void copy2_kernel(const float* __restrict__ src, float* __restrict__ dst,
                             __half* __restrict__ dst16, long n)
{
    long i = (long)blockIdx.x * 256 + threadIdx.x;
    if (i < n) { float v = src[i]; dst[i] = v; dst16[i] = __float2half(v); }
}

// ---------------- fused flash attention (v5: ldmatrix everywhere) -----------
// word offsets: K[2] @0 (2304 ea), V[2] @4608, Q/P @9216, bias[2] @11520
#define FLASH_SMEM (16128 * 4)   // 64512 B -> 3 CTAs/SM

__global__ __launch_bounds__(128, 3)
void flash_attn(const __half* __restrict__ Qg, const __half* __restrict__ Kg,
                const __half* __restrict__ Vg, const __half* __restrict__ biasg,
                __half* __restrict__ ctx)
{
    extern __shared__ uint32_t smw[];

    const int z  = blockIdx.y;
    const int q0 = blockIdx.x * 64;
    const int tid  = threadIdx.x;
    const int warp = tid >> 5, lane = tid & 31;
    const int g = lane >> 2, tig = lane & 3;

    const __half* Qz = Qg + (long)z * S_ * DH_;
    const __half* Kz = Kg + (long)z * S_ * DH_;
    const __half* Vz = Vg + (long)z * S_ * DH_;
    const __half* bz = biasg + (long)z * SS_;

    auto loadKVB = [&](int s, int kt) {
        __half* Kh = (__half*)(smw + s * 2304);
        __half* Vh = (__half*)(smw + 4608 + s * 2304);
        __half* Bh = (__half*)(smw + 11520 + s * 2304);
#pragma unroll
        for (int i = 0; i < 4; i++) {
            int idx = i * 128 + tid;
            int n = idx >> 3, c8 = (idx & 7) << 3;
            cp16(Kh + n * 72 + c8, Kz + (long)(kt * 64 + n) * DH_ + c8);
            cp16(Vh + n * 72 + c8, Vz + (long)(kt * 64 + n) * DH_ + c8);
            cp16(Bh + n * 72 + c8, bz + (long)(q0 + n) * S_ + kt * 64 + c8);
        }
    };

    {
        __half* Qh = (__half*)(smw + 9216);
#pragma unroll
        for (int i = 0; i < 4; i++) {
            int idx = i * 128 + tid;
            int m = idx >> 3, c8 = (idx & 7) << 3;
            cp16(Qh + m * 72 + c8, Qz + (long)(q0 + m) * DH_ + c8);
        }
    }
    loadKVB(0, 0);
    CP_COMMIT();
    asm volatile("cp.async.wait_group 0;");
    __syncthreads();

    const int r = warp * 16 + g;
    const uint32_t smem_u = (uint32_t)__cvta_generic_to_shared(smw);

    // ldmatrix lane invariants
    const int a_r = warp * 16 + (lane & 7) + ((lane >> 3) & 1) * 8;  // A frag row
    const int a_w = (lane >> 4) << 2;                                 // k-hi words
    const int b_r = (lane & 7) + ((lane >> 4) << 3);                  // B frag row
    const int b_w = ((lane >> 3) & 1) << 2;

    // hoist Q fragments (kt-invariant): 4 k16 steps via ldmatrix
    uint32_t afq[4][4];
#pragma unroll
    for (int ks = 0; ks < 4; ks++)
        ldsm4(afq[ks], smem_u + (9216 + a_r * 36 + ks * 8 + a_w) * 4);
    __syncthreads();   // all Q reads done before P overwrites the pane

    float acc[8][4] = {};
    float mrow0 = -1e30f, mrow1 = -1e30f;
    float l0 = 0.0f, l1 = 0.0f;
    int buf = 0;

    uint32_t* P2 = smw + 9216;
    const int lm = lane & 15, hi8 = (lane >> 4) << 3;

    for (int kt = 0; kt < 8; kt++) {
        if (kt < 7) loadKVB(buf ^ 1, kt + 1);
        CP_COMMIT();

        // phase A: S = Q.K^T (q pre-scaled by 1/8); K frags via ldmatrix
        const uint32_t koff = smem_u + (buf * 2304) * 4;
        float s[8][4] = {};
#pragma unroll
        for (int ks = 0; ks < 4; ks++) {
            uint32_t bf[8][2];
#pragma unroll
            for (int p = 0; p < 4; p++) {
                uint32_t d[4];
                ldsm4(d, koff + ((b_r + p * 16) * 36 + ks * 8 + b_w) * 4);
                bf[2 * p][0] = d[0]; bf[2 * p][1] = d[1];
                bf[2 * p + 1][0] = d[2]; bf[2 * p + 1][1] = d[3];
            }
#pragma unroll
            for (int nt = 0; nt < 8; nt++)
                mma_f16(s[nt], afq[ks], bf[nt]);
        }

        // bias (fp16, smem-prefetched) + online softmax
        const __half* bp = (const __half*)(smw + 11520 + buf * 2304);
        float nm0 = mrow0, nm1 = mrow1;
#pragma unroll
        for (int nt = 0; nt < 8; nt++) {
            int c = nt * 8 + 2 * tig;
            float2 b0 = __half22float2(*(const half2*)(bp + r * 72 + c));
            float2 b1 = __half22float2(*(const half2*)(bp + (r + 8) * 72 + c));
            s[nt][0] += b0.x; s[nt][1] += b0.y;
            s[nt][2] += b1.x; s[nt][3] += b1.y;
            nm0 = fmaxf(nm0, fmaxf(s[nt][0], s[nt][1]));
            nm1 = fmaxf(nm1, fmaxf(s[nt][2], s[nt][3]));
        }
        nm0 = fmaxf(nm0, __shfl_xor_sync(0xffffffffu, nm0, 1));
        nm0 = fmaxf(nm0, __shfl_xor_sync(0xffffffffu, nm0, 2));
        nm1 = fmaxf(nm1, __shfl_xor_sync(0xffffffffu, nm1, 1));
        nm1 = fmaxf(nm1, __shfl_xor_sync(0xffffffffu, nm1, 2));

        float alpha0 = __expf(mrow0 - nm0);
        float alpha1 = __expf(mrow1 - nm1);
        mrow0 = nm0; mrow1 = nm1;

        float rs0 = 0.0f, rs1 = 0.0f;
#pragma unroll
        for (int nt = 0; nt < 8; nt++) {
            float p0 = __expf(s[nt][0] - nm0);
            float p1 = __expf(s[nt][1] - nm0);
            float p2 = __expf(s[nt][2] - nm1);
            float p3 = __expf(s[nt][3] - nm1);
            rs0 += p0 + p1; rs1 += p2 + p3;
            half2 h01 = __floats2half2_rn(p0, p1);
            half2 h23 = __floats2half2_rn(p2, p3);
            P2[r * 36 + nt * 4 + tig]       = *(uint32_t*)&h01;
            P2[(r + 8) * 36 + nt * 4 + tig] = *(uint32_t*)&h23;
            acc[nt][0] *= alpha0; acc[nt][1] *= alpha0;
            acc[nt][2] *= alpha1; acc[nt][3] *= alpha1;
        }
        rs0 += __shfl_xor_sync(0xffffffffu, rs0, 1);
        rs0 += __shfl_xor_sync(0xffffffffu, rs0, 2);
        rs1 += __shfl_xor_sync(0xffffffffu, rs1, 1);
        rs1 += __shfl_xor_sync(0xffffffffu, rs1, 2);
        l0 = l0 * alpha0 + rs0;
        l1 = l1 * alpha1 + rs1;
        __syncwarp();

        // phase C: ctx += P.V (P frags via ldmatrix, V via ldmatrix.trans)
        const uint32_t psh = smem_u + 9216 * 4;
        const uint32_t vsh = smem_u + (4608 + buf * 2304) * 4;
#pragma unroll
        for (int ks = 0; ks < 4; ks++) {
            const int kk = ks * 16;
            uint32_t af[4];
            ldsm4(af, psh + (a_r * 36 + ks * 8 + a_w) * 4);
#pragma unroll
            for (int nt2 = 0; nt2 < 4; nt2++) {
                uint32_t b0, b1, b2, b3;
                uint32_t addr = vsh +
                    (((kk + lm) * 72 + nt2 * 16 + hi8) << 1);
                ldsm4t(b0, b1, b2, b3, addr);
                uint32_t bfA[2] = {b0, b1}, bfB[2] = {b2, b3};
                mma_f16(acc[nt2 * 2],     af, bfA);
                mma_f16(acc[nt2 * 2 + 1], af, bfB);
            }
        }

        if (kt < 7) {
            asm volatile("cp.async.wait_group 0;");
            __syncthreads();
        }
        buf ^= 1;
    }

    // epilogue: normalize, write fp16 ctx gathered to [B,S,D]
    const float inv0 = 1.0f / l0, inv1 = 1.0f / l1;
    const int b = z / H_, hh = z % H_;
    const int mg = q0 + r;
    __half* out0 = ctx + (long)(b * S_ + mg) * D_ + hh * DH_;
    __half* out1 = out0 + 8 * D_;
#pragma unroll
    for (int nt = 0; nt < 8; nt++) {
        int c = nt * 8 + 2 * tig;
        *(half2*)(out0 + c) = __floats2half2_rn(acc[nt][0] * inv0, acc[nt][1] * inv0);
        *(half2*)(out1 + c) = __floats2half2_rn(acc[nt][2] * inv1, acc[nt][3] * inv1);
    }
}

// ---------------- tensor-core FP16 GEMM (cp.async, 4-stage, ldmatrix) -------
// C = A[M,K_total] @ W (A fp16 row-major [M][K]; W pre-transposed fp16 [N][K]).
// BK=32 halves, mma m16n8k16, fp32 accum, frags via ldmatrix.x4.
// EPI: 0 = raw fp32 partial store to C + z*M*N
//      1 = fused QKV scatter, fp16 out; picks {Wq,Wk,Wv} by n-block
//      3 = fp16 gelu(acc + bias[n]) to (half*)C
template<int BN, int WARPS_M, int WARPS_N, int EPI>
__global__ __launch_bounds__(256, 2)
void gemm_h(const __half* __restrict__ A, const __half* __restrict__ Bt,
            float* __restrict__ C, const float* __restrict__ bias,
            const __half* __restrict__ Bt2, const float* __restrict__ bias2,
            float* __restrict__ C2,
            const __half* __restrict__ Bt3, const float* __restrict__ bias3,
            float* __restrict__ C3,
            int M, int N, int K, int lda, int ldb, float scaleval)
{
    constexpr int BM = 128, BK = 32, STAGES = 4;
    constexpr int WM = BM / WARPS_M, WN = BN / WARPS_N;
    constexpr int MT = WM / 16, NTL = WN / 8;
    constexpr int STR2 = BK / 2 + 4;      // 20 half2 words, ==4 mod 32
    constexpr int ASZ = BM * STR2;
    constexpr int BSZ = BN * STR2;

    extern __shared__ uint32_t sm2[];
    uint32_t* AsB = sm2;
    uint32_t* BsB = sm2 + STAGES * ASZ;

    const int zz = blockIdx.z;
    A  += (long)zz * K;
    Bt += (long)zz * K;

    int n0;
    if constexpr (EPI == 1) {
        const int nb = N / BN;
        const int which = blockIdx.x / nb;
        n0 = (blockIdx.x % nb) * BN;
        if (which == 1) { Bt = Bt2; bias = bias2; C = C2; scaleval = 1.0f; }
        else if (which == 2) { Bt = Bt3; bias = bias3; C = C3; scaleval = 1.0f; }
    } else {
        n0 = blockIdx.x * BN;
    }
    float* Cw = C;
    if constexpr (EPI == 0) Cw = C + (long)zz * M * N;

    const int m0 = blockIdx.y * BM;
    const int tid  = threadIdx.x;
    const int warp = tid >> 5, lane = tid & 31;
    const int g = lane >> 2, tig = lane & 3;
    const int wm = warp % WARPS_M, wn = warp / WARPS_M;
    const int m_base = wm * WM, n_base = wn * WN;

    const uint32_t smem_u = (uint32_t)__cvta_generic_to_shared(sm2);
    // ldmatrix lane invariants (A frag rows / B frag rows)
    const int a_r = m_base + (lane & 7) + ((lane >> 3) & 1) * 8;
    const int a_w = (lane >> 4) << 2;
    const int b_r = n_base + (lane & 7) + ((lane >> 4) << 3);
    const int b_w = ((lane >> 3) & 1) << 2;

    float acc[MT][NTL][4] = {};

    auto loadTiles = [&](int stage, int kt) {
        const int k0 = kt * BK;
        uint32_t* as = AsB + stage * ASZ;
        uint32_t* bs = BsB + stage * BSZ;
#pragma unroll
        for (int i = 0; i < 2; i++) {
            int id = tid * 2 + i;
            int m = id >> 2, j = id & 3;
            cp16(&as[m * STR2 + 4 * j], A + (long)(m0 + m) * lda + k0 + 8 * j);
        }
        if constexpr (BN == 128) {
#pragma unroll
            for (int i = 0; i < 2; i++) {
                int id = tid * 2 + i;
                int n = id >> 2, j = id & 3;
                cp16(&bs[n * STR2 + 4 * j], Bt + (long)(n0 + n) * ldb + k0 + 8 * j);
            }
        } else {
            int n = tid >> 2, j = tid & 3;
            cp16(&bs[n * STR2 + 4 * j], Bt + (long)(n0 + n) * ldb + k0 + 8 * j);
        }
    };

    auto compute = [&](int stage) {
        const uint32_t aoff = smem_u + (stage * ASZ) * 4;
        const uint32_t boff = smem_u + (STAGES * ASZ + stage * BSZ) * 4;
#pragma unroll
        for (int ks = 0; ks < 2; ks++) {
            const int kk2 = ks * 8;
            uint32_t af[MT][4], bf[NTL][2];
#pragma unroll
            for (int mt = 0; mt < MT; mt++)
                ldsm4(af[mt], aoff + ((a_r + mt * 16) * STR2 + kk2 + a_w) * 4);
#pragma unroll
            for (int p = 0; p < NTL / 2; p++) {
                uint32_t d[4];
                ldsm4(d, boff + ((b_r + p * 16) * STR2 + kk2 + b_w) * 4);
                bf[2 * p][0] = d[0]; bf[2 * p][1] = d[1];
                bf[2 * p + 1][0] = d[2]; bf[2 * p + 1][1] = d[3];
            }
#pragma unroll
            for (int mt = 0; mt < MT; mt++)
#pragma unroll
                for (int nt = 0; nt < NTL; nt++)
                    mma_f16(acc[mt][nt], af[mt], bf[nt]);
        }
    };

    const int KT = K / BK;
#pragma unroll
    for (int s = 0; s < STAGES - 1; s++) { loadTiles(s, s); CP_COMMIT(); }

    for (int kt = 0; kt < KT; kt++) {
        asm volatile("cp.async.wait_group 2;");
        __syncthreads();
        const int pf = kt + STAGES - 1;
        if (pf < KT) loadTiles(pf & (STAGES - 1), pf);
        CP_COMMIT();
        compute(kt & (STAGES - 1));
    }

#pragma unroll
    for (int mt = 0; mt < MT; mt++) {
        int r0 = m0 + m_base + mt * 16 + g;
#pragma unroll
        for (int nt = 0; nt < NTL; nt++) {
            int c0 = n0 + n_base + nt * 8 + 2 * tig;
            float v0 = acc[mt][nt][0], v1 = acc[mt][nt][1];
            float v2 = acc[mt][nt][2], v3 = acc[mt][nt][3];
            if constexpr (EPI == 0) {
                *(float2*)&Cw[(long)r0 * N + c0]       = make_float2(v0, v1);
                *(float2*)&Cw[(long)(r0 + 8) * N + c0] = make_float2(v2, v3);
            } else if constexpr (EPI == 1) {
                __half* Ch = (__half*)C;
                float2 bb = *(const float2*)&bias[c0];
                half2 w01 = __floats2half2_rn((v0 + bb.x) * scaleval,
                                              (v1 + bb.y) * scaleval);
                half2 w23 = __floats2half2_rn((v2 + bb.x) * scaleval,
                                              (v3 + bb.y) * scaleval);
                int bq = r0 >> 9, s = r0 & 511, hh = c0 >> 6, d = c0 & 63;
                long o0 = ((((long)bq * H_ + hh) * S_ + s) * DH_) + d;
                *(half2*)&Ch[o0]           = w01;
                *(half2*)&Ch[o0 + 8 * DH_] = w23;
            } else if constexpr (EPI == 3) {
                __half* Ch = (__half*)C;
                float2 bb = *(const float2*)&bias[c0];
                float x0 = v0 + bb.x, x1 = v1 + bb.y;
                float x2 = v2 + bb.x, x3 = v3 + bb.y;
                float w0 = 0.5f * x0 * (1.0f + erff(x0 * 0.70710678118654752f));
                float w1 = 0.5f * x1 * (1.0f + erff(x1 * 0.70710678118654752f));
                float w2 = 0.5f * x2 * (1.0f + erff(x2 * 0.70710678118654752f));
                float w3 = 0.5f * x3 * (1.0f + erff(x3 * 0.70710678118654752f));
                *(half2*)&Ch[(long)r0 * N + c0]       = __floats2half2_rn(w0, w1);
                *(half2*)&Ch[(long)(r0 + 8) * N + c0] = __floats2half2_rn(w2, w3);
            }
        }
    }
}

// ---- layernorm 768 with fused split-K reduce: x = p0 + p1 + bias + res ----
__global__ __launch_bounds__(256)
void layernorm768_red(const float* __restrict__ part, const float* __restrict__ bvec,
                      const float* __restrict__ res, const float* __restrict__ g,
                      const float* __restrict__ b, float* __restrict__ y,
                      __half* __restrict__ y16)
{
    const long off = (long)blockIdx.x * D_;
    const float* p0 = part + off;
    const float* p1 = part + (long)MR_ * D_ + off;
    const float* rr = res + off;
    float*  orow  = y   + off;
    __half* orow2 = y16 + off;
    int tid = threadIdx.x;
    float a0 = p0[tid]       + p1[tid]       + bvec[tid]       + rr[tid];
    float a1 = p0[tid + 256] + p1[tid + 256] + bvec[tid + 256] + rr[tid + 256];
    float a2 = p0[tid + 512] + p1[tid + 512] + bvec[tid + 512] + rr[tid + 512];
    float s = a0 + a1 + a2;
    float q = a0 * a0 + a1 * a1 + a2 * a2;
    __shared__ float rs[8], rq[8];
#pragma unroll
    for (int o = 16; o; o >>= 1) {
        s += __shfl_xor_sync(0xffffffffu, s, o);
        q += __shfl_xor_sync(0xffffffffu, q, o);
    }
    if ((tid & 31) == 0) { rs[tid >> 5] = s; rq[tid >> 5] = q; }
    __syncthreads();
    s = (rs[0] + rs[1]) + (rs[2] + rs[3]) + (rs[4] + rs[5]) + (rs[6] + rs[7]);
    q = (rq[0] + rq[1]) + (rq[2] + rq[3]) + (rq[4] + rq[5]) + (rq[6] + rq[7]);
    float mean = s * (1.0f / D_);
    float var  = q * (1.0f / D_) - mean * mean;
    float r = rsqrtf(var + 1e-5f);
    float v0 = (a0 - mean) * r * g[tid]       + b[tid];
    float v1 = (a1 - mean) * r * g[tid + 256] + b[tid + 256];
    float v2 = (a2 - mean) * r * g[tid + 512] + b[tid + 512];
    orow[tid]        = v0;  orow[tid + 256]  = v1;  orow[tid + 512]  = v2;
    orow2[tid]       = __float2half(v0);
    orow2[tid + 256] = __float2half(v1);
    orow2[tid + 512] = __float2half(v2);
}

// ---------------- host orchestration ----------------
extern "C" void kernel_launch(void* const* d_in, const int* in_sizes, int n_in,
                              void* d_out, int out_size)
{
    const float* hs    = (const float*)d_in[0];
    const float* mask  = (const float*)d_in[1];
    const float* rel   = (const float*)d_in[2];
    const float* rel2  = (const float*)d_in[3];
    const float* Wq    = (const float*)d_in[4];
    const float* bq    = (const float*)d_in[5];
    const float* Wk    = (const float*)d_in[6];
    const float* bk    = (const float*)d_in[7];
    const float* Wv    = (const float*)d_in[8];
    const float* bv    = (const float*)d_in[9];
    const float* Wo    = (const float*)d_in[10];
    const float* bo    = (const float*)d_in[11];
    const float* ln1g  = (const float*)d_in[12];
    const float* ln1b  = (const float*)d_in[13];
    const float* Wi    = (const float*)d_in[14];
    const float* bi    = (const float*)d_in[15];
    const float* Wo2   = (const float*)d_in[16];
    const float* bo2   = (const float*)d_in[17];
    const float* ln2g  = (const float*)d_in[18];
    const float* ln2b  = (const float*)d_in[19];
    float* out = (float*)d_out;

    float *p_h, *p_attn, *p_part;
    __half *p_bias16, *p_q16, *p_k16, *p_v16, *p_ctx16, *p_h16, *p_attn16, *p_ff16;
    __half *p_wq, *p_wk, *p_wv, *p_wo, *p_wi, *p_wo2;
    cudaGetSymbolAddress((void**)&p_bias16, g_bias16);
    cudaGetSymbolAddress((void**)&p_q16,    g_q16);
    cudaGetSymbolAddress((void**)&p_k16,    g_k16);
    cudaGetSymbolAddress((void**)&p_v16,    g_v16);
    cudaGetSymbolAddress((void**)&p_ctx16,  g_ctx16);
    cudaGetSymbolAddress((void**)&p_h,      g_h);
    cudaGetSymbolAddress((void**)&p_h16,    g_h16);
    cudaGetSymbolAddress((void**)&p_attn,   g_attn);
    cudaGetSymbolAddress((void**)&p_attn16, g_attn16);
    cudaGetSymbolAddress((void**)&p_ff16,   g_ff16);
    cudaGetSymbolAddress((void**)&p_part,   g_part);
    cudaGetSymbolAddress((void**)&p_wq,     g_wq16);
    cudaGetSymbolAddress((void**)&p_wk,     g_wk16);
    cudaGetSymbolAddress((void**)&p_wv,     g_wv16);
    cudaGetSymbolAddress((void**)&p_wo,     g_wo16);
    cudaGetSymbolAddress((void**)&p_wi,     g_wi16);
    cudaGetSymbolAddress((void**)&p_wo2,    g_wo216);

    cudaFuncSetAttribute(flash_attn,
                         cudaFuncAttributeMaxDynamicSharedMemorySize, FLASH_SMEM);
    const int SM_BN128 = 4 * (2560 + 128 * 20) * 4;   // 81920 B
    const int SM_BN64  = 4 * (2560 + 64 * 20) * 4;    // 61440 B
    cudaFuncSetAttribute(gemm_h<128,2,4,1>,
                         cudaFuncAttributeMaxDynamicSharedMemorySize, SM_BN128);
    cudaFuncSetAttribute(gemm_h<128,2,4,3>,
                         cudaFuncAttributeMaxDynamicSharedMemorySize, SM_BN128);
    cudaFuncSetAttribute(gemm_h<64,4,2,0>,
                         cudaFuncAttributeMaxDynamicSharedMemorySize, SM_BN64);

    // ---- prep: weight transpose->fp16 (QKVO batched), bias fp16, h/h16 ----
    dim3 tb(32, 8);
    dim3 gDD4(D_ / 32, D_ / 32, 4 * L_);
    dim3 gWi(FF_ / 32, D_ / 32, L_);
    dim3 gWo2(D_ / 32, FF_ / 32, L_);
    transpose_cvt4_kernel<<<gDD4, tb>>>(Wq, p_wq, Wk, p_wk, Wv, p_wv, Wo, p_wo);
    transpose_cvt_kernel<<<gWi, tb>>>(Wi,  p_wi,  D_, FF_);
    transpose_cvt_kernel<<<gWo2, tb>>>(Wo2, p_wo2, FF_, D_);

    long nb = (long)BH_ * SS_;
    bias_kernel<<<(unsigned)((nb + 255) / 256), 256>>>(rel, rel2, mask);
    copy2_kernel<<<(MR_ * D_ + 255) / 256, 256>>>(hs, p_h, p_h16, (long)MR_ * D_);

    dim3 gQKV(3 * D_ / 128, MR_ / 128, 1);  // 288
    dim3 gFA (S_ / 64, BH_, 1);             // 384, 3 CTAs/SM -> single wave
    dim3 gWoG(D_ / 64, MR_ / 128, 2);       // 384 (split-K=2)
    dim3 gF1 (FF_ / 128, MR_ / 128, 1);     // 384
    dim3 gF2 (D_ / 64, MR_ / 128, 2);       // 384 (split-K=2)

    for (int l = 0; l < L_; l++) {
        const __half* wq  = p_wq  + (long)l * D_ * D_;
        const __half* wk  = p_wk  + (long)l * D_ * D_;
        const __half* wv  = p_wv  + (long)l * D_ * D_;
        const __half* wo  = p_wo  + (long)l * D_ * D_;
        const __half* wi  = p_wi  + (long)l * D_ * FF_;
        const __half* wo2 = p_wo2 + (long)l * FF_ * D_;

        // fused QKV projections (q folds 1/8), fp16 scatter to [B,H,S,DH]
        gemm_h<128,2,4,1><<<gQKV, 256, SM_BN128>>>(
            p_h16, wq, (float*)p_q16, bq + l * D_,
            wk, bk + l * D_, (float*)p_k16,
            wv, bv + l * D_, (float*)p_v16,
            MR_, D_, D_, D_, D_, 0.125f);

        // fused attention (full fp16) -> ctx (fp16) [B,S,D]
        flash_attn<<<gFA, 128, FLASH_SMEM>>>(p_q16, p_k16, p_v16,
                                             p_bias16, p_ctx16);

        // ctx @ Wo (split-K=2, raw partials) -> LN1 fused reduce + bias + res
        gemm_h<64,4,2,0><<<gWoG, 256, SM_BN64>>>(
            p_ctx16, wo, p_part, nullptr,
            nullptr, nullptr, nullptr, nullptr, nullptr, nullptr,
            MR_, D_, D_ / 2, D_, D_, 1.0f);
        layernorm768_red<<<MR_, 256>>>(p_part, bo + l * D_, p_h,
                                       ln1g + l * D_, ln1b + l * D_,
                                       p_attn, p_attn16);

        // ff16 = fp16(gelu(attn @ Wi + bi))
        gemm_h<128,2,4,3><<<gF1, 256, SM_BN128>>>(
            p_attn16, wi, (float*)p_ff16, bi + l * FF_,
            nullptr, nullptr, nullptr, nullptr, nullptr, nullptr,
            MR_, FF_, D_, D_, D_, 1.0f);

        // ff @ Wo2 (split-K=2, raw partials) -> LN2 fused reduce + bias + res
        gemm_h<64,4,2,0><<<gF2, 256, SM_BN64>>>(
            p_ff16, wo2, p_part, nullptr,
            nullptr, nullptr, nullptr, nullptr, nullptr, nullptr,
            MR_, D_, FF_ / 2, FF_, FF_, 1.0f);
        float* dst = (l == L_ - 1) ? out : p_h;
        layernorm768_red<<<MR_, 256>>>(p_part, bo2 + l * D_, p_attn,
                                       ln2g + l * D_, ln2b + l * D_,
                                       dst, p_h16);
    }
}

// round 16
// speedup vs baseline: 3.1745x; 1.1759x over previous
#include <cuda_runtime.h>
#include <cuda_fp16.h>
#include <math.h>
#include <stdint.h>

// ---------------- problem constants ----------------
#define L_   12
#define B_   4
#define S_   512
#define D_   768
#define H_   12
#define DH_  64
#define FF_  3072
#define BH_  (B_*H_)        // 48
#define MR_  (B_*S_)        // 2048
#define SS_  (S_*S_)        // 262144

// ---------------- scratch (device globals; allocation-free) ----------------
__device__ __half g_bias16[BH_*SS_];   // fp16 attention bias (layer-invariant)
__device__ __half g_q16 [BH_*S_*DH_];  // fp16 (flash input)
__device__ __half g_k16 [BH_*S_*DH_];
__device__ __half g_v16 [BH_*S_*DH_];
__device__ __half g_ctx16[MR_*D_];     // flash output (fp16)
__device__ float  g_h   [MR_*D_];      // fp32 residual
__device__ __half g_h16 [MR_*D_];      // fp16 shadow
__device__ float  g_attn[MR_*D_];      // fp32 residual
__device__ __half g_attn16[MR_*D_];    // fp16 shadow
__device__ __half g_ff16[MR_*FF_];     // gelu out (fp16)
__device__ float  g_part[2*MR_*D_];    // split-K partials (fp32)
// pre-transposed fp16 weights [N][K]
__device__ __half g_wq16 [L_*D_*D_];
__device__ __half g_wk16 [L_*D_*D_];
__device__ __half g_wv16 [L_*D_*D_];
__device__ __half g_wo16 [L_*D_*D_];
__device__ __half g_wi16 [L_*D_*FF_];
__device__ __half g_wo216[L_*FF_*D_];

// ---------------- helpers ----------------
__device__ __forceinline__ void mma_f16(float* c, const uint32_t* a, const uint32_t* b)
{
    asm("mma.sync.aligned.m16n8k16.row.col.f32.f16.f16.f32 "
        "{%0,%1,%2,%3}, {%4,%5,%6,%7}, {%8,%9}, {%0,%1,%2,%3};"
        : "+f"(c[0]), "+f"(c[1]), "+f"(c[2]), "+f"(c[3])
        : "r"(a[0]), "r"(a[1]), "r"(a[2]), "r"(a[3]),
          "r"(b[0]), "r"(b[1]));
}

__device__ __forceinline__ void ldsm4(uint32_t* d, uint32_t addr)
{
    asm volatile("ldmatrix.sync.aligned.m8n8.x4.shared.b16 {%0,%1,%2,%3}, [%4];"
                 : "=r"(d[0]), "=r"(d[1]), "=r"(d[2]), "=r"(d[3]) : "r"(addr));
}

__device__ __forceinline__ void ldsm4t(uint32_t& d0, uint32_t& d1,
                                       uint32_t& d2, uint32_t& d3, uint32_t addr)
{
    asm volatile("ldmatrix.sync.aligned.m8n8.x4.trans.shared.b16 "
                 "{%0,%1,%2,%3}, [%4];"
                 : "=r"(d0), "=r"(d1), "=r"(d2), "=r"(d3) : "r"(addr));
}

__device__ __forceinline__ void cp16(void* dst, const void* src)
{
    uint32_t d = (uint32_t)__cvta_generic_to_shared(dst);
    asm volatile("cp.async.cg.shared.global [%0], [%1], 16;" :: "r"(d), "l"(src));
}
#define CP_COMMIT() asm volatile("cp.async.commit_group;")

// ---------------- small kernels ----------------
__global__ void bias_kernel(const float* __restrict__ rel,
                            const float* __restrict__ rel2,
                            const float* __restrict__ mask)
{
    long i = ((long)blockIdx.x * 256 + threadIdx.x) * 2;
    if (i >= (long)BH_ * SS_) return;
    int b = (int)(i / ((long)H_ * SS_));
    int kcol = (int)(i & (S_ - 1));
    float2 r1 = *(const float2*)&rel[i];
    float2 r2 = *(const float2*)&rel2[i];
    float2 mm = *(const float2*)&mask[b * S_ + kcol];
    *(half2*)&g_bias16[i] = __floats2half2_rn(
        (r1.x + r2.x) * 0.125f + mm.x, (r1.y + r2.y) * 0.125f + mm.y);
}

// batched transpose + fp16 cvt for the four DxD weights
__global__ void transpose_cvt4_kernel(const float* __restrict__ s0, __half* d0,
                                      const float* __restrict__ s1, __half* d1,
                                      const float* __restrict__ s2, __half* d2,
                                      const float* __restrict__ s3, __half* d3)
{
    __shared__ float tile[32][33];
    const int which = blockIdx.z / L_, layer = blockIdx.z % L_;
    const float* src = which == 0 ? s0 : which == 1 ? s1 : which == 2 ? s2 : s3;
    __half* dst = which == 0 ? d0 : which == 1 ? d1 : which == 2 ? d2 : d3;
    const long lz = (long)layer * D_ * D_;
    const int k0 = blockIdx.y * 32, n0 = blockIdx.x * 32;
    const int tx = threadIdx.x, ty = threadIdx.y;   // 32 x 8
#pragma unroll
    for (int i = 0; i < 32; i += 8)
        tile[ty + i][tx] = src[lz + (long)(k0 + ty + i) * D_ + n0 + tx];
    __syncthreads();
#pragma unroll
    for (int i = 0; i < 32; i += 8)
        dst[lz + (long)(n0 + ty + i) * D_ + k0 + tx] = __float2half(tile[tx][ty + i]);
}

__global__ void transpose_cvt_kernel(const float* __restrict__ src,
                                     __half* __restrict__ dst, int K, int N)
{
    __shared__ float tile[32][33];
    const long lz = (long)blockIdx.z * K * N;
    const int k0 = blockIdx.y * 32, n0 = blockIdx.x * 32;
    const int tx = threadIdx.x, ty = threadIdx.y;
#pragma unroll
    for (int i = 0; i < 32; i += 8)
        tile[ty + i][tx] = src[lz + (long)(k0 + ty + i) * N + n0 + tx];
    __syncthreads();
#pragma unroll
    for (int i = 0; i < 32; i += 8)
        dst[lz + (long)(n0 + ty + i) * K + k0 + tx] = __float2half(tile[tx][ty + i]);
}

__global__ void copy2_kernel(const float* __restrict__ src, float* __restrict__ dst,
                             __half* __restrict__ dst16, long n)
{
    long i = (long)blockIdx.x * 256 + threadIdx.x;
    if (i < n) { float v = src[i]; dst[i] = v; dst16[i] = __float2half(v); }
}

// ---------------- fused flash attention (v5: ldmatrix everywhere) -----------
// word offsets: K[2] @0 (2304 ea), V[2] @4608, Q/P @9216, bias[2] @11520
#define FLASH_SMEM (16128 * 4)   // 64512 B -> 3 CTAs/SM

__global__ __launch_bounds__(128, 3)
void flash_attn(const __half* __restrict__ Qg, const __half* __restrict__ Kg,
                const __half* __restrict__ Vg, const __half* __restrict__ biasg,
                __half* __restrict__ ctx)
{
    extern __shared__ uint32_t smw[];

    const int z  = blockIdx.y;
    const int q0 = blockIdx.x * 64;
    const int tid  = threadIdx.x;
    const int warp = tid >> 5, lane = tid & 31;
    const int g = lane >> 2, tig = lane & 3;

    const __half* Qz = Qg + (long)z * S_ * DH_;
    const __half* Kz = Kg + (long)z * S_ * DH_;
    const __half* Vz = Vg + (long)z * S_ * DH_;
    const __half* bz = biasg + (long)z * SS_;

    auto loadKVB = [&](int s, int kt) {
        __half* Kh = (__half*)(smw + s * 2304);
        __half* Vh = (__half*)(smw + 4608 + s * 2304);
        __half* Bh = (__half*)(smw + 11520 + s * 2304);
#pragma unroll
        for (int i = 0; i < 4; i++) {
            int idx = i * 128 + tid;
            int n = idx >> 3, c8 = (idx & 7) << 3;
            cp16(Kh + n * 72 + c8, Kz + (long)(kt * 64 + n) * DH_ + c8);
            cp16(Vh + n * 72 + c8, Vz + (long)(kt * 64 + n) * DH_ + c8);
            cp16(Bh + n * 72 + c8, bz + (long)(q0 + n) * S_ + kt * 64 + c8);
        }
    };

    {
        __half* Qh = (__half*)(smw + 9216);
#pragma unroll
        for (int i = 0; i < 4; i++) {
            int idx = i * 128 + tid;
            int m = idx >> 3, c8 = (idx & 7) << 3;
            cp16(Qh + m * 72 + c8, Qz + (long)(q0 + m) * DH_ + c8);
        }
    }
    loadKVB(0, 0);
    CP_COMMIT();
    asm volatile("cp.async.wait_group 0;");
    __syncthreads();

    const int r = warp * 16 + g;
    const uint32_t smem_u = (uint32_t)__cvta_generic_to_shared(smw);

    const int a_r = warp * 16 + (lane & 7) + ((lane >> 3) & 1) * 8;
    const int a_w = (lane >> 4) << 2;
    const int b_r = (lane & 7) + ((lane >> 4) << 3);
    const int b_w = ((lane >> 3) & 1) << 2;

    uint32_t afq[4][4];
#pragma unroll
    for (int ks = 0; ks < 4; ks++)
        ldsm4(afq[ks], smem_u + (9216 + a_r * 36 + ks * 8 + a_w) * 4);
    __syncthreads();

    float acc[8][4] = {};
    float mrow0 = -1e30f, mrow1 = -1e30f;
    float l0 = 0.0f, l1 = 0.0f;
    int buf = 0;

    uint32_t* P2 = smw + 9216;
    const int lm = lane & 15, hi8 = (lane >> 4) << 3;

    for (int kt = 0; kt < 8; kt++) {
        if (kt < 7) loadKVB(buf ^ 1, kt + 1);
        CP_COMMIT();

        const uint32_t koff = smem_u + (buf * 2304) * 4;
        float s[8][4] = {};
#pragma unroll
        for (int ks = 0; ks < 4; ks++) {
            uint32_t bf[8][2];
#pragma unroll
            for (int p = 0; p < 4; p++) {
                uint32_t d[4];
                ldsm4(d, koff + ((b_r + p * 16) * 36 + ks * 8 + b_w) * 4);
                bf[2 * p][0] = d[0]; bf[2 * p][1] = d[1];
                bf[2 * p + 1][0] = d[2]; bf[2 * p + 1][1] = d[3];
            }
#pragma unroll
            for (int nt = 0; nt < 8; nt++)
                mma_f16(s[nt], afq[ks], bf[nt]);
        }

        const __half* bp = (const __half*)(smw + 11520 + buf * 2304);
        float nm0 = mrow0, nm1 = mrow1;
#pragma unroll
        for (int nt = 0; nt < 8; nt++) {
            int c = nt * 8 + 2 * tig;
            float2 b0 = __half22float2(*(const half2*)(bp + r * 72 + c));
            float2 b1 = __half22float2(*(const half2*)(bp + (r + 8) * 72 + c));
            s[nt][0] += b0.x; s[nt][1] += b0.y;
            s[nt][2] += b1.x; s[nt][3] += b1.y;
            nm0 = fmaxf(nm0, fmaxf(s[nt][0], s[nt][1]));
            nm1 = fmaxf(nm1, fmaxf(s[nt][2], s[nt][3]));
        }
        nm0 = fmaxf(nm0, __shfl_xor_sync(0xffffffffu, nm0, 1));
        nm0 = fmaxf(nm0, __shfl_xor_sync(0xffffffffu, nm0, 2));
        nm1 = fmaxf(nm1, __shfl_xor_sync(0xffffffffu, nm1, 1));
        nm1 = fmaxf(nm1, __shfl_xor_sync(0xffffffffu, nm1, 2));

        float alpha0 = __expf(mrow0 - nm0);
        float alpha1 = __expf(mrow1 - nm1);
        mrow0 = nm0; mrow1 = nm1;

        float rs0 = 0.0f, rs1 = 0.0f;
#pragma unroll
        for (int nt = 0; nt < 8; nt++) {
            float p0 = __expf(s[nt][0] - nm0);
            float p1 = __expf(s[nt][1] - nm0);
            float p2 = __expf(s[nt][2] - nm1);
            float p3 = __expf(s[nt][3] - nm1);
            rs0 += p0 + p1; rs1 += p2 + p3;
            half2 h01 = __floats2half2_rn(p0, p1);
            half2 h23 = __floats2half2_rn(p2, p3);
            P2[r * 36 + nt * 4 + tig]       = *(uint32_t*)&h01;
            P2[(r + 8) * 36 + nt * 4 + tig] = *(uint32_t*)&h23;
            acc[nt][0] *= alpha0; acc[nt][1] *= alpha0;
            acc[nt][2] *= alpha1; acc[nt][3] *= alpha1;
        }
        rs0 += __shfl_xor_sync(0xffffffffu, rs0, 1);
        rs0 += __shfl_xor_sync(0xffffffffu, rs0, 2);
        rs1 += __shfl_xor_sync(0xffffffffu, rs1, 1);
        rs1 += __shfl_xor_sync(0xffffffffu, rs1, 2);
        l0 = l0 * alpha0 + rs0;
        l1 = l1 * alpha1 + rs1;
        __syncwarp();

        const uint32_t psh = smem_u + 9216 * 4;
        const uint32_t vsh = smem_u + (4608 + buf * 2304) * 4;
#pragma unroll
        for (int ks = 0; ks < 4; ks++) {
            const int kk = ks * 16;
            uint32_t af[4];
            ldsm4(af, psh + (a_r * 36 + ks * 8 + a_w) * 4);
#pragma unroll
            for (int nt2 = 0; nt2 < 4; nt2++) {
                uint32_t b0, b1, b2, b3;
                uint32_t addr = vsh +
                    (((kk + lm) * 72 + nt2 * 16 + hi8) << 1);
                ldsm4t(b0, b1, b2, b3, addr);
                uint32_t bfA[2] = {b0, b1}, bfB[2] = {b2, b3};
                mma_f16(acc[nt2 * 2],     af, bfA);
                mma_f16(acc[nt2 * 2 + 1], af, bfB);
            }
        }

        if (kt < 7) {
            asm volatile("cp.async.wait_group 0;");
            __syncthreads();
        }
        buf ^= 1;
    }

    const float inv0 = 1.0f / l0, inv1 = 1.0f / l1;
    const int b = z / H_, hh = z % H_;
    const int mg = q0 + r;
    __half* out0 = ctx + (long)(b * S_ + mg) * D_ + hh * DH_;
    __half* out1 = out0 + 8 * D_;
#pragma unroll
    for (int nt = 0; nt < 8; nt++) {
        int c = nt * 8 + 2 * tig;
        *(half2*)(out0 + c) = __floats2half2_rn(acc[nt][0] * inv0, acc[nt][1] * inv0);
        *(half2*)(out1 + c) = __floats2half2_rn(acc[nt][2] * inv1, acc[nt][3] * inv1);
    }
}

// ---------------- tensor-core FP16 GEMM (128 thr, warp tile 64xWN) ----------
// 4 warps (2x2). BN=128: warp tile 64x64 (MT=4,NTL=8). BN=64: 64x32.
// cp.async 4-stage, BK=32, ldmatrix.x4 frags, fp32 accum.
// EPI: 0 = raw fp32 partial store to C + z*M*N
//      1 = fused QKV scatter, fp16 out; picks {Wq,Wk,Wv} by n-block
//      3 = fp16 gelu(acc + bias[n]) to (half*)C
template<int BN, int EPI>
__global__ __launch_bounds__(128, 2)
void gemm_h(const __half* __restrict__ A, const __half* __restrict__ Bt,
            float* __restrict__ C, const float* __restrict__ bias,
            const __half* __restrict__ Bt2, const float* __restrict__ bias2,
            float* __restrict__ C2,
            const __half* __restrict__ Bt3, const float* __restrict__ bias3,
            float* __restrict__ C3,
            int M, int N, int K, int lda, int ldb, float scaleval)
{
    constexpr int BM = 128, BK = 32, STAGES = 4;
    constexpr int WM = 64, WN = BN / 2;
    constexpr int MT = WM / 16, NTL = WN / 8;   // 4, 8|4
    constexpr int STR2 = BK / 2 + 4;            // 20 half2 words
    constexpr int ASZ = BM * STR2;
    constexpr int BSZ = BN * STR2;

    extern __shared__ uint32_t sm2[];
    uint32_t* AsB = sm2;
    uint32_t* BsB = sm2 + STAGES * ASZ;

    const int zz = blockIdx.z;
    A  += (long)zz * K;
    Bt += (long)zz * K;

    int n0;
    if constexpr (EPI == 1) {
        const int nb = N / BN;
        const int which = blockIdx.x / nb;
        n0 = (blockIdx.x % nb) * BN;
        if (which == 1) { Bt = Bt2; bias = bias2; C = C2; scaleval = 1.0f; }
        else if (which == 2) { Bt = Bt3; bias = bias3; C = C3; scaleval = 1.0f; }
    } else {
        n0 = blockIdx.x * BN;
    }
    float* Cw = C;
    if constexpr (EPI == 0) Cw = C + (long)zz * M * N;

    const int m0 = blockIdx.y * BM;
    const int tid  = threadIdx.x;
    const int warp = tid >> 5, lane = tid & 31;
    const int g = lane >> 2, tig = lane & 3;
    const int wm = warp & 1, wn = warp >> 1;
    const int m_base = wm * WM, n_base = wn * WN;

    const uint32_t smem_u = (uint32_t)__cvta_generic_to_shared(sm2);
    const int a_r = m_base + (lane & 7) + ((lane >> 3) & 1) * 8;
    const int a_w = (lane >> 4) << 2;
    const int b_r = n_base + (lane & 7) + ((lane >> 4) << 3);
    const int b_w = ((lane >> 3) & 1) << 2;

    float acc[MT][NTL][4] = {};

    auto loadTiles = [&](int stage, int kt) {
        const int k0 = kt * BK;
        uint32_t* as = AsB + stage * ASZ;
        uint32_t* bs = BsB + stage * BSZ;
#pragma unroll
        for (int i = 0; i < 4; i++) {           // A: 128 rows x 4 chunks
            int id = i * 128 + tid;
            int m = id >> 2, j = id & 3;
            cp16(&as[m * STR2 + 4 * j], A + (long)(m0 + m) * lda + k0 + 8 * j);
        }
#pragma unroll
        for (int i = 0; i < BN / 32; i++) {     // B: BN rows x 4 chunks
            int id = i * 128 + tid;
            int n = id >> 2, j = id & 3;
            cp16(&bs[n * STR2 + 4 * j], Bt + (long)(n0 + n) * ldb + k0 + 8 * j);
        }
    };

    auto compute = [&](int stage) {
        const uint32_t aoff = smem_u + (stage * ASZ) * 4;
        const uint32_t boff = smem_u + (STAGES * ASZ + stage * BSZ) * 4;
#pragma unroll
        for (int ks = 0; ks < 2; ks++) {
            const int kk2 = ks * 8;
            uint32_t af[MT][4], bf[NTL][2];
#pragma unroll
            for (int mt = 0; mt < MT; mt++)
                ldsm4(af[mt], aoff + ((a_r + mt * 16) * STR2 + kk2 + a_w) * 4);
#pragma unroll
            for (int p = 0; p < NTL / 2; p++) {
                uint32_t d[4];
                ldsm4(d, boff + ((b_r + p * 16) * STR2 + kk2 + b_w) * 4);
                bf[2 * p][0] = d[0]; bf[2 * p][1] = d[1];
                bf[2 * p + 1][0] = d[2]; bf[2 * p + 1][1] = d[3];
            }
#pragma unroll
            for (int mt = 0; mt < MT; mt++)
#pragma unroll
                for (int nt = 0; nt < NTL; nt++)
                    mma_f16(acc[mt][nt], af[mt], bf[nt]);
        }
    };

    const int KT = K / BK;
#pragma unroll
    for (int s = 0; s < STAGES - 1; s++) { loadTiles(s, s); CP_COMMIT(); }

    for (int kt = 0; kt < KT; kt++) {
        asm volatile("cp.async.wait_group 2;");
        __syncthreads();
        const int pf = kt + STAGES - 1;
        if (pf < KT) loadTiles(pf & (STAGES - 1), pf);
        CP_COMMIT();
        compute(kt & (STAGES - 1));
    }

#pragma unroll
    for (int mt = 0; mt < MT; mt++) {
        int r0 = m0 + m_base + mt * 16 + g;
#pragma unroll
        for (int nt = 0; nt < NTL; nt++) {
            int c0 = n0 + n_base + nt * 8 + 2 * tig;
            float v0 = acc[mt][nt][0], v1 = acc[mt][nt][1];
            float v2 = acc[mt][nt][2], v3 = acc[mt][nt][3];
            if constexpr (EPI == 0) {
                *(float2*)&Cw[(long)r0 * N + c0]       = make_float2(v0, v1);
                *(float2*)&Cw[(long)(r0 + 8) * N + c0] = make_float2(v2, v3);
            } else if constexpr (EPI == 1) {
                __half* Ch = (__half*)C;
                float2 bb = *(const float2*)&bias[c0];
                half2 w01 = __floats2half2_rn((v0 + bb.x) * scaleval,
                                              (v1 + bb.y) * scaleval);
                half2 w23 = __floats2half2_rn((v2 + bb.x) * scaleval,
                                              (v3 + bb.y) * scaleval);
                int bq = r0 >> 9, s = r0 & 511, hh = c0 >> 6, d = c0 & 63;
                long o0 = ((((long)bq * H_ + hh) * S_ + s) * DH_) + d;
                *(half2*)&Ch[o0]           = w01;
                *(half2*)&Ch[o0 + 8 * DH_] = w23;
            } else if constexpr (EPI == 3) {
                __half* Ch = (__half*)C;
                float2 bb = *(const float2*)&bias[c0];
                float x0 = v0 + bb.x, x1 = v1 + bb.y;
                float x2 = v2 + bb.x, x3 = v3 + bb.y;
                float w0 = 0.5f * x0 * (1.0f + erff(x0 * 0.70710678118654752f));
                float w1 = 0.5f * x1 * (1.0f + erff(x1 * 0.70710678118654752f));
                float w2 = 0.5f * x2 * (1.0f + erff(x2 * 0.70710678118654752f));
                float w3 = 0.5f * x3 * (1.0f + erff(x3 * 0.70710678118654752f));
                *(half2*)&Ch[(long)r0 * N + c0]       = __floats2half2_rn(w0, w1);
                *(half2*)&Ch[(long)(r0 + 8) * N + c0] = __floats2half2_rn(w2, w3);
            }
        }
    }
}

// ---- layernorm 768 with fused split-K reduce: x = p0 + p1 + bias + res ----
__global__ __launch_bounds__(256)
void layernorm768_red(const float* __restrict__ part, const float* __restrict__ bvec,
                      const float* __restrict__ res, const float* __restrict__ g,
                      const float* __restrict__ b, float* __restrict__ y,
                      __half* __restrict__ y16)
{
    const long off = (long)blockIdx.x * D_;
    const float* p0 = part + off;
    const float* p1 = part + (long)MR_ * D_ + off;
    const float* rr = res + off;
    float*  orow  = y   + off;
    __half* orow2 = y16 + off;
    int tid = threadIdx.x;
    float a0 = p0[tid]       + p1[tid]       + bvec[tid]       + rr[tid];
    float a1 = p0[tid + 256] + p1[tid + 256] + bvec[tid + 256] + rr[tid + 256];
    float a2 = p0[tid + 512] + p1[tid + 512] + bvec[tid + 512] + rr[tid + 512];
    float s = a0 + a1 + a2;
    float q = a0 * a0 + a1 * a1 + a2 * a2;
    __shared__ float rs[8], rq[8];
#pragma unroll
    for (int o = 16; o; o >>= 1) {
        s += __shfl_xor_sync(0xffffffffu, s, o);
        q += __shfl_xor_sync(0xffffffffu, q, o);
    }
    if ((tid & 31) == 0) { rs[tid >> 5] = s; rq[tid >> 5] = q; }
    __syncthreads();
    s = (rs[0] + rs[1]) + (rs[2] + rs[3]) + (rs[4] + rs[5]) + (rs[6] + rs[7]);
    q = (rq[0] + rq[1]) + (rq[2] + rq[3]) + (rq[4] + rq[5]) + (rq[6] + rq[7]);
    float mean = s * (1.0f / D_);
    float var  = q * (1.0f / D_) - mean * mean;
    float r = rsqrtf(var + 1e-5f);
    float v0 = (a0 - mean) * r * g[tid]       + b[tid];
    float v1 = (a1 - mean) * r * g[tid + 256] + b[tid + 256];
    float v2 = (a2 - mean) * r * g[tid + 512] + b[tid + 512];
    orow[tid]        = v0;  orow[tid + 256]  = v1;  orow[tid + 512]  = v2;
    orow2[tid]       = __float2half(v0);
    orow2[tid + 256] = __float2half(v1);
    orow2[tid + 512] = __float2half(v2);
}

// ---------------- host orchestration ----------------
extern "C" void kernel_launch(void* const* d_in, const int* in_sizes, int n_in,
                              void* d_out, int out_size)
{
    const float* hs    = (const float*)d_in[0];
    const float* mask  = (const float*)d_in[1];
    const float* rel   = (const float*)d_in[2];
    const float* rel2  = (const float*)d_in[3];
    const float* Wq    = (const float*)d_in[4];
    const float* bq    = (const float*)d_in[5];
    const float* Wk    = (const float*)d_in[6];
    const float* bk    = (const float*)d_in[7];
    const float* Wv    = (const float*)d_in[8];
    const float* bv    = (const float*)d_in[9];
    const float* Wo    = (const float*)d_in[10];
    const float* bo    = (const float*)d_in[11];
    const float* ln1g  = (const float*)d_in[12];
    const float* ln1b  = (const float*)d_in[13];
    const float* Wi    = (const float*)d_in[14];
    const float* bi    = (const float*)d_in[15];
    const float* Wo2   = (const float*)d_in[16];
    const float* bo2   = (const float*)d_in[17];
    const float* ln2g  = (const float*)d_in[18];
    const float* ln2b  = (const float*)d_in[19];
    float* out = (float*)d_out;

    float *p_h, *p_attn, *p_part;
    __half *p_bias16, *p_q16, *p_k16, *p_v16, *p_ctx16, *p_h16, *p_attn16, *p_ff16;
    __half *p_wq, *p_wk, *p_wv, *p_wo, *p_wi, *p_wo2;
    cudaGetSymbolAddress((void**)&p_bias16, g_bias16);
    cudaGetSymbolAddress((void**)&p_q16,    g_q16);
    cudaGetSymbolAddress((void**)&p_k16,    g_k16);
    cudaGetSymbolAddress((void**)&p_v16,    g_v16);
    cudaGetSymbolAddress((void**)&p_ctx16,  g_ctx16);
    cudaGetSymbolAddress((void**)&p_h,      g_h);
    cudaGetSymbolAddress((void**)&p_h16,    g_h16);
    cudaGetSymbolAddress((void**)&p_attn,   g_attn);
    cudaGetSymbolAddress((void**)&p_attn16, g_attn16);
    cudaGetSymbolAddress((void**)&p_ff16,   g_ff16);
    cudaGetSymbolAddress((void**)&p_part,   g_part);
    cudaGetSymbolAddress((void**)&p_wq,     g_wq16);
    cudaGetSymbolAddress((void**)&p_wk,     g_wk16);
    cudaGetSymbolAddress((void**)&p_wv,     g_wv16);
    cudaGetSymbolAddress((void**)&p_wo,     g_wo16);
    cudaGetSymbolAddress((void**)&p_wi,     g_wi16);
    cudaGetSymbolAddress((void**)&p_wo2,    g_wo216);

    cudaFuncSetAttribute(flash_attn,
                         cudaFuncAttributeMaxDynamicSharedMemorySize, FLASH_SMEM);
    const int SM_BN128 = 4 * (2560 + 128 * 20) * 4;   // 81920 B
    const int SM_BN64  = 4 * (2560 + 64 * 20) * 4;    // 61440 B
    cudaFuncSetAttribute(gemm_h<128,1>,
                         cudaFuncAttributeMaxDynamicSharedMemorySize, SM_BN128);
    cudaFuncSetAttribute(gemm_h<128,3>,
                         cudaFuncAttributeMaxDynamicSharedMemorySize, SM_BN128);
    cudaFuncSetAttribute(gemm_h<64,0>,
                         cudaFuncAttributeMaxDynamicSharedMemorySize, SM_BN64);

    // ---- prep: weight transpose->fp16 (QKVO batched), bias fp16, h/h16 ----
    dim3 tb(32, 8);
    dim3 gDD4(D_ / 32, D_ / 32, 4 * L_);
    dim3 gWi(FF_ / 32, D_ / 32, L_);
    dim3 gWo2(D_ / 32, FF_ / 32, L_);
    transpose_cvt4_kernel<<<gDD4, tb>>>(Wq, p_wq, Wk, p_wk, Wv, p_wv, Wo, p_wo);
    transpose_cvt_kernel<<<gWi, tb>>>(Wi,  p_wi,  D_, FF_);
    transpose_cvt_kernel<<<gWo2, tb>>>(Wo2, p_wo2, FF_, D_);

    long nb = (long)BH_ * SS_;
    bias_kernel<<<(unsigned)((nb / 2 + 255) / 256), 256>>>(rel, rel2, mask);
    copy2_kernel<<<(MR_ * D_ + 255) / 256, 256>>>(hs, p_h, p_h16, (long)MR_ * D_);

    dim3 gQKV(3 * D_ / 128, MR_ / 128, 1);  // 288
    dim3 gFA (S_ / 64, BH_, 1);             // 384, 3 CTAs/SM -> single wave
    dim3 gWoG(D_ / 64, MR_ / 128, 2);       // 384 (split-K=2)
    dim3 gF1 (FF_ / 128, MR_ / 128, 1);     // 384
    dim3 gF2 (D_ / 64, MR_ / 128, 2);       // 384 (split-K=2)

    for (int l = 0; l < L_; l++) {
        const __half* wq  = p_wq  + (long)l * D_ * D_;
        const __half* wk  = p_wk  + (long)l * D_ * D_;
        const __half* wv  = p_wv  + (long)l * D_ * D_;
        const __half* wo  = p_wo  + (long)l * D_ * D_;
        const __half* wi  = p_wi  + (long)l * D_ * FF_;
        const __half* wo2 = p_wo2 + (long)l * FF_ * D_;

        // fused QKV projections (q folds 1/8), fp16 scatter to [B,H,S,DH]
        gemm_h<128,1><<<gQKV, 128, SM_BN128>>>(
            p_h16, wq, (float*)p_q16, bq + l * D_,
            wk, bk + l * D_, (float*)p_k16,
            wv, bv + l * D_, (float*)p_v16,
            MR_, D_, D_, D_, D_, 0.125f);

        // fused attention (full fp16) -> ctx (fp16) [B,S,D]
        flash_attn<<<gFA, 128, FLASH_SMEM>>>(p_q16, p_k16, p_v16,
                                             p_bias16, p_ctx16);

        // ctx @ Wo (split-K=2, raw partials) -> LN1 fused reduce + bias + res
        gemm_h<64,0><<<gWoG, 128, SM_BN64>>>(
            p_ctx16, wo, p_part, nullptr,
            nullptr, nullptr, nullptr, nullptr, nullptr, nullptr,
            MR_, D_, D_ / 2, D_, D_, 1.0f);
        layernorm768_red<<<MR_, 256>>>(p_part, bo + l * D_, p_h,
                                       ln1g + l * D_, ln1b + l * D_,
                                       p_attn, p_attn16);

        // ff16 = fp16(gelu(attn @ Wi + bi))
        gemm_h<128,3><<<gF1, 128, SM_BN128>>>(
            p_attn16, wi, (float*)p_ff16, bi + l * FF_,
            nullptr, nullptr, nullptr, nullptr, nullptr, nullptr,
            MR_, FF_, D_, D_, D_, 1.0f);

        // ff @ Wo2 (split-K=2, raw partials) -> LN2 fused reduce + bias + res
        gemm_h<64,0><<<gF2, 128, SM_BN64>>>(
            p_ff16, wo2, p_part, nullptr,
            nullptr, nullptr, nullptr, nullptr, nullptr, nullptr,
            MR_, D_, FF_ / 2, FF_, FF_, 1.0f);
        float* dst = (l == L_ - 1) ? out : p_h;
        layernorm768_red<<<MR_, 256>>>(p_part, bo2 + l * D_, p_attn,
                                       ln2g + l * D_, ln2b + l * D_,
                                       dst, p_h16);
    }
}